// round 2
// baseline (speedup 1.0000x reference)
#include <cuda_runtime.h>
#include <cuda_bf16.h>
#include <math.h>

// ---------------------------------------------------------------------------
// LogLinearAttention — fp32 baseline (pipelined SGEMM)
//   B=4, T=4096, C=1024, H=16, dh=64, nc=8, cs=512
// Inputs (metadata order): x, Wqkv, Wout, bout, Wl1, bl1, Wl2, bl2
// Output: [B,T,C] float32
// ---------------------------------------------------------------------------

#define B_  4
#define T_  4096
#define C_  1024
#define H_  16
#define DH_ 64
#define NC_ 8
#define CS_ 512
#define QKV_N (3 * C_)          // 3072
#define M_  (B_ * T_)           // 16384

// Scratch (device globals — allocation-free per harness rules)
__device__ float g_qkv[(size_t)M_ * QKV_N];   // [16384, 3072]
__device__ float g_att[(size_t)M_ * C_];      // [16384, 1024]
__device__ float g_lam[H_ * T_];              // [16, 4096]

// ---------------------------------------------------------------------------
// Lambda gate MLP:  lam[h][t] = sigmoid( Wl2[h,:] @ relu(log(t+1)*Wl1[:,0]+bl1) + bl2[h] )
// ---------------------------------------------------------------------------
__global__ void lambda_kernel(const float* __restrict__ Wl1,
                              const float* __restrict__ bl1,
                              const float* __restrict__ Wl2,
                              const float* __restrict__ bl2) {
    int t = blockIdx.x * blockDim.x + threadIdx.x;
    if (t >= T_) return;
    float lp = logf((float)t + 1.0f);
    float h1[64];
#pragma unroll
    for (int j = 0; j < 64; j++)
        h1[j] = fmaxf(lp * Wl1[j] + bl1[j], 0.0f);
#pragma unroll
    for (int h = 0; h < H_; h++) {
        float s = bl2[h];
        const float* w = Wl2 + h * 64;
#pragma unroll
        for (int j = 0; j < 64; j++) s += w[j] * h1[j];
        g_lam[h * T_ + t] = 1.0f / (1.0f + __expf(-s));
    }
}

// ---------------------------------------------------------------------------
// Generic SGEMM:  C[M,N] = A[M,K] @ W[N,K]^T (+ bias[n])
// Block tile 128x128, K-tile 8, 256 threads, 8x8 per-thread tile (4+4 split).
// Global loads for tile k+1 are prefetched into registers before the FMA block
// of tile k (software pipelining), hiding DRAM/L2 latency behind compute.
// M, N multiples of 128; K multiple of 8.
// ---------------------------------------------------------------------------
__global__ __launch_bounds__(256, 2)
void sgemm_nt_kernel(const float* __restrict__ A,
                     const float* __restrict__ W,
                     const float* __restrict__ bias,
                     float* __restrict__ C,
                     int M, int N, int K) {
    __shared__ float As[8][128];
    __shared__ float Bs[8][128];

    const int tid = threadIdx.x;
    const int tx = tid & 15;       // 0..15 -> N
    const int ty = tid >> 4;       // 0..15 -> M
    const int m0 = blockIdx.y * 128;
    const int n0 = blockIdx.x * 128;

    const int ldrow = tid >> 1;          // 0..127
    const int ldk4  = (tid & 1) * 4;     // 0 or 4

    const float* Ap = A + (size_t)(m0 + ldrow) * K + ldk4;
    const float* Wp = W + (size_t)(n0 + ldrow) * K + ldk4;

    float acc[8][8];
#pragma unroll
    for (int i = 0; i < 8; i++)
#pragma unroll
        for (int j = 0; j < 8; j++) acc[i][j] = 0.0f;

    // prologue: first tile's loads
    float4 av = *(const float4*)(Ap);
    float4 wv = *(const float4*)(Wp);

    for (int k0 = 0; k0 < K; k0 += 8) {
        As[ldk4 + 0][ldrow] = av.x;
        As[ldk4 + 1][ldrow] = av.y;
        As[ldk4 + 2][ldrow] = av.z;
        As[ldk4 + 3][ldrow] = av.w;
        Bs[ldk4 + 0][ldrow] = wv.x;
        Bs[ldk4 + 1][ldrow] = wv.y;
        Bs[ldk4 + 2][ldrow] = wv.z;
        Bs[ldk4 + 3][ldrow] = wv.w;
        __syncthreads();

        // prefetch next tile (overlaps with FMA block below)
        if (k0 + 8 < K) {
            av = *(const float4*)(Ap + k0 + 8);
            wv = *(const float4*)(Wp + k0 + 8);
        }

#pragma unroll
        for (int kk = 0; kk < 8; kk++) {
            float4 a0 = *(const float4*)&As[kk][ty * 4];
            float4 a1 = *(const float4*)&As[kk][64 + ty * 4];
            float4 b0 = *(const float4*)&Bs[kk][tx * 4];
            float4 b1 = *(const float4*)&Bs[kk][64 + tx * 4];
            float a[8] = {a0.x, a0.y, a0.z, a0.w, a1.x, a1.y, a1.z, a1.w};
            float b[8] = {b0.x, b0.y, b0.z, b0.w, b1.x, b1.y, b1.z, b1.w};
#pragma unroll
            for (int i = 0; i < 8; i++)
#pragma unroll
                for (int j = 0; j < 8; j++)
                    acc[i][j] = fmaf(a[i], b[j], acc[i][j]);
        }
        __syncthreads();
    }

    // epilogue
    float badd[8];
#pragma unroll
    for (int j = 0; j < 8; j++) {
        int c = (j < 4) ? (tx * 4 + j) : (64 + tx * 4 + (j - 4));
        badd[j] = bias ? bias[n0 + c] : 0.0f;
    }
#pragma unroll
    for (int i = 0; i < 8; i++) {
        int r = (i < 4) ? (ty * 4 + i) : (64 + ty * 4 + (i - 4));
        float* crow = C + (size_t)(m0 + r) * N + n0;
        float4 o0 = make_float4(acc[i][0] + badd[0], acc[i][1] + badd[1],
                                acc[i][2] + badd[2], acc[i][3] + badd[3]);
        float4 o1 = make_float4(acc[i][4] + badd[4], acc[i][5] + badd[5],
                                acc[i][6] + badd[6], acc[i][7] + badd[7]);
        *(float4*)(crow + tx * 4)      = o0;
        *(float4*)(crow + 64 + tx * 4) = o1;
    }
}

// ---------------------------------------------------------------------------
// Chunked attention.
// One block = 64 query rows of one (b,h,chunk). 256 threads.
// Phase 1: S[64][512] = (Q K^T) * scale * lam  in smem.
// Softmax over keys (warp per 8 rows).
// Phase 2: O = P V, normalized by row sums, written to g_att in [B,T,C] layout.
// ---------------------------------------------------------------------------
#define SPITCH 516
#define KPITCH 68
#define ATT_SMEM_FLOATS (64 * KPITCH /*Qt*/ + 64 * KPITCH /*KV*/ + 64 * SPITCH /*S*/ + 64 /*gate*/ + 64 /*rinv*/)
#define ATT_SMEM_BYTES (ATT_SMEM_FLOATS * 4)

__global__ __launch_bounds__(256, 1)
void attn_kernel() {
    extern __shared__ float smem[];
    float* Qt   = smem;                       // [64 d][68 r]  (transposed, padded)
    float* KV   = Qt + 64 * KPITCH;           // phase1: Kt[d][c]; phase2: V[c][d]
    float* Ss   = KV + 64 * KPITCH;           // [64 r][516 c]
    float* gs   = Ss + 64 * SPITCH;           // per-key gate (scale*lambda)
    float* rinv = gs + 64;                    // 1/rowsum

    const int tid  = threadIdx.x;
    const int tx   = tid & 15;
    const int ty   = tid >> 4;
    const int cid  = blockIdx.x;              // 4096 blocks
    const int qt   = cid & 7;
    const int n    = (cid >> 3) & 7;
    const int h    = (cid >> 6) & 15;
    const int b    = cid >> 10;

    const int t0     = n * CS_ + qt * 64;       // first query row (in T)
    const int tk0    = n * CS_;                 // first key row of chunk
    const float scale = 0.125f;                 // dh^-0.5

    const float* qbase = g_qkv + (size_t)(b * T_ + t0) * QKV_N + h * DH_;
    // ---- load Q transposed: Qt[d][r] ----
    for (int idx = tid; idx < 1024; idx += 256) {
        int r  = idx >> 4;
        int d4 = (idx & 15) * 4;
        float4 v = *(const float4*)(qbase + (size_t)r * QKV_N + d4);
        Qt[(d4 + 0) * KPITCH + r] = v.x;
        Qt[(d4 + 1) * KPITCH + r] = v.y;
        Qt[(d4 + 2) * KPITCH + r] = v.z;
        Qt[(d4 + 3) * KPITCH + r] = v.w;
    }

    // ================= Phase 1: scores =================
    const int r0 = ty * 4;
    const int c0 = tx * 4;
    for (int kt = 0; kt < 8; kt++) {
        __syncthreads();   // protect KV + gs reuse
        const float* kbase = g_qkv + (size_t)(b * T_ + tk0 + kt * 64) * QKV_N + C_ + h * DH_;
        for (int idx = tid; idx < 1024; idx += 256) {
            int c  = idx >> 4;
            int d4 = (idx & 15) * 4;
            float4 v = *(const float4*)(kbase + (size_t)c * QKV_N + d4);
            KV[(d4 + 0) * KPITCH + c] = v.x;
            KV[(d4 + 1) * KPITCH + c] = v.y;
            KV[(d4 + 2) * KPITCH + c] = v.z;
            KV[(d4 + 3) * KPITCH + c] = v.w;
        }
        if (tid < 64)
            gs[tid] = scale * g_lam[h * T_ + tk0 + kt * 64 + tid];
        __syncthreads();

        float acc[4][4];
#pragma unroll
        for (int i = 0; i < 4; i++)
#pragma unroll
            for (int j = 0; j < 4; j++) acc[i][j] = 0.0f;

#pragma unroll 16
        for (int kk = 0; kk < 64; kk++) {
            float4 qv = *(const float4*)&Qt[kk * KPITCH + r0];
            float4 kv = *(const float4*)&KV[kk * KPITCH + c0];
            float qa[4] = {qv.x, qv.y, qv.z, qv.w};
            float ka[4] = {kv.x, kv.y, kv.z, kv.w};
#pragma unroll
            for (int i = 0; i < 4; i++)
#pragma unroll
                for (int j = 0; j < 4; j++)
                    acc[i][j] = fmaf(qa[i], ka[j], acc[i][j]);
        }
#pragma unroll
        for (int i = 0; i < 4; i++) {
            float* srow = Ss + (size_t)(r0 + i) * SPITCH + kt * 64 + c0;
#pragma unroll
            for (int j = 0; j < 4; j++)
                srow[j] = acc[i][j] * gs[c0 + j];
        }
    }
    __syncthreads();

    // ================= Softmax (warp per 8 rows) =================
    {
        const int warp = tid >> 5, lane = tid & 31;
        for (int r = warp * 8; r < warp * 8 + 8; r++) {
            float* row = Ss + (size_t)r * SPITCH;
            float vals[16];
            float m = -1e30f;
#pragma unroll
            for (int i = 0; i < 16; i++) {
                vals[i] = row[lane + i * 32];
                m = fmaxf(m, vals[i]);
            }
#pragma unroll
            for (int off = 16; off > 0; off >>= 1)
                m = fmaxf(m, __shfl_xor_sync(0xffffffffu, m, off));
            float s = 0.0f;
#pragma unroll
            for (int i = 0; i < 16; i++) {
                float e = __expf(vals[i] - m);
                s += e;
                row[lane + i * 32] = e;
            }
#pragma unroll
            for (int off = 16; off > 0; off >>= 1)
                s += __shfl_xor_sync(0xffffffffu, s, off);
            if (lane == 0) rinv[r] = 1.0f / s;
        }
    }
    __syncthreads();

    // ================= Phase 2: O = P V =================
    float acc[4][4];
#pragma unroll
    for (int i = 0; i < 4; i++)
#pragma unroll
        for (int j = 0; j < 4; j++) acc[i][j] = 0.0f;

    const int d0 = tx * 4;
    for (int kt = 0; kt < 8; kt++) {
        const float* vbase = g_qkv + (size_t)(b * T_ + tk0 + kt * 64) * QKV_N + 2 * C_ + h * DH_;
        // load V row-major: KV[c][d]
        for (int idx = tid; idx < 1024; idx += 256) {
            int c  = idx >> 4;
            int d4 = (idx & 15) * 4;
            *(float4*)&KV[c * KPITCH + d4] = *(const float4*)(vbase + (size_t)c * QKV_N + d4);
        }
        __syncthreads();

#pragma unroll 8
        for (int k = 0; k < 64; k++) {
            float4 vv = *(const float4*)&KV[k * KPITCH + d0];
            float va[4] = {vv.x, vv.y, vv.z, vv.w};
            float p0 = Ss[(size_t)(r0 + 0) * SPITCH + kt * 64 + k];
            float p1 = Ss[(size_t)(r0 + 1) * SPITCH + kt * 64 + k];
            float p2 = Ss[(size_t)(r0 + 2) * SPITCH + kt * 64 + k];
            float p3 = Ss[(size_t)(r0 + 3) * SPITCH + kt * 64 + k];
#pragma unroll
            for (int j = 0; j < 4; j++) {
                acc[0][j] = fmaf(p0, va[j], acc[0][j]);
                acc[1][j] = fmaf(p1, va[j], acc[1][j]);
                acc[2][j] = fmaf(p2, va[j], acc[2][j]);
                acc[3][j] = fmaf(p3, va[j], acc[3][j]);
            }
        }
        __syncthreads();   // before next V overwrite
    }

    // write O to g_att in [B,T,C] layout
#pragma unroll
    for (int i = 0; i < 4; i++) {
        float inv = rinv[r0 + i];
        float4 o = make_float4(acc[i][0] * inv, acc[i][1] * inv,
                               acc[i][2] * inv, acc[i][3] * inv);
        *(float4*)(g_att + (size_t)(b * T_ + t0 + r0 + i) * C_ + h * DH_ + d0) = o;
    }
}

// ---------------------------------------------------------------------------
// Launch
// ---------------------------------------------------------------------------
extern "C" void kernel_launch(void* const* d_in, const int* in_sizes, int n_in,
                              void* d_out, int out_size) {
    const float* x    = (const float*)d_in[0];
    const float* Wqkv = (const float*)d_in[1];
    const float* Wout = (const float*)d_in[2];
    const float* bout = (const float*)d_in[3];
    const float* Wl1  = (const float*)d_in[4];
    const float* bl1  = (const float*)d_in[5];
    const float* Wl2  = (const float*)d_in[6];
    const float* bl2  = (const float*)d_in[7];
    float* out = (float*)d_out;

    float* qkv_ptr = nullptr;
    float* att_ptr = nullptr;
    cudaGetSymbolAddress((void**)&qkv_ptr, g_qkv);
    cudaGetSymbolAddress((void**)&att_ptr, g_att);

    // No static guard (harness forbids them) — idempotent, cheap, every call.
    cudaFuncSetAttribute(attn_kernel,
                         cudaFuncAttributeMaxDynamicSharedMemorySize,
                         ATT_SMEM_BYTES);

    // 1) lambda gates
    lambda_kernel<<<(T_ + 127) / 128, 128>>>(Wl1, bl1, Wl2, bl2);

    // 2) QKV projection: g_qkv = x @ Wqkv^T
    {
        dim3 grid(QKV_N / 128, M_ / 128);
        sgemm_nt_kernel<<<grid, 256>>>(x, Wqkv, nullptr, qkv_ptr, M_, QKV_N, C_);
    }

    // 3) chunked gated attention -> g_att ([B,T,C] layout)
    attn_kernel<<<B_ * H_ * NC_ * (CS_ / 64), 256, ATT_SMEM_BYTES>>>();

    // 4) output projection: out = g_att @ Wout^T + bout
    {
        dim3 grid(C_ / 128, M_ / 128);
        sgemm_nt_kernel<<<grid, 256>>>(att_ptr, Wout, bout, out, M_, C_, C_);
    }
}

// round 5
// speedup vs baseline: 1.3407x; 1.3407x over previous
#include <cuda_runtime.h>
#include <cuda_bf16.h>
#include <math.h>

// ---------------------------------------------------------------------------
// LogLinearAttention — R5 (= R4 resubmit after infra flake):
// projections on tensor cores (bf16 3-split HMMA, fixed split variants),
// attention unchanged fp32.
//   B=4, T=4096, C=1024, H=16, dh=64, nc=8, cs=512
// Inputs (metadata order): x, Wqkv, Wout, bout, Wl1, bl1, Wl2, bl2
// Output: [B,T,C] float32
// ---------------------------------------------------------------------------

#define B_  4
#define T_  4096
#define C_  1024
#define H_  16
#define DH_ 64
#define NC_ 8
#define CS_ 512
#define QKV_N (3 * C_)          // 3072
#define M_  (B_ * T_)           // 16384
#define K3_ (3 * C_)            // split-3 K' = 3072

// Scratch (device globals — allocation-free per harness rules)
__device__ float g_qkv[(size_t)M_ * QKV_N];            // [16384, 3072] fp32
__device__ float g_att[(size_t)M_ * C_];               // [16384, 1024] fp32
__device__ float g_lam[H_ * T_];                       // [16, 4096]
__device__ __nv_bfloat16 g_xs[(size_t)M_ * K3_];       // split3 of x       [hi|hi|lo]
__device__ __nv_bfloat16 g_atts[(size_t)M_ * K3_];     // split3 of g_att   [hi|hi|lo]
__device__ __nv_bfloat16 g_wqkvs[(size_t)QKV_N * K3_]; // split3 of Wqkv    [hi|lo|hi]
__device__ __nv_bfloat16 g_wouts[(size_t)C_ * K3_];    // split3 of Wout    [hi|lo|hi]

// ---------------------------------------------------------------------------
// Lambda gate MLP
// ---------------------------------------------------------------------------
__global__ void lambda_kernel(const float* __restrict__ Wl1,
                              const float* __restrict__ bl1,
                              const float* __restrict__ Wl2,
                              const float* __restrict__ bl2) {
    int t = blockIdx.x * blockDim.x + threadIdx.x;
    if (t >= T_) return;
    float lp = logf((float)t + 1.0f);
    float h1[64];
#pragma unroll
    for (int j = 0; j < 64; j++)
        h1[j] = fmaxf(lp * Wl1[j] + bl1[j], 0.0f);
#pragma unroll
    for (int h = 0; h < H_; h++) {
        float s = bl2[h];
        const float* w = Wl2 + h * 64;
#pragma unroll
        for (int j = 0; j < 64; j++) s += w[j] * h1[j];
        g_lam[h * T_ + t] = 1.0f / (1.0f + __expf(-s));
    }
}

// ---------------------------------------------------------------------------
// split3: fp32 A[M,K] -> bf16 out[M,3K].
//   variant 0 (activations): [hi | hi | lo]
//   variant 1 (weights):     [hi | lo | hi]
// So A'·B'^T over K'=3K = hi·hi + hi·lo + lo·hi  (drops only lo·lo ~2^-16).
// ---------------------------------------------------------------------------
__global__ void split3_kernel(const float* __restrict__ A,
                              __nv_bfloat16* __restrict__ out,
                              int Mrows, int K, int variant) {
    size_t i4 = (size_t)blockIdx.x * blockDim.x + threadIdx.x;
    size_t total = (size_t)Mrows * K / 4;
    if (i4 >= total) return;
    size_t e0 = i4 * 4;
    int row = (int)(e0 / K);
    int k   = (int)(e0 % K);
    float4 v = *(const float4*)(A + e0);
    __nv_bfloat16 h0 = __float2bfloat16_rn(v.x);
    __nv_bfloat16 h1 = __float2bfloat16_rn(v.y);
    __nv_bfloat16 h2 = __float2bfloat16_rn(v.z);
    __nv_bfloat16 h3 = __float2bfloat16_rn(v.w);
    __nv_bfloat16 l0 = __float2bfloat16_rn(v.x - __bfloat162float(h0));
    __nv_bfloat16 l1 = __float2bfloat16_rn(v.y - __bfloat162float(h1));
    __nv_bfloat16 l2 = __float2bfloat16_rn(v.z - __bfloat162float(h2));
    __nv_bfloat16 l3 = __float2bfloat16_rn(v.w - __bfloat162float(h3));
    __nv_bfloat162 hA = __halves2bfloat162(h0, h1);
    __nv_bfloat162 hB = __halves2bfloat162(h2, h3);
    __nv_bfloat162 lA = __halves2bfloat162(l0, l1);
    __nv_bfloat162 lB = __halves2bfloat162(l2, l3);
    __nv_bfloat16* base = out + (size_t)row * (3 * K);
    // segment 0: hi (both variants)
    *(__nv_bfloat162*)(base + k)     = hA;
    *(__nv_bfloat162*)(base + k + 2) = hB;
    if (variant == 0) {
        // [hi | hi | lo]
        *(__nv_bfloat162*)(base + K + k)         = hA;
        *(__nv_bfloat162*)(base + K + k + 2)     = hB;
        *(__nv_bfloat162*)(base + 2 * K + k)     = lA;
        *(__nv_bfloat162*)(base + 2 * K + k + 2) = lB;
    } else {
        // [hi | lo | hi]
        *(__nv_bfloat162*)(base + K + k)         = lA;
        *(__nv_bfloat162*)(base + K + k + 2)     = lB;
        *(__nv_bfloat162*)(base + 2 * K + k)     = hA;
        *(__nv_bfloat162*)(base + 2 * K + k + 2) = hB;
    }
}

// ---------------------------------------------------------------------------
// bf16 tensor-core GEMM:  C[M,N] = A[M,Kp] @ B[N,Kp]^T (+bias), fp32 accum/out
// Block 128x128, BK=32, 8 warps (2x4), warp tile 64x32 via m16n8k16 mma.
// cp.async double-buffered smem; 80B-padded rows -> conflict-free ldmatrix.
// ---------------------------------------------------------------------------
#define GP 40   // smem row pitch in bf16 (80 bytes)

__device__ __forceinline__ unsigned smem_u32(const void* p) {
    return (unsigned)__cvta_generic_to_shared(p);
}
__device__ __forceinline__ void cp16(void* smem_dst, const void* gmem_src) {
    asm volatile("cp.async.cg.shared.global [%0], [%1], 16;\n"
                 :: "r"(smem_u32(smem_dst)), "l"(gmem_src));
}
__device__ __forceinline__ void ldm_x4(unsigned& r0, unsigned& r1,
                                       unsigned& r2, unsigned& r3,
                                       const void* p) {
    asm volatile("ldmatrix.sync.aligned.m8n8.x4.shared.b16 {%0,%1,%2,%3}, [%4];\n"
                 : "=r"(r0), "=r"(r1), "=r"(r2), "=r"(r3) : "r"(smem_u32(p)));
}
__device__ __forceinline__ void mma16816(float* c, const unsigned* a, const unsigned* b) {
    asm volatile("mma.sync.aligned.m16n8k16.row.col.f32.bf16.bf16.f32 "
                 "{%0,%1,%2,%3}, {%4,%5,%6,%7}, {%8,%9}, {%0,%1,%2,%3};\n"
                 : "+f"(c[0]), "+f"(c[1]), "+f"(c[2]), "+f"(c[3])
                 : "r"(a[0]), "r"(a[1]), "r"(a[2]), "r"(a[3]),
                   "r"(b[0]), "r"(b[1]));
}

__global__ __launch_bounds__(256)
void hgemm_bf16_kernel(const __nv_bfloat16* __restrict__ A,
                       const __nv_bfloat16* __restrict__ B,
                       const float* __restrict__ bias,
                       float* __restrict__ C,
                       int M, int N, int Kp) {
    __shared__ __nv_bfloat16 As[2][128 * GP];
    __shared__ __nv_bfloat16 Bs[2][128 * GP];

    const int tid  = threadIdx.x;
    const int lane = tid & 31;
    const int wid  = tid >> 5;
    const int wm   = wid >> 2;        // 0..1
    const int wn   = wid & 3;         // 0..3
    const int m0   = blockIdx.y * 128;
    const int n0   = blockIdx.x * 128;

    float acc[4][4][4];
#pragma unroll
    for (int i = 0; i < 4; i++)
#pragma unroll
        for (int j = 0; j < 4; j++)
#pragma unroll
            for (int r = 0; r < 4; r++) acc[i][j][r] = 0.0f;

    const int KT = Kp / 32;

    // prologue: tile 0 -> buf 0
    {
        int c1 = tid, c2 = tid + 256;
        int r1 = c1 >> 2, kc1 = c1 & 3;
        int r2 = c2 >> 2, kc2 = c2 & 3;
        cp16(&As[0][r1 * GP + kc1 * 8], A + (size_t)(m0 + r1) * Kp + kc1 * 8);
        cp16(&As[0][r2 * GP + kc2 * 8], A + (size_t)(m0 + r2) * Kp + kc2 * 8);
        cp16(&Bs[0][r1 * GP + kc1 * 8], B + (size_t)(n0 + r1) * Kp + kc1 * 8);
        cp16(&Bs[0][r2 * GP + kc2 * 8], B + (size_t)(n0 + r2) * Kp + kc2 * 8);
        asm volatile("cp.async.commit_group;\n");
        asm volatile("cp.async.wait_group 0;\n");
    }
    __syncthreads();

    int buf = 0;
    for (int kt = 0; kt < KT; kt++) {
        if (kt + 1 < KT) {
            int k0 = (kt + 1) * 32;
            int c1 = tid, c2 = tid + 256;
            int r1 = c1 >> 2, kc1 = c1 & 3;
            int r2 = c2 >> 2, kc2 = c2 & 3;
            cp16(&As[buf ^ 1][r1 * GP + kc1 * 8], A + (size_t)(m0 + r1) * Kp + k0 + kc1 * 8);
            cp16(&As[buf ^ 1][r2 * GP + kc2 * 8], A + (size_t)(m0 + r2) * Kp + k0 + kc2 * 8);
            cp16(&Bs[buf ^ 1][r1 * GP + kc1 * 8], B + (size_t)(n0 + r1) * Kp + k0 + kc1 * 8);
            cp16(&Bs[buf ^ 1][r2 * GP + kc2 * 8], B + (size_t)(n0 + r2) * Kp + k0 + kc2 * 8);
            asm volatile("cp.async.commit_group;\n");
        }

        const __nv_bfloat16* Ab = As[buf];
        const __nv_bfloat16* Bb = Bs[buf];
#pragma unroll
        for (int ks = 0; ks < 2; ks++) {
            unsigned a[4][4], b[4][2];
            const int ar = lane & 15;
            const int ak = ks * 16 + ((lane >> 4) << 3);
#pragma unroll
            for (int mi = 0; mi < 4; mi++)
                ldm_x4(a[mi][0], a[mi][1], a[mi][2], a[mi][3],
                       Ab + (wm * 64 + mi * 16 + ar) * GP + ak);
            const int br = ((lane >> 4) << 3) + (lane & 7);
            const int bk = ks * 16 + (((lane >> 3) & 1) << 3);
#pragma unroll
            for (int njp = 0; njp < 2; njp++) {
                unsigned r0, r1, r2, r3;
                ldm_x4(r0, r1, r2, r3, Bb + (wn * 32 + njp * 16 + br) * GP + bk);
                b[njp * 2][0] = r0; b[njp * 2][1] = r1;
                b[njp * 2 + 1][0] = r2; b[njp * 2 + 1][1] = r3;
            }
#pragma unroll
            for (int mi = 0; mi < 4; mi++)
#pragma unroll
                for (int nj = 0; nj < 4; nj++)
                    mma16816(acc[mi][nj], a[mi], b[nj]);
        }

        if (kt + 1 < KT) asm volatile("cp.async.wait_group 0;\n");
        __syncthreads();
        buf ^= 1;
    }

    // epilogue
    const int rbase = m0 + wm * 64 + (lane >> 2);
    const int cbase = n0 + wn * 32 + (lane & 3) * 2;
#pragma unroll
    for (int mi = 0; mi < 4; mi++) {
#pragma unroll
        for (int nj = 0; nj < 4; nj++) {
            int col = cbase + nj * 8;
            float b0 = bias ? bias[col] : 0.0f;
            float b1 = bias ? bias[col + 1] : 0.0f;
            int r0 = rbase + mi * 16;
            float2 v0 = make_float2(acc[mi][nj][0] + b0, acc[mi][nj][1] + b1);
            float2 v1 = make_float2(acc[mi][nj][2] + b0, acc[mi][nj][3] + b1);
            *(float2*)(C + (size_t)r0 * N + col)       = v0;
            *(float2*)(C + (size_t)(r0 + 8) * N + col) = v1;
        }
    }
}

// ---------------------------------------------------------------------------
// Chunked attention (unchanged fp32) — one block = 64 q rows of one (b,h,chunk)
// ---------------------------------------------------------------------------
#define SPITCH 516
#define KPITCH 68
#define ATT_SMEM_FLOATS (64 * KPITCH + 64 * KPITCH + 64 * SPITCH + 64 + 64)
#define ATT_SMEM_BYTES (ATT_SMEM_FLOATS * 4)

__global__ __launch_bounds__(256, 1)
void attn_kernel() {
    extern __shared__ float smem[];
    float* Qt   = smem;
    float* KV   = Qt + 64 * KPITCH;
    float* Ss   = KV + 64 * KPITCH;
    float* gs   = Ss + 64 * SPITCH;
    float* rinv = gs + 64;

    const int tid  = threadIdx.x;
    const int tx   = tid & 15;
    const int ty   = tid >> 4;
    const int cid  = blockIdx.x;
    const int qt   = cid & 7;
    const int n    = (cid >> 3) & 7;
    const int h    = (cid >> 6) & 15;
    const int b    = cid >> 10;

    const int t0  = n * CS_ + qt * 64;
    const int tk0 = n * CS_;
    const float scale = 0.125f;

    const float* qbase = g_qkv + (size_t)(b * T_ + t0) * QKV_N + h * DH_;
    for (int idx = tid; idx < 1024; idx += 256) {
        int r  = idx >> 4;
        int d4 = (idx & 15) * 4;
        float4 v = *(const float4*)(qbase + (size_t)r * QKV_N + d4);
        Qt[(d4 + 0) * KPITCH + r] = v.x;
        Qt[(d4 + 1) * KPITCH + r] = v.y;
        Qt[(d4 + 2) * KPITCH + r] = v.z;
        Qt[(d4 + 3) * KPITCH + r] = v.w;
    }

    const int r0 = ty * 4;
    const int c0 = tx * 4;
    for (int kt = 0; kt < 8; kt++) {
        __syncthreads();
        const float* kbase = g_qkv + (size_t)(b * T_ + tk0 + kt * 64) * QKV_N + C_ + h * DH_;
        for (int idx = tid; idx < 1024; idx += 256) {
            int c  = idx >> 4;
            int d4 = (idx & 15) * 4;
            float4 v = *(const float4*)(kbase + (size_t)c * QKV_N + d4);
            KV[(d4 + 0) * KPITCH + c] = v.x;
            KV[(d4 + 1) * KPITCH + c] = v.y;
            KV[(d4 + 2) * KPITCH + c] = v.z;
            KV[(d4 + 3) * KPITCH + c] = v.w;
        }
        if (tid < 64)
            gs[tid] = scale * g_lam[h * T_ + tk0 + kt * 64 + tid];
        __syncthreads();

        float acc[4][4];
#pragma unroll
        for (int i = 0; i < 4; i++)
#pragma unroll
            for (int j = 0; j < 4; j++) acc[i][j] = 0.0f;

#pragma unroll 16
        for (int kk = 0; kk < 64; kk++) {
            float4 qv = *(const float4*)&Qt[kk * KPITCH + r0];
            float4 kv = *(const float4*)&KV[kk * KPITCH + c0];
            float qa[4] = {qv.x, qv.y, qv.z, qv.w};
            float ka[4] = {kv.x, kv.y, kv.z, kv.w};
#pragma unroll
            for (int i = 0; i < 4; i++)
#pragma unroll
                for (int j = 0; j < 4; j++)
                    acc[i][j] = fmaf(qa[i], ka[j], acc[i][j]);
        }
#pragma unroll
        for (int i = 0; i < 4; i++) {
            float* srow = Ss + (size_t)(r0 + i) * SPITCH + kt * 64 + c0;
#pragma unroll
            for (int j = 0; j < 4; j++)
                srow[j] = acc[i][j] * gs[c0 + j];
        }
    }
    __syncthreads();

    {
        const int warp = tid >> 5, lane = tid & 31;
        for (int r = warp * 8; r < warp * 8 + 8; r++) {
            float* row = Ss + (size_t)r * SPITCH;
            float vals[16];
            float m = -1e30f;
#pragma unroll
            for (int i = 0; i < 16; i++) {
                vals[i] = row[lane + i * 32];
                m = fmaxf(m, vals[i]);
            }
#pragma unroll
            for (int off = 16; off > 0; off >>= 1)
                m = fmaxf(m, __shfl_xor_sync(0xffffffffu, m, off));
            float s = 0.0f;
#pragma unroll
            for (int i = 0; i < 16; i++) {
                float e = __expf(vals[i] - m);
                s += e;
                row[lane + i * 32] = e;
            }
#pragma unroll
            for (int off = 16; off > 0; off >>= 1)
                s += __shfl_xor_sync(0xffffffffu, s, off);
            if (lane == 0) rinv[r] = 1.0f / s;
        }
    }
    __syncthreads();

    float acc[4][4];
#pragma unroll
    for (int i = 0; i < 4; i++)
#pragma unroll
        for (int j = 0; j < 4; j++) acc[i][j] = 0.0f;

    const int d0 = tx * 4;
    for (int kt = 0; kt < 8; kt++) {
        const float* vbase = g_qkv + (size_t)(b * T_ + tk0 + kt * 64) * QKV_N + 2 * C_ + h * DH_;
        for (int idx = tid; idx < 1024; idx += 256) {
            int c  = idx >> 4;
            int d4 = (idx & 15) * 4;
            *(float4*)&KV[c * KPITCH + d4] = *(const float4*)(vbase + (size_t)c * QKV_N + d4);
        }
        __syncthreads();

#pragma unroll 8
        for (int k = 0; k < 64; k++) {
            float4 vv = *(const float4*)&KV[k * KPITCH + d0];
            float va[4] = {vv.x, vv.y, vv.z, vv.w};
            float p0 = Ss[(size_t)(r0 + 0) * SPITCH + kt * 64 + k];
            float p1 = Ss[(size_t)(r0 + 1) * SPITCH + kt * 64 + k];
            float p2 = Ss[(size_t)(r0 + 2) * SPITCH + kt * 64 + k];
            float p3 = Ss[(size_t)(r0 + 3) * SPITCH + kt * 64 + k];
#pragma unroll
            for (int j = 0; j < 4; j++) {
                acc[0][j] = fmaf(p0, va[j], acc[0][j]);
                acc[1][j] = fmaf(p1, va[j], acc[1][j]);
                acc[2][j] = fmaf(p2, va[j], acc[2][j]);
                acc[3][j] = fmaf(p3, va[j], acc[3][j]);
            }
        }
        __syncthreads();
    }

#pragma unroll
    for (int i = 0; i < 4; i++) {
        float inv = rinv[r0 + i];
        float4 o = make_float4(acc[i][0] * inv, acc[i][1] * inv,
                               acc[i][2] * inv, acc[i][3] * inv);
        *(float4*)(g_att + (size_t)(b * T_ + t0 + r0 + i) * C_ + h * DH_ + d0) = o;
    }
}

// ---------------------------------------------------------------------------
// Launch
// ---------------------------------------------------------------------------
extern "C" void kernel_launch(void* const* d_in, const int* in_sizes, int n_in,
                              void* d_out, int out_size) {
    const float* x    = (const float*)d_in[0];
    const float* Wqkv = (const float*)d_in[1];
    const float* Wout = (const float*)d_in[2];
    const float* bout = (const float*)d_in[3];
    const float* Wl1  = (const float*)d_in[4];
    const float* bl1  = (const float*)d_in[5];
    const float* Wl2  = (const float*)d_in[6];
    const float* bl2  = (const float*)d_in[7];
    float* out = (float*)d_out;

    float *qkv_ptr = nullptr, *att_ptr = nullptr;
    __nv_bfloat16 *xs = nullptr, *atts = nullptr, *wqkvs = nullptr, *wouts = nullptr;
    cudaGetSymbolAddress((void**)&qkv_ptr, g_qkv);
    cudaGetSymbolAddress((void**)&att_ptr, g_att);
    cudaGetSymbolAddress((void**)&xs, g_xs);
    cudaGetSymbolAddress((void**)&atts, g_atts);
    cudaGetSymbolAddress((void**)&wqkvs, g_wqkvs);
    cudaGetSymbolAddress((void**)&wouts, g_wouts);

    cudaFuncSetAttribute(attn_kernel,
                         cudaFuncAttributeMaxDynamicSharedMemorySize,
                         ATT_SMEM_BYTES);

    // 1) lambda gates
    lambda_kernel<<<(T_ + 127) / 128, 128>>>(Wl1, bl1, Wl2, bl2);

    // 2) splits for QKV GEMM (activations variant 0, weights variant 1)
    {
        int threads = 256;
        size_t tx4 = (size_t)M_ * C_ / 4;
        split3_kernel<<<(unsigned)((tx4 + threads - 1) / threads), threads>>>(x, xs, M_, C_, 0);
        size_t tw4 = (size_t)QKV_N * C_ / 4;
        split3_kernel<<<(unsigned)((tw4 + threads - 1) / threads), threads>>>(Wqkv, wqkvs, QKV_N, C_, 1);
    }

    // 3) QKV projection on tensor cores: g_qkv = x @ Wqkv^T (split-3 bf16)
    {
        dim3 grid(QKV_N / 128, M_ / 128);
        hgemm_bf16_kernel<<<grid, 256>>>(xs, wqkvs, nullptr, qkv_ptr, M_, QKV_N, K3_);
    }

    // 4) chunked gated attention -> g_att ([B,T,C] fp32)
    attn_kernel<<<B_ * H_ * NC_ * (CS_ / 64), 256, ATT_SMEM_BYTES>>>();

    // 5) splits for out GEMM
    {
        int threads = 256;
        size_t ta4 = (size_t)M_ * C_ / 4;
        split3_kernel<<<(unsigned)((ta4 + threads - 1) / threads), threads>>>(att_ptr, atts, M_, C_, 0);
        size_t tw4 = (size_t)C_ * C_ / 4;
        split3_kernel<<<(unsigned)((tw4 + threads - 1) / threads), threads>>>(Wout, wouts, C_, C_, 1);
    }

    // 6) output projection on tensor cores: out = g_att @ Wout^T + bout
    {
        dim3 grid(C_ / 128, M_ / 128);
        hgemm_bf16_kernel<<<grid, 256>>>(atts, wouts, bout, out, M_, C_, K3_);
    }
}

// round 6
// speedup vs baseline: 1.9842x; 1.4800x over previous
#include <cuda_runtime.h>
#include <cuda_bf16.h>
#include <math.h>

// ---------------------------------------------------------------------------
// LogLinearAttention — R6: everything heavy on tensor cores.
//   - QKV / out projections: split-3 bf16 HMMA GEMM (validated R5)
//   - attention: HMMA with 3-term split on QK^T and P·V, exact softmax
//   B=4, T=4096, C=1024, H=16, dh=64, nc=8, cs=512
// Inputs: x, Wqkv, Wout, bout, Wl1, bl1, Wl2, bl2 ; Output: [B,T,C] fp32
// ---------------------------------------------------------------------------

#define B_  4
#define T_  4096
#define C_  1024
#define H_  16
#define DH_ 64
#define NC_ 8
#define CS_ 512
#define QKV_N (3 * C_)          // 3072
#define M_  (B_ * T_)           // 16384
#define K3_ (3 * C_)            // split-3 K' = 3072

// Scratch (device globals)
__device__ float g_qkv[(size_t)M_ * QKV_N];            // [16384,3072] fp32
__device__ float g_lam[H_ * T_];
__device__ __nv_bfloat16 g_xs[(size_t)M_ * K3_];       // split3 x     [hi|hi|lo]
__device__ __nv_bfloat16 g_atts[(size_t)M_ * K3_];     // split3 O     [hi|hi|lo] (written by attn)
__device__ __nv_bfloat16 g_wqkvs[(size_t)QKV_N * K3_]; // split3 Wqkv  [hi|lo|hi]
__device__ __nv_bfloat16 g_wouts[(size_t)C_ * K3_];    // split3 Wout  [hi|lo|hi]
// q/k/v hi/lo, per-(b,h) contiguous: [comp3][part2][bh64][t4096][d64]
__device__ __nv_bfloat16 g_s16[(size_t)3 * 2 * 64 * T_ * DH_];

#define S16_OFF(comp, part, bh, t) \
    (((((size_t)((comp) * 2 + (part)) * 64 + (bh)) * T_) + (t)) * DH_)

// ---------------------------------------------------------------------------
__global__ void lambda_kernel(const float* __restrict__ Wl1,
                              const float* __restrict__ bl1,
                              const float* __restrict__ Wl2,
                              const float* __restrict__ bl2) {
    int t = blockIdx.x * blockDim.x + threadIdx.x;
    if (t >= T_) return;
    float lp = logf((float)t + 1.0f);
    float h1[64];
#pragma unroll
    for (int j = 0; j < 64; j++)
        h1[j] = fmaxf(lp * Wl1[j] + bl1[j], 0.0f);
#pragma unroll
    for (int h = 0; h < H_; h++) {
        float s = bl2[h];
        const float* w = Wl2 + h * 64;
#pragma unroll
        for (int j = 0; j < 64; j++) s += w[j] * h1[j];
        g_lam[h * T_ + t] = 1.0f / (1.0f + __expf(-s));
    }
}

// ---------------------------------------------------------------------------
// split3 for GEMM operands (variant 0: [hi|hi|lo], variant 1: [hi|lo|hi])
// ---------------------------------------------------------------------------
__global__ void split3_kernel(const float* __restrict__ A,
                              __nv_bfloat16* __restrict__ out,
                              int Mrows, int K, int variant) {
    size_t i4 = (size_t)blockIdx.x * blockDim.x + threadIdx.x;
    size_t total = (size_t)Mrows * K / 4;
    if (i4 >= total) return;
    size_t e0 = i4 * 4;
    int row = (int)(e0 / K);
    int k   = (int)(e0 % K);
    float4 v = *(const float4*)(A + e0);
    __nv_bfloat16 h0 = __float2bfloat16_rn(v.x);
    __nv_bfloat16 h1 = __float2bfloat16_rn(v.y);
    __nv_bfloat16 h2 = __float2bfloat16_rn(v.z);
    __nv_bfloat16 h3 = __float2bfloat16_rn(v.w);
    __nv_bfloat16 l0 = __float2bfloat16_rn(v.x - __bfloat162float(h0));
    __nv_bfloat16 l1 = __float2bfloat16_rn(v.y - __bfloat162float(h1));
    __nv_bfloat16 l2 = __float2bfloat16_rn(v.z - __bfloat162float(h2));
    __nv_bfloat16 l3 = __float2bfloat16_rn(v.w - __bfloat162float(h3));
    __nv_bfloat162 hA = __halves2bfloat162(h0, h1);
    __nv_bfloat162 hB = __halves2bfloat162(h2, h3);
    __nv_bfloat162 lA = __halves2bfloat162(l0, l1);
    __nv_bfloat162 lB = __halves2bfloat162(l2, l3);
    __nv_bfloat16* base = out + (size_t)row * (3 * K);
    *(__nv_bfloat162*)(base + k)     = hA;
    *(__nv_bfloat162*)(base + k + 2) = hB;
    if (variant == 0) {
        *(__nv_bfloat162*)(base + K + k)         = hA;
        *(__nv_bfloat162*)(base + K + k + 2)     = hB;
        *(__nv_bfloat162*)(base + 2 * K + k)     = lA;
        *(__nv_bfloat162*)(base + 2 * K + k + 2) = lB;
    } else {
        *(__nv_bfloat162*)(base + K + k)         = lA;
        *(__nv_bfloat162*)(base + K + k + 2)     = lB;
        *(__nv_bfloat162*)(base + 2 * K + k)     = hA;
        *(__nv_bfloat162*)(base + 2 * K + k + 2) = hB;
    }
}

// ---------------------------------------------------------------------------
// qkv_split: g_qkv fp32 -> g_s16 bf16 hi/lo in per-(b,h) layout
// ---------------------------------------------------------------------------
__global__ void qkvsplit_kernel() {
    size_t idx = (size_t)blockIdx.x * blockDim.x + threadIdx.x;
    size_t total = (size_t)M_ * QKV_N / 4;
    if (idx >= total) return;
    int bt = (int)(idx / (QKV_N / 4));
    int c4 = (int)(idx % (QKV_N / 4)) * 4;
    int comp = c4 >> 10;
    int rem  = c4 & 1023;
    int h = rem >> 6;
    int d = rem & 63;
    int b = bt >> 12;
    int t = bt & 4095;
    int bh = b * H_ + h;
    float4 v = *(const float4*)(g_qkv + (size_t)bt * QKV_N + c4);
    __nv_bfloat16 h0 = __float2bfloat16_rn(v.x);
    __nv_bfloat16 h1 = __float2bfloat16_rn(v.y);
    __nv_bfloat16 h2 = __float2bfloat16_rn(v.z);
    __nv_bfloat16 h3 = __float2bfloat16_rn(v.w);
    __nv_bfloat16 l0 = __float2bfloat16_rn(v.x - __bfloat162float(h0));
    __nv_bfloat16 l1 = __float2bfloat16_rn(v.y - __bfloat162float(h1));
    __nv_bfloat16 l2 = __float2bfloat16_rn(v.z - __bfloat162float(h2));
    __nv_bfloat16 l3 = __float2bfloat16_rn(v.w - __bfloat162float(h3));
    __nv_bfloat16* hid = g_s16 + S16_OFF(comp, 0, bh, t) + d;
    __nv_bfloat16* lod = g_s16 + S16_OFF(comp, 1, bh, t) + d;
    *(__nv_bfloat162*)(hid)     = __halves2bfloat162(h0, h1);
    *(__nv_bfloat162*)(hid + 2) = __halves2bfloat162(h2, h3);
    *(__nv_bfloat162*)(lod)     = __halves2bfloat162(l0, l1);
    *(__nv_bfloat162*)(lod + 2) = __halves2bfloat162(l2, l3);
}

// ---------------------------------------------------------------------------
// PTX helpers
// ---------------------------------------------------------------------------
__device__ __forceinline__ unsigned smem_u32(const void* p) {
    return (unsigned)__cvta_generic_to_shared(p);
}
__device__ __forceinline__ void cp16(void* smem_dst, const void* gmem_src) {
    asm volatile("cp.async.cg.shared.global [%0], [%1], 16;\n"
                 :: "r"(smem_u32(smem_dst)), "l"(gmem_src));
}
__device__ __forceinline__ void ldm_x4(unsigned& r0, unsigned& r1,
                                       unsigned& r2, unsigned& r3,
                                       const void* p) {
    asm volatile("ldmatrix.sync.aligned.m8n8.x4.shared.b16 {%0,%1,%2,%3}, [%4];\n"
                 : "=r"(r0), "=r"(r1), "=r"(r2), "=r"(r3) : "r"(smem_u32(p)));
}
__device__ __forceinline__ void ldm_x4t(unsigned& r0, unsigned& r1,
                                        unsigned& r2, unsigned& r3,
                                        const void* p) {
    asm volatile("ldmatrix.sync.aligned.m8n8.x4.trans.shared.b16 {%0,%1,%2,%3}, [%4];\n"
                 : "=r"(r0), "=r"(r1), "=r"(r2), "=r"(r3) : "r"(smem_u32(p)));
}
__device__ __forceinline__ void mma16816(float* c, const unsigned* a, const unsigned* b) {
    asm volatile("mma.sync.aligned.m16n8k16.row.col.f32.bf16.bf16.f32 "
                 "{%0,%1,%2,%3}, {%4,%5,%6,%7}, {%8,%9}, {%0,%1,%2,%3};\n"
                 : "+f"(c[0]), "+f"(c[1]), "+f"(c[2]), "+f"(c[3])
                 : "r"(a[0]), "r"(a[1]), "r"(a[2]), "r"(a[3]),
                   "r"(b[0]), "r"(b[1]));
}

// ---------------------------------------------------------------------------
// bf16 HMMA GEMM (unchanged from R5): C[M,N] = A[M,Kp] @ B[N,Kp]^T (+bias)
// ---------------------------------------------------------------------------
#define GP 40

__global__ __launch_bounds__(256)
void hgemm_bf16_kernel(const __nv_bfloat16* __restrict__ A,
                       const __nv_bfloat16* __restrict__ B,
                       const float* __restrict__ bias,
                       float* __restrict__ C,
                       int M, int N, int Kp) {
    __shared__ __nv_bfloat16 As[2][128 * GP];
    __shared__ __nv_bfloat16 Bs[2][128 * GP];

    const int tid  = threadIdx.x;
    const int lane = tid & 31;
    const int wid  = tid >> 5;
    const int wm   = wid >> 2;
    const int wn   = wid & 3;
    const int m0   = blockIdx.y * 128;
    const int n0   = blockIdx.x * 128;

    float acc[4][4][4];
#pragma unroll
    for (int i = 0; i < 4; i++)
#pragma unroll
        for (int j = 0; j < 4; j++)
#pragma unroll
            for (int r = 0; r < 4; r++) acc[i][j][r] = 0.0f;

    const int KT = Kp / 32;
    {
        int c1 = tid, c2 = tid + 256;
        int r1 = c1 >> 2, kc1 = c1 & 3;
        int r2 = c2 >> 2, kc2 = c2 & 3;
        cp16(&As[0][r1 * GP + kc1 * 8], A + (size_t)(m0 + r1) * Kp + kc1 * 8);
        cp16(&As[0][r2 * GP + kc2 * 8], A + (size_t)(m0 + r2) * Kp + kc2 * 8);
        cp16(&Bs[0][r1 * GP + kc1 * 8], B + (size_t)(n0 + r1) * Kp + kc1 * 8);
        cp16(&Bs[0][r2 * GP + kc2 * 8], B + (size_t)(n0 + r2) * Kp + kc2 * 8);
        asm volatile("cp.async.commit_group;\n");
        asm volatile("cp.async.wait_group 0;\n");
    }
    __syncthreads();

    int buf = 0;
    for (int kt = 0; kt < KT; kt++) {
        if (kt + 1 < KT) {
            int k0 = (kt + 1) * 32;
            int c1 = tid, c2 = tid + 256;
            int r1 = c1 >> 2, kc1 = c1 & 3;
            int r2 = c2 >> 2, kc2 = c2 & 3;
            cp16(&As[buf ^ 1][r1 * GP + kc1 * 8], A + (size_t)(m0 + r1) * Kp + k0 + kc1 * 8);
            cp16(&As[buf ^ 1][r2 * GP + kc2 * 8], A + (size_t)(m0 + r2) * Kp + k0 + kc2 * 8);
            cp16(&Bs[buf ^ 1][r1 * GP + kc1 * 8], B + (size_t)(n0 + r1) * Kp + k0 + kc1 * 8);
            cp16(&Bs[buf ^ 1][r2 * GP + kc2 * 8], B + (size_t)(n0 + r2) * Kp + k0 + kc2 * 8);
            asm volatile("cp.async.commit_group;\n");
        }
        const __nv_bfloat16* Ab = As[buf];
        const __nv_bfloat16* Bb = Bs[buf];
#pragma unroll
        for (int ks = 0; ks < 2; ks++) {
            unsigned a[4][4], b[4][2];
            const int ar = lane & 15;
            const int ak = ks * 16 + ((lane >> 4) << 3);
#pragma unroll
            for (int mi = 0; mi < 4; mi++)
                ldm_x4(a[mi][0], a[mi][1], a[mi][2], a[mi][3],
                       Ab + (wm * 64 + mi * 16 + ar) * GP + ak);
            const int br = ((lane >> 4) << 3) + (lane & 7);
            const int bk = ks * 16 + (((lane >> 3) & 1) << 3);
#pragma unroll
            for (int njp = 0; njp < 2; njp++) {
                unsigned r0, r1, r2, r3;
                ldm_x4(r0, r1, r2, r3, Bb + (wn * 32 + njp * 16 + br) * GP + bk);
                b[njp * 2][0] = r0; b[njp * 2][1] = r1;
                b[njp * 2 + 1][0] = r2; b[njp * 2 + 1][1] = r3;
            }
#pragma unroll
            for (int mi = 0; mi < 4; mi++)
#pragma unroll
                for (int nj = 0; nj < 4; nj++)
                    mma16816(acc[mi][nj], a[mi], b[nj]);
        }
        if (kt + 1 < KT) asm volatile("cp.async.wait_group 0;\n");
        __syncthreads();
        buf ^= 1;
    }

    const int rbase = m0 + wm * 64 + (lane >> 2);
    const int cbase = n0 + wn * 32 + (lane & 3) * 2;
#pragma unroll
    for (int mi = 0; mi < 4; mi++) {
#pragma unroll
        for (int nj = 0; nj < 4; nj++) {
            int col = cbase + nj * 8;
            float b0 = bias ? bias[col] : 0.0f;
            float b1 = bias ? bias[col + 1] : 0.0f;
            int r0 = rbase + mi * 16;
            float2 v0 = make_float2(acc[mi][nj][0] + b0, acc[mi][nj][1] + b1);
            float2 v1 = make_float2(acc[mi][nj][2] + b0, acc[mi][nj][3] + b1);
            *(float2*)(C + (size_t)r0 * N + col)       = v0;
            *(float2*)(C + (size_t)(r0 + 8) * N + col) = v1;
        }
    }
}

// ---------------------------------------------------------------------------
// HMMA attention. One block = 64 q rows of one (b,h,chunk). 256 threads.
// Phase 1: S = (Q K^T)*scale*lam via split-3 mma  (warps: 2 q-half x 4 key-16)
// Softmax (exact, fp32 in smem).
// Phase 2: O = P V via split-3 mma (warps: 2 q-half x 4 d-16), epilogue writes
// O directly in split-3 [hi|hi|lo] layout to g_atts.
// ---------------------------------------------------------------------------
#define QP 72          // bf16 tile pitch (144 B)
#define SP 516         // S fp32 pitch
#define TILE_E (64 * QP)
#define ATT2_SMEM (4 * TILE_E * 2 + 64 * SP * 4 + 512 * 4 + 64 * 4)

__global__ __launch_bounds__(256, 1)
void attn2_kernel() {
    extern __shared__ char sm2[];
    __nv_bfloat16* QV0 = (__nv_bfloat16*)sm2;           // Qh / Vh
    __nv_bfloat16* QV1 = QV0 + TILE_E;                  // Ql / Vl
    __nv_bfloat16* KP0 = QV1 + TILE_E;                  // Kh / Ph
    __nv_bfloat16* KP1 = KP0 + TILE_E;                  // Kl / Pl
    float* Ss   = (float*)(KP1 + TILE_E);               // [64][516]
    float* gs   = Ss + 64 * SP;                         // [512]
    float* rinv = gs + 512;                             // [64]

    const int tid  = threadIdx.x;
    const int lane = tid & 31;
    const int wid  = tid >> 5;
    const int wq   = wid >> 2;       // q half (0..1)
    const int wk   = wid & 3;        // key/d sixteenth (0..3)

    const int cid = blockIdx.x;
    const int qt  = cid & 7;
    const int n   = (cid >> 3) & 7;
    const int h   = (cid >> 6) & 15;
    const int b   = cid >> 10;
    const int bh  = b * H_ + h;
    const int t0  = n * CS_ + qt * 64;
    const int tk0 = n * CS_;

    // ---- load Q hi/lo tiles + gates ----
    {
        const __nv_bfloat16* qh_g = g_s16 + S16_OFF(0, 0, bh, t0);
        const __nv_bfloat16* ql_g = g_s16 + S16_OFF(0, 1, bh, t0);
#pragma unroll
        for (int c = tid; c < 512; c += 256) {
            int r = c >> 3, c8 = (c & 7) * 8;
            cp16(QV0 + r * QP + c8, qh_g + c * 8);
            cp16(QV1 + r * QP + c8, ql_g + c * 8);
        }
        asm volatile("cp.async.commit_group;\n");
        for (int i = tid; i < 512; i += 256)
            gs[i] = 0.125f * g_lam[h * T_ + tk0 + i];
        asm volatile("cp.async.wait_group 0;\n");
    }
    __syncthreads();

    // ---- Q fragments (persist) ----
    unsigned qh[2][4][4], ql[2][4][4];
    {
        const int ar = lane & 15;
        const int ao = (lane >> 4) << 3;
#pragma unroll
        for (int mi = 0; mi < 2; mi++)
#pragma unroll
            for (int ks = 0; ks < 4; ks++) {
                int row = wq * 32 + mi * 16 + ar;
                int kc  = ks * 16 + ao;
                ldm_x4(qh[mi][ks][0], qh[mi][ks][1], qh[mi][ks][2], qh[mi][ks][3],
                       QV0 + row * QP + kc);
                ldm_x4(ql[mi][ks][0], ql[mi][ks][1], ql[mi][ks][2], ql[mi][ks][3],
                       QV1 + row * QP + kc);
            }
    }

    // ================= Phase 1: S = QK^T * gate =================
    for (int kt = 0; kt < 8; kt++) {
        __syncthreads();
        {
            const __nv_bfloat16* kh_g = g_s16 + S16_OFF(1, 0, bh, tk0 + kt * 64);
            const __nv_bfloat16* kl_g = g_s16 + S16_OFF(1, 1, bh, tk0 + kt * 64);
#pragma unroll
            for (int c = tid; c < 512; c += 256) {
                int r = c >> 3, c8 = (c & 7) * 8;
                cp16(KP0 + r * QP + c8, kh_g + c * 8);
                cp16(KP1 + r * QP + c8, kl_g + c * 8);
            }
            asm volatile("cp.async.commit_group;\n");
            asm volatile("cp.async.wait_group 0;\n");
        }
        __syncthreads();

        unsigned kh[4][4], kl[4][4];
        {
            const int br = wk * 16 + ((lane >> 4) << 3) + (lane & 7);
            const int bo = ((lane >> 3) & 1) << 3;
#pragma unroll
            for (int ks = 0; ks < 4; ks++) {
                int bk = ks * 16 + bo;
                ldm_x4(kh[ks][0], kh[ks][1], kh[ks][2], kh[ks][3],
                       KP0 + br * QP + bk);
                ldm_x4(kl[ks][0], kl[ks][1], kl[ks][2], kl[ks][3],
                       KP1 + br * QP + bk);
            }
        }

        float acc[2][2][4];
#pragma unroll
        for (int mi = 0; mi < 2; mi++)
#pragma unroll
            for (int nj = 0; nj < 2; nj++)
#pragma unroll
                for (int r = 0; r < 4; r++) acc[mi][nj][r] = 0.0f;

#pragma unroll
        for (int ks = 0; ks < 4; ks++)
#pragma unroll
            for (int mi = 0; mi < 2; mi++) {
                mma16816(acc[mi][0], qh[mi][ks], &kh[ks][0]);
                mma16816(acc[mi][1], qh[mi][ks], &kh[ks][2]);
                mma16816(acc[mi][0], qh[mi][ks], &kl[ks][0]);
                mma16816(acc[mi][1], qh[mi][ks], &kl[ks][2]);
                mma16816(acc[mi][0], ql[mi][ks], &kh[ks][0]);
                mma16816(acc[mi][1], ql[mi][ks], &kh[ks][2]);
            }

#pragma unroll
        for (int mi = 0; mi < 2; mi++)
#pragma unroll
            for (int nj = 0; nj < 2; nj++) {
                int rl = wq * 32 + mi * 16 + (lane >> 2);
                int cl = kt * 64 + wk * 16 + nj * 8 + (lane & 3) * 2;
                float g0 = gs[cl], g1 = gs[cl + 1];
                *(float2*)&Ss[(size_t)rl * SP + cl] =
                    make_float2(acc[mi][nj][0] * g0, acc[mi][nj][1] * g1);
                *(float2*)&Ss[(size_t)(rl + 8) * SP + cl] =
                    make_float2(acc[mi][nj][2] * g0, acc[mi][nj][3] * g1);
            }
    }
    __syncthreads();

    // ================= Softmax =================
    {
        for (int r = wid * 8; r < wid * 8 + 8; r++) {
            float* row = Ss + (size_t)r * SP;
            float vals[16];
            float m = -1e30f;
#pragma unroll
            for (int i = 0; i < 16; i++) {
                vals[i] = row[lane + i * 32];
                m = fmaxf(m, vals[i]);
            }
#pragma unroll
            for (int off = 16; off > 0; off >>= 1)
                m = fmaxf(m, __shfl_xor_sync(0xffffffffu, m, off));
            float s = 0.0f;
#pragma unroll
            for (int i = 0; i < 16; i++) {
                float e = __expf(vals[i] - m);
                s += e;
                row[lane + i * 32] = e;
            }
#pragma unroll
            for (int off = 16; off > 0; off >>= 1)
                s += __shfl_xor_sync(0xffffffffu, s, off);
            if (lane == 0) rinv[r] = 1.0f / s;
        }
    }

    // ================= Phase 2: O = P V =================
    float facc[2][2][4];
#pragma unroll
    for (int mi = 0; mi < 2; mi++)
#pragma unroll
        for (int nj = 0; nj < 2; nj++)
#pragma unroll
            for (int r = 0; r < 4; r++) facc[mi][nj][r] = 0.0f;

    for (int kt = 0; kt < 8; kt++) {
        __syncthreads();
        // convert P tile (fp32 -> bf16 hi/lo) into KP buffers
        for (int idx = tid; idx < 4096; idx += 256) {
            int r = idx >> 6, c = idx & 63;
            float p = Ss[(size_t)r * SP + kt * 64 + c];
            __nv_bfloat16 ph = __float2bfloat16_rn(p);
            KP0[r * QP + c] = ph;
            KP1[r * QP + c] = __float2bfloat16_rn(p - __bfloat162float(ph));
        }
        // load V tile hi/lo into QV buffers
        {
            const __nv_bfloat16* vh_g = g_s16 + S16_OFF(2, 0, bh, tk0 + kt * 64);
            const __nv_bfloat16* vl_g = g_s16 + S16_OFF(2, 1, bh, tk0 + kt * 64);
#pragma unroll
            for (int c = tid; c < 512; c += 256) {
                int r = c >> 3, c8 = (c & 7) * 8;
                cp16(QV0 + r * QP + c8, vh_g + c * 8);
                cp16(QV1 + r * QP + c8, vl_g + c * 8);
            }
            asm volatile("cp.async.commit_group;\n");
            asm volatile("cp.async.wait_group 0;\n");
        }
        __syncthreads();

        // P fragments
        unsigned pfh[2][4][4], pfl[2][4][4];
        {
            const int ar = lane & 15;
            const int ao = (lane >> 4) << 3;
#pragma unroll
            for (int mi = 0; mi < 2; mi++)
#pragma unroll
                for (int ks = 0; ks < 4; ks++) {
                    int row = wq * 32 + mi * 16 + ar;
                    int kc  = ks * 16 + ao;
                    ldm_x4(pfh[mi][ks][0], pfh[mi][ks][1], pfh[mi][ks][2], pfh[mi][ks][3],
                           KP0 + row * QP + kc);
                    ldm_x4(pfl[mi][ks][0], pfl[mi][ks][1], pfl[mi][ks][2], pfl[mi][ks][3],
                           KP1 + row * QP + kc);
                }
        }
        // V fragments via ldmatrix.trans : B[n=d][k=key] from V[k][n]
        unsigned vh[4][4], vl[4][4];
        {
            const int vm = lane >> 3;   // matrix id 0..3
            const int vr = lane & 7;
#pragma unroll
            for (int ks = 0; ks < 4; ks++) {
                int row = ks * 16 + ((vm & 1) << 3) + vr;
                int col = wk * 16 + ((vm >> 1) << 3);
                ldm_x4t(vh[ks][0], vh[ks][1], vh[ks][2], vh[ks][3],
                        QV0 + row * QP + col);
                ldm_x4t(vl[ks][0], vl[ks][1], vl[ks][2], vl[ks][3],
                        QV1 + row * QP + col);
            }
        }
#pragma unroll
        for (int ks = 0; ks < 4; ks++)
#pragma unroll
            for (int mi = 0; mi < 2; mi++) {
                mma16816(facc[mi][0], pfh[mi][ks], &vh[ks][0]);
                mma16816(facc[mi][1], pfh[mi][ks], &vh[ks][2]);
                mma16816(facc[mi][0], pfh[mi][ks], &vl[ks][0]);
                mma16816(facc[mi][1], pfh[mi][ks], &vl[ks][2]);
                mma16816(facc[mi][0], pfl[mi][ks], &vh[ks][0]);
                mma16816(facc[mi][1], pfl[mi][ks], &vh[ks][2]);
            }
    }

    // ---- epilogue: normalize, write O in split-3 [hi|hi|lo] layout ----
#pragma unroll
    for (int mi = 0; mi < 2; mi++)
#pragma unroll
        for (int nj = 0; nj < 2; nj++) {
            int rl = wq * 32 + mi * 16 + (lane >> 2);
            int cl = wk * 16 + nj * 8 + (lane & 3) * 2;
            int colC = h * 64 + cl;
#pragma unroll
            for (int half = 0; half < 2; half++) {
                int rr = rl + half * 8;
                float inv = rinv[rr];
                float o0 = facc[mi][nj][half * 2 + 0] * inv;
                float o1 = facc[mi][nj][half * 2 + 1] * inv;
                __nv_bfloat16 h0 = __float2bfloat16_rn(o0);
                __nv_bfloat16 h1 = __float2bfloat16_rn(o1);
                __nv_bfloat16 l0 = __float2bfloat16_rn(o0 - __bfloat162float(h0));
                __nv_bfloat16 l1 = __float2bfloat16_rn(o1 - __bfloat162float(h1));
                __nv_bfloat162 hp = __halves2bfloat162(h0, h1);
                __nv_bfloat162 lp = __halves2bfloat162(l0, l1);
                __nv_bfloat16* base = g_atts + (size_t)(b * T_ + t0 + rr) * K3_;
                *(__nv_bfloat162*)(base + colC)            = hp;
                *(__nv_bfloat162*)(base + C_ + colC)       = hp;
                *(__nv_bfloat162*)(base + 2 * C_ + colC)   = lp;
            }
        }
}

// ---------------------------------------------------------------------------
// Launch
// ---------------------------------------------------------------------------
extern "C" void kernel_launch(void* const* d_in, const int* in_sizes, int n_in,
                              void* d_out, int out_size) {
    const float* x    = (const float*)d_in[0];
    const float* Wqkv = (const float*)d_in[1];
    const float* Wout = (const float*)d_in[2];
    const float* bout = (const float*)d_in[3];
    const float* Wl1  = (const float*)d_in[4];
    const float* bl1  = (const float*)d_in[5];
    const float* Wl2  = (const float*)d_in[6];
    const float* bl2  = (const float*)d_in[7];
    float* out = (float*)d_out;

    float* qkv_ptr = nullptr;
    __nv_bfloat16 *xs = nullptr, *atts = nullptr, *wqkvs = nullptr, *wouts = nullptr;
    cudaGetSymbolAddress((void**)&qkv_ptr, g_qkv);
    cudaGetSymbolAddress((void**)&xs, g_xs);
    cudaGetSymbolAddress((void**)&atts, g_atts);
    cudaGetSymbolAddress((void**)&wqkvs, g_wqkvs);
    cudaGetSymbolAddress((void**)&wouts, g_wouts);

    cudaFuncSetAttribute(attn2_kernel,
                         cudaFuncAttributeMaxDynamicSharedMemorySize,
                         ATT2_SMEM);

    // 1) lambda gates
    lambda_kernel<<<(T_ + 127) / 128, 128>>>(Wl1, bl1, Wl2, bl2);

    // 2) splits for QKV GEMM
    {
        int threads = 256;
        size_t tx4 = (size_t)M_ * C_ / 4;
        split3_kernel<<<(unsigned)((tx4 + threads - 1) / threads), threads>>>(x, xs, M_, C_, 0);
        size_t tw4 = (size_t)QKV_N * C_ / 4;
        split3_kernel<<<(unsigned)((tw4 + threads - 1) / threads), threads>>>(Wqkv, wqkvs, QKV_N, C_, 1);
    }

    // 3) QKV projection (tensor cores)
    {
        dim3 grid(QKV_N / 128, M_ / 128);
        hgemm_bf16_kernel<<<grid, 256>>>(xs, wqkvs, nullptr, qkv_ptr, M_, QKV_N, K3_);
    }

    // 4) q/k/v -> bf16 hi/lo per-(b,h) layout
    {
        size_t total = (size_t)M_ * QKV_N / 4;
        qkvsplit_kernel<<<(unsigned)((total + 255) / 256), 256>>>();
    }

    // 5) HMMA attention -> g_atts (split-3 layout, ready for out GEMM)
    attn2_kernel<<<B_ * H_ * NC_ * (CS_ / 64), 256, ATT2_SMEM>>>();

    // 6) split Wout, then output projection (tensor cores)
    {
        int threads = 256;
        size_t tw4 = (size_t)C_ * C_ / 4;
        split3_kernel<<<(unsigned)((tw4 + threads - 1) / threads), threads>>>(Wout, wouts, C_, C_, 1);
    }
    {
        dim3 grid(C_ / 128, M_ / 128);
        hgemm_bf16_kernel<<<grid, 256>>>(atts, wouts, bout, out, M_, C_, K3_);
    }
}

// round 9
// speedup vs baseline: 2.6350x; 1.3280x over previous
#include <cuda_runtime.h>
#include <cuda_bf16.h>
#include <math.h>
#include <stdint.h>

// ---------------------------------------------------------------------------
// LogLinearAttention — R9: mma.sync everywhere (harness targets sm_100, no
// tcgen05). Projections = validated R6 hgemm. Attention = flash-style online
// softmax, P in registers, double-buffered K/V, 128 q-rows per block.
//   B=4, T=4096, C=1024, H=16, dh=64, nc=8, cs=512
// ---------------------------------------------------------------------------

#define B_  4
#define T_  4096
#define C_  1024
#define H_  16
#define DH_ 64
#define NC_ 8
#define CS_ 512
#define QKV_N (3 * C_)
#define M_  (B_ * T_)
#define K3_ (3 * C_)

__device__ float g_qkv[(size_t)M_ * QKV_N];            // fp32 QKV
__device__ float g_lam[H_ * T_];
__device__ __nv_bfloat16 g_xs[(size_t)M_ * K3_];       // split3 x    [hi|hi|lo]
__device__ __nv_bfloat16 g_atts[(size_t)M_ * K3_];     // split3 O    [hi|hi|lo]
__device__ __nv_bfloat16 g_wqkvs[(size_t)QKV_N * K3_]; // split3 Wqkv [hi|lo|hi]
__device__ __nv_bfloat16 g_wouts[(size_t)C_ * K3_];    // split3 Wout [hi|lo|hi]
// q/k/v hi/lo per-(b,h): [comp3][part2][bh64][t4096][d64]
__device__ __nv_bfloat16 g_s16[(size_t)3 * 2 * 64 * T_ * DH_];

#define S16_OFF(comp, part, bh, t) \
    (((((size_t)((comp) * 2 + (part)) * 64 + (bh)) * T_) + (t)) * DH_)

// ---------------------------------------------------------------------------
__global__ void lambda_kernel(const float* __restrict__ Wl1,
                              const float* __restrict__ bl1,
                              const float* __restrict__ Wl2,
                              const float* __restrict__ bl2) {
    int t = blockIdx.x * blockDim.x + threadIdx.x;
    if (t >= T_) return;
    float lp = logf((float)t + 1.0f);
    float h1[64];
#pragma unroll
    for (int j = 0; j < 64; j++)
        h1[j] = fmaxf(lp * Wl1[j] + bl1[j], 0.0f);
#pragma unroll
    for (int h = 0; h < H_; h++) {
        float s = bl2[h];
        const float* w = Wl2 + h * 64;
#pragma unroll
        for (int j = 0; j < 64; j++) s += w[j] * h1[j];
        g_lam[h * T_ + t] = 1.0f / (1.0f + __expf(-s));
    }
}

// ---------------------------------------------------------------------------
__global__ void split3_kernel(const float* __restrict__ A,
                              __nv_bfloat16* __restrict__ out,
                              int Mrows, int K, int variant) {
    size_t i4 = (size_t)blockIdx.x * blockDim.x + threadIdx.x;
    size_t total = (size_t)Mrows * K / 4;
    if (i4 >= total) return;
    size_t e0 = i4 * 4;
    int row = (int)(e0 / K);
    int k   = (int)(e0 % K);
    float4 v = *(const float4*)(A + e0);
    __nv_bfloat16 h0 = __float2bfloat16_rn(v.x);
    __nv_bfloat16 h1 = __float2bfloat16_rn(v.y);
    __nv_bfloat16 h2 = __float2bfloat16_rn(v.z);
    __nv_bfloat16 h3 = __float2bfloat16_rn(v.w);
    __nv_bfloat16 l0 = __float2bfloat16_rn(v.x - __bfloat162float(h0));
    __nv_bfloat16 l1 = __float2bfloat16_rn(v.y - __bfloat162float(h1));
    __nv_bfloat16 l2 = __float2bfloat16_rn(v.z - __bfloat162float(h2));
    __nv_bfloat16 l3 = __float2bfloat16_rn(v.w - __bfloat162float(h3));
    __nv_bfloat162 hA = __halves2bfloat162(h0, h1);
    __nv_bfloat162 hB = __halves2bfloat162(h2, h3);
    __nv_bfloat162 lA = __halves2bfloat162(l0, l1);
    __nv_bfloat162 lB = __halves2bfloat162(l2, l3);
    __nv_bfloat16* base = out + (size_t)row * (3 * K);
    *(__nv_bfloat162*)(base + k)     = hA;
    *(__nv_bfloat162*)(base + k + 2) = hB;
    if (variant == 0) {
        *(__nv_bfloat162*)(base + K + k)         = hA;
        *(__nv_bfloat162*)(base + K + k + 2)     = hB;
        *(__nv_bfloat162*)(base + 2 * K + k)     = lA;
        *(__nv_bfloat162*)(base + 2 * K + k + 2) = lB;
    } else {
        *(__nv_bfloat162*)(base + K + k)         = lA;
        *(__nv_bfloat162*)(base + K + k + 2)     = lB;
        *(__nv_bfloat162*)(base + 2 * K + k)     = hA;
        *(__nv_bfloat162*)(base + 2 * K + k + 2) = hB;
    }
}

// ---------------------------------------------------------------------------
// qkv_split: g_qkv fp32 -> g_s16 bf16 hi/lo per-(b,h)
// ---------------------------------------------------------------------------
__global__ void qkvsplit_kernel() {
    size_t idx = (size_t)blockIdx.x * blockDim.x + threadIdx.x;
    size_t total = (size_t)M_ * QKV_N / 4;
    if (idx >= total) return;
    int bt = (int)(idx / (QKV_N / 4));
    int c4 = (int)(idx % (QKV_N / 4)) * 4;
    int comp = c4 >> 10;
    int rem  = c4 & 1023;
    int h = rem >> 6;
    int d = rem & 63;
    int b = bt >> 12;
    int t = bt & 4095;
    int bh = b * H_ + h;
    float4 v = *(const float4*)(g_qkv + (size_t)bt * QKV_N + c4);
    __nv_bfloat16 h0 = __float2bfloat16_rn(v.x);
    __nv_bfloat16 h1 = __float2bfloat16_rn(v.y);
    __nv_bfloat16 h2 = __float2bfloat16_rn(v.z);
    __nv_bfloat16 h3 = __float2bfloat16_rn(v.w);
    __nv_bfloat16 l0 = __float2bfloat16_rn(v.x - __bfloat162float(h0));
    __nv_bfloat16 l1 = __float2bfloat16_rn(v.y - __bfloat162float(h1));
    __nv_bfloat16 l2 = __float2bfloat16_rn(v.z - __bfloat162float(h2));
    __nv_bfloat16 l3 = __float2bfloat16_rn(v.w - __bfloat162float(h3));
    __nv_bfloat16* hid = g_s16 + S16_OFF(comp, 0, bh, t) + d;
    __nv_bfloat16* lod = g_s16 + S16_OFF(comp, 1, bh, t) + d;
    *(__nv_bfloat162*)(hid)     = __halves2bfloat162(h0, h1);
    *(__nv_bfloat162*)(hid + 2) = __halves2bfloat162(h2, h3);
    *(__nv_bfloat162*)(lod)     = __halves2bfloat162(l0, l1);
    *(__nv_bfloat162*)(lod + 2) = __halves2bfloat162(l2, l3);
}

// ---------------------------------------------------------------------------
// PTX helpers
// ---------------------------------------------------------------------------
__device__ __forceinline__ unsigned smem_u32(const void* p) {
    return (unsigned)__cvta_generic_to_shared(p);
}
__device__ __forceinline__ void cp16(void* smem_dst, const void* gmem_src) {
    asm volatile("cp.async.cg.shared.global [%0], [%1], 16;\n"
                 :: "r"(smem_u32(smem_dst)), "l"(gmem_src));
}
__device__ __forceinline__ void ldm_x4(unsigned& r0, unsigned& r1,
                                       unsigned& r2, unsigned& r3,
                                       const void* p) {
    asm volatile("ldmatrix.sync.aligned.m8n8.x4.shared.b16 {%0,%1,%2,%3}, [%4];\n"
                 : "=r"(r0), "=r"(r1), "=r"(r2), "=r"(r3) : "r"(smem_u32(p)));
}
__device__ __forceinline__ void ldm_x4t(unsigned& r0, unsigned& r1,
                                        unsigned& r2, unsigned& r3,
                                        const void* p) {
    asm volatile("ldmatrix.sync.aligned.m8n8.x4.trans.shared.b16 {%0,%1,%2,%3}, [%4];\n"
                 : "=r"(r0), "=r"(r1), "=r"(r2), "=r"(r3) : "r"(smem_u32(p)));
}
__device__ __forceinline__ void mma16816(float* c, const unsigned* a, const unsigned* b) {
    asm volatile("mma.sync.aligned.m16n8k16.row.col.f32.bf16.bf16.f32 "
                 "{%0,%1,%2,%3}, {%4,%5,%6,%7}, {%8,%9}, {%0,%1,%2,%3};\n"
                 : "+f"(c[0]), "+f"(c[1]), "+f"(c[2]), "+f"(c[3])
                 : "r"(a[0]), "r"(a[1]), "r"(a[2]), "r"(a[3]),
                   "r"(b[0]), "r"(b[1]));
}
__device__ __forceinline__ unsigned pack_bf16(float a, float b) {
    unsigned ha = (unsigned)__bfloat16_as_ushort(__float2bfloat16_rn(a));
    unsigned hb = (unsigned)__bfloat16_as_ushort(__float2bfloat16_rn(b));
    return ha | (hb << 16);
}

// ---------------------------------------------------------------------------
// bf16 HMMA GEMM (validated R5/R6): C[M,N] = A[M,Kp] @ B[N,Kp]^T (+bias)
// ---------------------------------------------------------------------------
#define GP 40

__global__ __launch_bounds__(256)
void hgemm_bf16_kernel(const __nv_bfloat16* __restrict__ A,
                       const __nv_bfloat16* __restrict__ B,
                       const float* __restrict__ bias,
                       float* __restrict__ C,
                       int M, int N, int Kp) {
    __shared__ __nv_bfloat16 As[2][128 * GP];
    __shared__ __nv_bfloat16 Bs[2][128 * GP];

    const int tid  = threadIdx.x;
    const int lane = tid & 31;
    const int wid  = tid >> 5;
    const int wm   = wid >> 2;
    const int wn   = wid & 3;
    const int m0   = blockIdx.y * 128;
    const int n0   = blockIdx.x * 128;

    float acc[4][4][4];
#pragma unroll
    for (int i = 0; i < 4; i++)
#pragma unroll
        for (int j = 0; j < 4; j++)
#pragma unroll
            for (int r = 0; r < 4; r++) acc[i][j][r] = 0.0f;

    const int KT = Kp / 32;
    {
        int c1 = tid, c2 = tid + 256;
        int r1 = c1 >> 2, kc1 = c1 & 3;
        int r2 = c2 >> 2, kc2 = c2 & 3;
        cp16(&As[0][r1 * GP + kc1 * 8], A + (size_t)(m0 + r1) * Kp + kc1 * 8);
        cp16(&As[0][r2 * GP + kc2 * 8], A + (size_t)(m0 + r2) * Kp + kc2 * 8);
        cp16(&Bs[0][r1 * GP + kc1 * 8], B + (size_t)(n0 + r1) * Kp + kc1 * 8);
        cp16(&Bs[0][r2 * GP + kc2 * 8], B + (size_t)(n0 + r2) * Kp + kc2 * 8);
        asm volatile("cp.async.commit_group;\n");
        asm volatile("cp.async.wait_group 0;\n");
    }
    __syncthreads();

    int buf = 0;
    for (int kt = 0; kt < KT; kt++) {
        if (kt + 1 < KT) {
            int k0 = (kt + 1) * 32;
            int c1 = tid, c2 = tid + 256;
            int r1 = c1 >> 2, kc1 = c1 & 3;
            int r2 = c2 >> 2, kc2 = c2 & 3;
            cp16(&As[buf ^ 1][r1 * GP + kc1 * 8], A + (size_t)(m0 + r1) * Kp + k0 + kc1 * 8);
            cp16(&As[buf ^ 1][r2 * GP + kc2 * 8], A + (size_t)(m0 + r2) * Kp + k0 + kc2 * 8);
            cp16(&Bs[buf ^ 1][r1 * GP + kc1 * 8], B + (size_t)(n0 + r1) * Kp + k0 + kc1 * 8);
            cp16(&Bs[buf ^ 1][r2 * GP + kc2 * 8], B + (size_t)(n0 + r2) * Kp + k0 + kc2 * 8);
            asm volatile("cp.async.commit_group;\n");
        }
        const __nv_bfloat16* Ab = As[buf];
        const __nv_bfloat16* Bb = Bs[buf];
#pragma unroll
        for (int ks = 0; ks < 2; ks++) {
            unsigned a[4][4], b[4][2];
            const int ar = lane & 15;
            const int ak = ks * 16 + ((lane >> 4) << 3);
#pragma unroll
            for (int mi = 0; mi < 4; mi++)
                ldm_x4(a[mi][0], a[mi][1], a[mi][2], a[mi][3],
                       Ab + (wm * 64 + mi * 16 + ar) * GP + ak);
            const int br = ((lane >> 4) << 3) + (lane & 7);
            const int bk = ks * 16 + (((lane >> 3) & 1) << 3);
#pragma unroll
            for (int njp = 0; njp < 2; njp++) {
                unsigned r0, r1, r2, r3;
                ldm_x4(r0, r1, r2, r3, Bb + (wn * 32 + njp * 16 + br) * GP + bk);
                b[njp * 2][0] = r0; b[njp * 2][1] = r1;
                b[njp * 2 + 1][0] = r2; b[njp * 2 + 1][1] = r3;
            }
#pragma unroll
            for (int mi = 0; mi < 4; mi++)
#pragma unroll
                for (int nj = 0; nj < 4; nj++)
                    mma16816(acc[mi][nj], a[mi], b[nj]);
        }
        if (kt + 1 < KT) asm volatile("cp.async.wait_group 0;\n");
        __syncthreads();
        buf ^= 1;
    }

    const int rbase = m0 + wm * 64 + (lane >> 2);
    const int cbase = n0 + wn * 32 + (lane & 3) * 2;
#pragma unroll
    for (int mi = 0; mi < 4; mi++) {
#pragma unroll
        for (int nj = 0; nj < 4; nj++) {
            int col = cbase + nj * 8;
            float b0 = bias ? bias[col] : 0.0f;
            float b1 = bias ? bias[col + 1] : 0.0f;
            int r0 = rbase + mi * 16;
            float2 v0 = make_float2(acc[mi][nj][0] + b0, acc[mi][nj][1] + b1);
            float2 v1 = make_float2(acc[mi][nj][2] + b0, acc[mi][nj][3] + b1);
            *(float2*)(C + (size_t)r0 * N + col)       = v0;
            *(float2*)(C + (size_t)(r0 + 8) * N + col) = v1;
        }
    }
}

// ---------------------------------------------------------------------------
// Flash-style HMMA attention. One block = 128 q rows of one (b,h,chunk).
// 256 threads / 8 warps; warp w owns q rows [16w,16w+16), ALL d=64.
// Online softmax; P stays in registers (C-frag -> A-frag identity);
// K/V hi/lo tiles double-buffered via cp.async.
// smem: 2 stages x (Kh|Kl|Vh|Vl)[64][72] + gates = ~74 KB.
// ---------------------------------------------------------------------------
#define QP 72
#define MAT_E (64 * QP)                 // 4608 elems per matrix part
#define STAGE_E (4 * MAT_E)             // 18432 elems per stage
#define ATT3_SMEM (2 * STAGE_E * 2 + 512 * 4)

__global__ __launch_bounds__(256)
void attn3_kernel() {
    extern __shared__ char sm3[];
    __nv_bfloat16* KV = (__nv_bfloat16*)sm3;       // 2 stages
    float* gs = (float*)(KV + 2 * STAGE_E);        // [512] gate = scale*lam

    const int tid  = threadIdx.x;
    const int lane = tid & 31;
    const int wid  = tid >> 5;

    const int cid = blockIdx.x;                    // 2048 blocks
    const int qt  = cid & 3;                       // q 128-tile
    const int n   = (cid >> 2) & 7;
    const int h   = (cid >> 5) & 15;
    const int b   = cid >> 9;
    const int bh  = b * H_ + h;
    const int t0  = n * CS_ + qt * 128;
    const int tk0 = n * CS_;

    // ---- Q load into stage0 area (aliased; freed after frag extraction) ----
    for (int q = tid; q < 2048; q += 256) {
        int part = q >> 10;                        // 0=hi,1=lo
        int r = (q >> 3) & 127;
        int c8 = (q & 7) * 8;
        cp16(KV + part * (2 * MAT_E) + r * QP + c8,
             g_s16 + S16_OFF(0, part, bh, t0 + r) + c8);
    }
    asm volatile("cp.async.commit_group;\n");
    for (int i = tid; i < 512; i += 256)
        gs[i] = 0.125f * g_lam[h * T_ + tk0 + i];
    asm volatile("cp.async.wait_group 0;\n");
    __syncthreads();

    // Q fragments (persist): rows 16*wid + (lane&15)
    unsigned qh[4][4], ql[4][4];
    {
        const int ar = 16 * wid + (lane & 15);
        const int ao = (lane >> 4) << 3;
#pragma unroll
        for (int ks = 0; ks < 4; ks++) {
            ldm_x4(qh[ks][0], qh[ks][1], qh[ks][2], qh[ks][3],
                   KV + ar * QP + ks * 16 + ao);
            ldm_x4(ql[ks][0], ql[ks][1], ql[ks][2], ql[ks][3],
                   KV + 2 * MAT_E + ar * QP + ks * 16 + ao);
        }
    }
    __syncthreads();

    // ---- K/V stage fill: parts {Kh,Kl,Vh,Vl} ----
    auto fillKV = [&](int st, int kt) {
        __nv_bfloat16* stage = KV + st * STAGE_E;
        int tb = tk0 + kt * 64;
        for (int q = tid; q < 2048; q += 256) {
            int part = q >> 9;                     // 0..3
            int r = (q >> 3) & 63;
            int c8 = (q & 7) * 8;
            int comp = 1 + (part >> 1);            // 1=K, 2=V
            int lo = part & 1;
            cp16(stage + part * MAT_E + r * QP + c8,
                 g_s16 + S16_OFF(comp, lo, bh, tb + r) + c8);
        }
        asm volatile("cp.async.commit_group;\n");
    };
    fillKV(0, 0);
    fillKV(1, 1);

    // ---- online softmax state + O accumulators ----
    float m0 = -1e30f, m1 = -1e30f;                // row max (rows r, r+8)
    float l0 = 0.0f, l1 = 0.0f;                    // lane-partial row sums
    float facc[8][4];
#pragma unroll
    for (int i = 0; i < 8; i++)
#pragma unroll
        for (int j = 0; j < 4; j++) facc[i][j] = 0.0f;

    for (int kt = 0; kt < 8; kt++) {
        if (kt == 7) { asm volatile("cp.async.wait_group 0;\n" ::: "memory"); }
        else        { asm volatile("cp.async.wait_group 1;\n" ::: "memory"); }
        __syncthreads();
        __nv_bfloat16* Kh = KV + (kt & 1) * STAGE_E;
        __nv_bfloat16* Kl = Kh + MAT_E;
        __nv_bfloat16* Vh = Kl + MAT_E;
        __nv_bfloat16* Vl = Vh + MAT_E;

        // ===== S = Q K^T (split-3) =====
        float s[8][4];
#pragma unroll
        for (int i = 0; i < 8; i++)
#pragma unroll
            for (int j = 0; j < 4; j++) s[i][j] = 0.0f;

        {
            const int br = ((lane >> 4) << 3) + (lane & 7);
            const int bo = ((lane >> 3) & 1) << 3;
#pragma unroll
            for (int np = 0; np < 4; np++) {
                int rowb = np * 16 + br;
#pragma unroll
                for (int ks = 0; ks < 4; ks++) {
                    unsigned kh4[4], kl4[4];
                    int bk = ks * 16 + bo;
                    ldm_x4(kh4[0], kh4[1], kh4[2], kh4[3], Kh + rowb * QP + bk);
                    ldm_x4(kl4[0], kl4[1], kl4[2], kl4[3], Kl + rowb * QP + bk);
                    mma16816(s[2 * np],     qh[ks], &kh4[0]);
                    mma16816(s[2 * np + 1], qh[ks], &kh4[2]);
                    mma16816(s[2 * np],     qh[ks], &kl4[0]);
                    mma16816(s[2 * np + 1], qh[ks], &kl4[2]);
                    mma16816(s[2 * np],     ql[ks], &kh4[0]);
                    mma16816(s[2 * np + 1], ql[ks], &kh4[2]);
                }
            }
        }

        // ===== gate + online softmax =====
        float tm0 = -1e30f, tm1 = -1e30f;
#pragma unroll
        for (int nt = 0; nt < 8; nt++) {
            int c = kt * 64 + nt * 8 + (lane & 3) * 2;
            float g0 = gs[c - kt * 64 + kt * 64];  // = gs[key within chunk]
            float g1 = gs[c - kt * 64 + kt * 64 + 1];
            s[nt][0] *= g0; s[nt][1] *= g1;
            s[nt][2] *= g0; s[nt][3] *= g1;
            tm0 = fmaxf(tm0, fmaxf(s[nt][0], s[nt][1]));
            tm1 = fmaxf(tm1, fmaxf(s[nt][2], s[nt][3]));
        }
        tm0 = fmaxf(tm0, __shfl_xor_sync(0xffffffffu, tm0, 1));
        tm0 = fmaxf(tm0, __shfl_xor_sync(0xffffffffu, tm0, 2));
        tm1 = fmaxf(tm1, __shfl_xor_sync(0xffffffffu, tm1, 1));
        tm1 = fmaxf(tm1, __shfl_xor_sync(0xffffffffu, tm1, 2));

        float mn0 = fmaxf(m0, tm0), mn1 = fmaxf(m1, tm1);
        float a0 = __expf(m0 - mn0), a1 = __expf(m1 - mn1);
        m0 = mn0; m1 = mn1;

        unsigned ph[4][4], pl[4][4];
        float ts0 = 0.0f, ts1 = 0.0f;
#pragma unroll
        for (int j = 0; j < 4; j++) {
#pragma unroll
            for (int half = 0; half < 2; half++) {
                int nt = 2 * j + half;
                float p00 = __expf(s[nt][0] - m0);
                float p01 = __expf(s[nt][1] - m0);
                float p10 = __expf(s[nt][2] - m1);
                float p11 = __expf(s[nt][3] - m1);
                ts0 += p00 + p01;
                ts1 += p10 + p11;
                unsigned hp0 = pack_bf16(p00, p01);
                unsigned hp1 = pack_bf16(p10, p11);
                ph[j][half * 2]     = hp0;
                ph[j][half * 2 + 1] = hp1;
                // lo residuals
                float r00 = p00 - __bfloat162float(__ushort_as_bfloat16((unsigned short)(hp0 & 0xffff)));
                float r01 = p01 - __bfloat162float(__ushort_as_bfloat16((unsigned short)(hp0 >> 16)));
                float r10 = p10 - __bfloat162float(__ushort_as_bfloat16((unsigned short)(hp1 & 0xffff)));
                float r11 = p11 - __bfloat162float(__ushort_as_bfloat16((unsigned short)(hp1 >> 16)));
                pl[j][half * 2]     = pack_bf16(r00, r01);
                pl[j][half * 2 + 1] = pack_bf16(r10, r11);
            }
        }
        l0 = l0 * a0 + ts0;
        l1 = l1 * a1 + ts1;
#pragma unroll
        for (int nt = 0; nt < 8; nt++) {
            facc[nt][0] *= a0; facc[nt][1] *= a0;
            facc[nt][2] *= a1; facc[nt][3] *= a1;
        }

        // ===== O += P V (split-3) =====
        {
            const int vm = lane >> 3;
            const int vr = lane & 7;
#pragma unroll
            for (int dt = 0; dt < 4; dt++) {
#pragma unroll
                for (int ks = 0; ks < 4; ks++) {
                    unsigned vh4[4], vl4[4];
                    int row = ks * 16 + ((vm & 1) << 3) + vr;
                    int col = dt * 16 + ((vm >> 1) << 3);
                    ldm_x4t(vh4[0], vh4[1], vh4[2], vh4[3], Vh + row * QP + col);
                    ldm_x4t(vl4[0], vl4[1], vl4[2], vl4[3], Vl + row * QP + col);
                    mma16816(facc[2 * dt],     ph[ks], &vh4[0]);
                    mma16816(facc[2 * dt + 1], ph[ks], &vh4[2]);
                    mma16816(facc[2 * dt],     ph[ks], &vl4[0]);
                    mma16816(facc[2 * dt + 1], ph[ks], &vl4[2]);
                    mma16816(facc[2 * dt],     pl[ks], &vh4[0]);
                    mma16816(facc[2 * dt + 1], pl[ks], &vh4[2]);
                }
            }
        }

        __syncthreads();
        if (kt + 2 < 8) fillKV(kt & 1, kt + 2);
    }

    // ---- epilogue: normalize, write split-3 [hi|hi|lo] to g_atts ----
    l0 += __shfl_xor_sync(0xffffffffu, l0, 1);
    l0 += __shfl_xor_sync(0xffffffffu, l0, 2);
    l1 += __shfl_xor_sync(0xffffffffu, l1, 1);
    l1 += __shfl_xor_sync(0xffffffffu, l1, 2);
    float inv0 = 1.0f / l0, inv1 = 1.0f / l1;

    int qrow0 = t0 + 16 * wid + (lane >> 2);
#pragma unroll
    for (int nt = 0; nt < 8; nt++) {
        int colC = h * 64 + nt * 8 + (lane & 3) * 2;
#pragma unroll
        for (int half = 0; half < 2; half++) {
            int rr = qrow0 + half * 8;
            float inv = half ? inv1 : inv0;
            float o0 = facc[nt][half * 2 + 0] * inv;
            float o1 = facc[nt][half * 2 + 1] * inv;
            __nv_bfloat16 h0 = __float2bfloat16_rn(o0);
            __nv_bfloat16 h1 = __float2bfloat16_rn(o1);
            __nv_bfloat16 L0 = __float2bfloat16_rn(o0 - __bfloat162float(h0));
            __nv_bfloat16 L1 = __float2bfloat16_rn(o1 - __bfloat162float(h1));
            __nv_bfloat162 hp = __halves2bfloat162(h0, h1);
            __nv_bfloat162 lp = __halves2bfloat162(L0, L1);
            __nv_bfloat16* base = g_atts + (size_t)(b * T_ + rr) * K3_;
            *(__nv_bfloat162*)(base + colC)          = hp;
            *(__nv_bfloat162*)(base + C_ + colC)     = hp;
            *(__nv_bfloat162*)(base + 2 * C_ + colC) = lp;
        }
    }
}

// ---------------------------------------------------------------------------
// Launch
// ---------------------------------------------------------------------------
extern "C" void kernel_launch(void* const* d_in, const int* in_sizes, int n_in,
                              void* d_out, int out_size) {
    const float* x    = (const float*)d_in[0];
    const float* Wqkv = (const float*)d_in[1];
    const float* Wout = (const float*)d_in[2];
    const float* bout = (const float*)d_in[3];
    const float* Wl1  = (const float*)d_in[4];
    const float* bl1  = (const float*)d_in[5];
    const float* Wl2  = (const float*)d_in[6];
    const float* bl2  = (const float*)d_in[7];
    float* out = (float*)d_out;

    float* qkv_ptr = nullptr;
    __nv_bfloat16 *xs = nullptr, *atts = nullptr, *wqkvs = nullptr, *wouts = nullptr;
    cudaGetSymbolAddress((void**)&qkv_ptr, g_qkv);
    cudaGetSymbolAddress((void**)&xs, g_xs);
    cudaGetSymbolAddress((void**)&atts, g_atts);
    cudaGetSymbolAddress((void**)&wqkvs, g_wqkvs);
    cudaGetSymbolAddress((void**)&wouts, g_wouts);

    cudaFuncSetAttribute(attn3_kernel,
                         cudaFuncAttributeMaxDynamicSharedMemorySize, ATT3_SMEM);

    // 1) lambda gates
    lambda_kernel<<<(T_ + 127) / 128, 128>>>(Wl1, bl1, Wl2, bl2);

    // 2) splits for QKV GEMM
    {
        int threads = 256;
        size_t tx4 = (size_t)M_ * C_ / 4;
        split3_kernel<<<(unsigned)((tx4 + threads - 1) / threads), threads>>>(x, xs, M_, C_, 0);
        size_t tw4 = (size_t)QKV_N * C_ / 4;
        split3_kernel<<<(unsigned)((tw4 + threads - 1) / threads), threads>>>(Wqkv, wqkvs, QKV_N, C_, 1);
    }

    // 3) QKV projection (HMMA)
    {
        dim3 grid(QKV_N / 128, M_ / 128);
        hgemm_bf16_kernel<<<grid, 256>>>(xs, wqkvs, nullptr, qkv_ptr, M_, QKV_N, K3_);
    }

    // 4) q/k/v -> bf16 hi/lo per-(b,h)
    {
        size_t total = (size_t)M_ * QKV_N / 4;
        qkvsplit_kernel<<<(unsigned)((total + 255) / 256), 256>>>();
    }

    // 5) flash attention -> g_atts (split-3 layout)
    attn3_kernel<<<B_ * H_ * NC_ * (CS_ / 128), 256, ATT3_SMEM>>>();

    // 6) split Wout, output projection (HMMA)
    {
        int threads = 256;
        size_t tw4 = (size_t)C_ * C_ / 4;
        split3_kernel<<<(unsigned)((tw4 + threads - 1) / threads), threads>>>(Wout, wouts, C_, C_, 1);
    }
    {
        dim3 grid(C_ / 128, M_ / 128);
        hgemm_bf16_kernel<<<grid, 256>>>(atts, wouts, bout, out, M_, C_, K3_);
    }
}

// round 10
// speedup vs baseline: 2.9468x; 1.1183x over previous
#include <cuda_runtime.h>
#include <cuda_bf16.h>
#include <math.h>
#include <stdint.h>

// ---------------------------------------------------------------------------
// LogLinearAttention — R10: fragment-level split-3 GEMM ([hi|lo] K'=2K
// operands, 3 mma per fragment pair) — cuts GEMM LDSM/global traffic 33%
// and barriers 3x vs packed K'=3K. Flash attention from R9 (validated),
// epilogue now writes [hi|lo].
//   B=4, T=4096, C=1024, H=16, dh=64, nc=8, cs=512
// ---------------------------------------------------------------------------

#define B_  4
#define T_  4096
#define C_  1024
#define H_  16
#define DH_ 64
#define NC_ 8
#define CS_ 512
#define QKV_N (3 * C_)
#define M_  (B_ * T_)
#define K2_ (2 * C_)            // [hi|lo] packed K' = 2048

__device__ float g_qkv[(size_t)M_ * QKV_N];            // fp32 QKV
__device__ float g_lam[H_ * T_];
__device__ __nv_bfloat16 g_xs[(size_t)M_ * K2_];       // x    [hi|lo]
__device__ __nv_bfloat16 g_atts[(size_t)M_ * K2_];     // O    [hi|lo]
__device__ __nv_bfloat16 g_wqkvs[(size_t)QKV_N * K2_]; // Wqkv [hi|lo]
__device__ __nv_bfloat16 g_wouts[(size_t)C_ * K2_];    // Wout [hi|lo]
// q/k/v hi/lo per-(b,h): [comp3][part2][bh64][t4096][d64]
__device__ __nv_bfloat16 g_s16[(size_t)3 * 2 * 64 * T_ * DH_];

#define S16_OFF(comp, part, bh, t) \
    (((((size_t)((comp) * 2 + (part)) * 64 + (bh)) * T_) + (t)) * DH_)

// ---------------------------------------------------------------------------
__global__ void lambda_kernel(const float* __restrict__ Wl1,
                              const float* __restrict__ bl1,
                              const float* __restrict__ Wl2,
                              const float* __restrict__ bl2) {
    int t = blockIdx.x * blockDim.x + threadIdx.x;
    if (t >= T_) return;
    float lp = logf((float)t + 1.0f);
    float h1[64];
#pragma unroll
    for (int j = 0; j < 64; j++)
        h1[j] = fmaxf(lp * Wl1[j] + bl1[j], 0.0f);
#pragma unroll
    for (int h = 0; h < H_; h++) {
        float s = bl2[h];
        const float* w = Wl2 + h * 64;
#pragma unroll
        for (int j = 0; j < 64; j++) s += w[j] * h1[j];
        g_lam[h * T_ + t] = 1.0f / (1.0f + __expf(-s));
    }
}

// ---------------------------------------------------------------------------
// split2: fp32 A[M,K] -> bf16 out[M,2K] = [hi | lo]
// ---------------------------------------------------------------------------
__global__ void split2_kernel(const float* __restrict__ A,
                              __nv_bfloat16* __restrict__ out,
                              int Mrows, int K) {
    size_t i4 = (size_t)blockIdx.x * blockDim.x + threadIdx.x;
    size_t total = (size_t)Mrows * K / 4;
    if (i4 >= total) return;
    size_t e0 = i4 * 4;
    int row = (int)(e0 / K);
    int k   = (int)(e0 % K);
    float4 v = *(const float4*)(A + e0);
    __nv_bfloat16 h0 = __float2bfloat16_rn(v.x);
    __nv_bfloat16 h1 = __float2bfloat16_rn(v.y);
    __nv_bfloat16 h2 = __float2bfloat16_rn(v.z);
    __nv_bfloat16 h3 = __float2bfloat16_rn(v.w);
    __nv_bfloat16 l0 = __float2bfloat16_rn(v.x - __bfloat162float(h0));
    __nv_bfloat16 l1 = __float2bfloat16_rn(v.y - __bfloat162float(h1));
    __nv_bfloat16 l2 = __float2bfloat16_rn(v.z - __bfloat162float(h2));
    __nv_bfloat16 l3 = __float2bfloat16_rn(v.w - __bfloat162float(h3));
    __nv_bfloat16* base = out + (size_t)row * (2 * K);
    *(__nv_bfloat162*)(base + k)         = __halves2bfloat162(h0, h1);
    *(__nv_bfloat162*)(base + k + 2)     = __halves2bfloat162(h2, h3);
    *(__nv_bfloat162*)(base + K + k)     = __halves2bfloat162(l0, l1);
    *(__nv_bfloat162*)(base + K + k + 2) = __halves2bfloat162(l2, l3);
}

// ---------------------------------------------------------------------------
// qkv_split: g_qkv fp32 -> g_s16 bf16 hi/lo per-(b,h)
// ---------------------------------------------------------------------------
__global__ void qkvsplit_kernel() {
    size_t idx = (size_t)blockIdx.x * blockDim.x + threadIdx.x;
    size_t total = (size_t)M_ * QKV_N / 4;
    if (idx >= total) return;
    int bt = (int)(idx / (QKV_N / 4));
    int c4 = (int)(idx % (QKV_N / 4)) * 4;
    int comp = c4 >> 10;
    int rem  = c4 & 1023;
    int h = rem >> 6;
    int d = rem & 63;
    int b = bt >> 12;
    int t = bt & 4095;
    int bh = b * H_ + h;
    float4 v = *(const float4*)(g_qkv + (size_t)bt * QKV_N + c4);
    __nv_bfloat16 h0 = __float2bfloat16_rn(v.x);
    __nv_bfloat16 h1 = __float2bfloat16_rn(v.y);
    __nv_bfloat16 h2 = __float2bfloat16_rn(v.z);
    __nv_bfloat16 h3 = __float2bfloat16_rn(v.w);
    __nv_bfloat16 l0 = __float2bfloat16_rn(v.x - __bfloat162float(h0));
    __nv_bfloat16 l1 = __float2bfloat16_rn(v.y - __bfloat162float(h1));
    __nv_bfloat16 l2 = __float2bfloat16_rn(v.z - __bfloat162float(h2));
    __nv_bfloat16 l3 = __float2bfloat16_rn(v.w - __bfloat162float(h3));
    __nv_bfloat16* hid = g_s16 + S16_OFF(comp, 0, bh, t) + d;
    __nv_bfloat16* lod = g_s16 + S16_OFF(comp, 1, bh, t) + d;
    *(__nv_bfloat162*)(hid)     = __halves2bfloat162(h0, h1);
    *(__nv_bfloat162*)(hid + 2) = __halves2bfloat162(h2, h3);
    *(__nv_bfloat162*)(lod)     = __halves2bfloat162(l0, l1);
    *(__nv_bfloat162*)(lod + 2) = __halves2bfloat162(l2, l3);
}

// ---------------------------------------------------------------------------
// PTX helpers
// ---------------------------------------------------------------------------
__device__ __forceinline__ unsigned smem_u32(const void* p) {
    return (unsigned)__cvta_generic_to_shared(p);
}
__device__ __forceinline__ void cp16(void* smem_dst, const void* gmem_src) {
    asm volatile("cp.async.cg.shared.global [%0], [%1], 16;\n"
                 :: "r"(smem_u32(smem_dst)), "l"(gmem_src));
}
__device__ __forceinline__ void ldm_x4(unsigned& r0, unsigned& r1,
                                       unsigned& r2, unsigned& r3,
                                       const void* p) {
    asm volatile("ldmatrix.sync.aligned.m8n8.x4.shared.b16 {%0,%1,%2,%3}, [%4];\n"
                 : "=r"(r0), "=r"(r1), "=r"(r2), "=r"(r3) : "r"(smem_u32(p)));
}
__device__ __forceinline__ void ldm_x4t(unsigned& r0, unsigned& r1,
                                        unsigned& r2, unsigned& r3,
                                        const void* p) {
    asm volatile("ldmatrix.sync.aligned.m8n8.x4.trans.shared.b16 {%0,%1,%2,%3}, [%4];\n"
                 : "=r"(r0), "=r"(r1), "=r"(r2), "=r"(r3) : "r"(smem_u32(p)));
}
__device__ __forceinline__ void mma16816(float* c, const unsigned* a, const unsigned* b) {
    asm volatile("mma.sync.aligned.m16n8k16.row.col.f32.bf16.bf16.f32 "
                 "{%0,%1,%2,%3}, {%4,%5,%6,%7}, {%8,%9}, {%0,%1,%2,%3};\n"
                 : "+f"(c[0]), "+f"(c[1]), "+f"(c[2]), "+f"(c[3])
                 : "r"(a[0]), "r"(a[1]), "r"(a[2]), "r"(a[3]),
                   "r"(b[0]), "r"(b[1]));
}
__device__ __forceinline__ unsigned pack_bf16(float a, float b) {
    unsigned ha = (unsigned)__bfloat16_as_ushort(__float2bfloat16_rn(a));
    unsigned hb = (unsigned)__bfloat16_as_ushort(__float2bfloat16_rn(b));
    return ha | (hb << 16);
}

// ---------------------------------------------------------------------------
// Fragment-split HMMA GEMM:
//   C[M,N] = A(hi+lo)[M,2K] @ B(hi+lo)[N,2K]^T (+bias), 3-term split:
//   acc += ah*bh + ah*bl + al*bh   (lo*lo dropped, ~2^-16)
// Block tile 128x128, K-step 32, 8 warps (2x4), warp tile 64x32.
// Tiles: Ah|Al|Bh|Bl each [128][40], double-buffered (80 KB dynamic smem).
// ---------------------------------------------------------------------------
#define GP 40
#define TILE_ELE (128 * GP)
#define STAGE_ELE (4 * TILE_ELE)
#define GEMM2_SMEM (2 * STAGE_ELE * 2)    // bytes

__global__ __launch_bounds__(256)
void hgemm2_kernel(const __nv_bfloat16* __restrict__ A,
                   const __nv_bfloat16* __restrict__ B,
                   const float* __restrict__ bias,
                   float* __restrict__ C,
                   int M, int N, int Kreal) {
    extern __shared__ __nv_bfloat16 S[];   // [2][4][128][GP]

    const int tid  = threadIdx.x;
    const int lane = tid & 31;
    const int wid  = tid >> 5;
    const int wm   = wid >> 2;
    const int wn   = wid & 3;
    const int m0   = blockIdx.y * 128;
    const int n0   = blockIdx.x * 128;
    const int K2   = 2 * Kreal;
    const int KT   = Kreal / 32;

    float acc[4][4][4];
#pragma unroll
    for (int i = 0; i < 4; i++)
#pragma unroll
        for (int j = 0; j < 4; j++)
#pragma unroll
            for (int r = 0; r < 4; r++) acc[i][j][r] = 0.0f;

    // fill: 2048 16B chunks (4 tiles x 128 rows x 4)
    auto fill = [&](int buf, int kt) {
        int k0 = kt * 32;
        __nv_bfloat16* stage = S + buf * STAGE_ELE;
#pragma unroll
        for (int q = tid; q < 2048; q += 256) {
            int tile = q >> 9;             // 0=Ah 1=Al 2=Bh 3=Bl
            int c    = q & 511;
            int row  = c >> 2;
            int kc   = (c & 3) * 8;
            const __nv_bfloat16* src = (tile < 2)
                ? A + (size_t)(m0 + row) * K2 + (tile & 1) * Kreal + k0 + kc
                : B + (size_t)(n0 + row) * K2 + (tile & 1) * Kreal + k0 + kc;
            cp16(stage + tile * TILE_ELE + row * GP + kc, src);
        }
        asm volatile("cp.async.commit_group;\n");
    };

    fill(0, 0);
    asm volatile("cp.async.wait_group 0;\n");
    __syncthreads();

    int buf = 0;
    for (int kt = 0; kt < KT; kt++) {
        if (kt + 1 < KT) fill(buf ^ 1, kt + 1);

        const __nv_bfloat16* Ah = S + buf * STAGE_ELE;
        const __nv_bfloat16* Al = Ah + TILE_ELE;
        const __nv_bfloat16* Bh = Al + TILE_ELE;
        const __nv_bfloat16* Bl = Bh + TILE_ELE;
#pragma unroll
        for (int ks = 0; ks < 2; ks++) {
            unsigned ah[4][4], al[4][4], bh[4][2], bl[4][2];
            const int ar = lane & 15;
            const int ak = ks * 16 + ((lane >> 4) << 3);
#pragma unroll
            for (int mi = 0; mi < 4; mi++) {
                int ro = (wm * 64 + mi * 16 + ar) * GP + ak;
                ldm_x4(ah[mi][0], ah[mi][1], ah[mi][2], ah[mi][3], Ah + ro);
                ldm_x4(al[mi][0], al[mi][1], al[mi][2], al[mi][3], Al + ro);
            }
            const int br = ((lane >> 4) << 3) + (lane & 7);
            const int bk = ks * 16 + (((lane >> 3) & 1) << 3);
#pragma unroll
            for (int njp = 0; njp < 2; njp++) {
                int ro = (wn * 32 + njp * 16 + br) * GP + bk;
                unsigned r0, r1, r2, r3;
                ldm_x4(r0, r1, r2, r3, Bh + ro);
                bh[njp * 2][0] = r0; bh[njp * 2][1] = r1;
                bh[njp * 2 + 1][0] = r2; bh[njp * 2 + 1][1] = r3;
                ldm_x4(r0, r1, r2, r3, Bl + ro);
                bl[njp * 2][0] = r0; bl[njp * 2][1] = r1;
                bl[njp * 2 + 1][0] = r2; bl[njp * 2 + 1][1] = r3;
            }
#pragma unroll
            for (int mi = 0; mi < 4; mi++)
#pragma unroll
                for (int nj = 0; nj < 4; nj++) {
                    mma16816(acc[mi][nj], ah[mi], bh[nj]);
                    mma16816(acc[mi][nj], ah[mi], bl[nj]);
                    mma16816(acc[mi][nj], al[mi], bh[nj]);
                }
        }
        if (kt + 1 < KT) asm volatile("cp.async.wait_group 0;\n");
        __syncthreads();
        buf ^= 1;
    }

    const int rbase = m0 + wm * 64 + (lane >> 2);
    const int cbase = n0 + wn * 32 + (lane & 3) * 2;
#pragma unroll
    for (int mi = 0; mi < 4; mi++) {
#pragma unroll
        for (int nj = 0; nj < 4; nj++) {
            int col = cbase + nj * 8;
            float b0 = bias ? bias[col] : 0.0f;
            float b1 = bias ? bias[col + 1] : 0.0f;
            int r0 = rbase + mi * 16;
            float2 v0 = make_float2(acc[mi][nj][0] + b0, acc[mi][nj][1] + b1);
            float2 v1 = make_float2(acc[mi][nj][2] + b0, acc[mi][nj][3] + b1);
            *(float2*)(C + (size_t)r0 * N + col)       = v0;
            *(float2*)(C + (size_t)(r0 + 8) * N + col) = v1;
        }
    }
}

// ---------------------------------------------------------------------------
// Flash-style HMMA attention (validated R9; epilogue now writes [hi|lo])
// ---------------------------------------------------------------------------
#define QP 72
#define MAT_E (64 * QP)
#define STAGE_E (4 * MAT_E)
#define ATT3_SMEM (2 * STAGE_E * 2 + 512 * 4)

__global__ __launch_bounds__(256)
void attn3_kernel() {
    extern __shared__ char sm3[];
    __nv_bfloat16* KV = (__nv_bfloat16*)sm3;
    float* gs = (float*)(KV + 2 * STAGE_E);

    const int tid  = threadIdx.x;
    const int lane = tid & 31;
    const int wid  = tid >> 5;

    const int cid = blockIdx.x;
    const int qt  = cid & 3;
    const int n   = (cid >> 2) & 7;
    const int h   = (cid >> 5) & 15;
    const int b   = cid >> 9;
    const int bh  = b * H_ + h;
    const int t0  = n * CS_ + qt * 128;
    const int tk0 = n * CS_;

    for (int q = tid; q < 2048; q += 256) {
        int part = q >> 10;
        int r = (q >> 3) & 127;
        int c8 = (q & 7) * 8;
        cp16(KV + part * (2 * MAT_E) + r * QP + c8,
             g_s16 + S16_OFF(0, part, bh, t0 + r) + c8);
    }
    asm volatile("cp.async.commit_group;\n");
    for (int i = tid; i < 512; i += 256)
        gs[i] = 0.125f * g_lam[h * T_ + tk0 + i];
    asm volatile("cp.async.wait_group 0;\n");
    __syncthreads();

    unsigned qh[4][4], ql[4][4];
    {
        const int ar = 16 * wid + (lane & 15);
        const int ao = (lane >> 4) << 3;
#pragma unroll
        for (int ks = 0; ks < 4; ks++) {
            ldm_x4(qh[ks][0], qh[ks][1], qh[ks][2], qh[ks][3],
                   KV + ar * QP + ks * 16 + ao);
            ldm_x4(ql[ks][0], ql[ks][1], ql[ks][2], ql[ks][3],
                   KV + 2 * MAT_E + ar * QP + ks * 16 + ao);
        }
    }
    __syncthreads();

    auto fillKV = [&](int st, int kt) {
        __nv_bfloat16* stage = KV + st * STAGE_E;
        int tb = tk0 + kt * 64;
        for (int q = tid; q < 2048; q += 256) {
            int part = q >> 9;
            int r = (q >> 3) & 63;
            int c8 = (q & 7) * 8;
            int comp = 1 + (part >> 1);
            int lo = part & 1;
            cp16(stage + part * MAT_E + r * QP + c8,
                 g_s16 + S16_OFF(comp, lo, bh, tb + r) + c8);
        }
        asm volatile("cp.async.commit_group;\n");
    };
    fillKV(0, 0);
    fillKV(1, 1);

    float m0 = -1e30f, m1 = -1e30f;
    float l0 = 0.0f, l1 = 0.0f;
    float facc[8][4];
#pragma unroll
    for (int i = 0; i < 8; i++)
#pragma unroll
        for (int j = 0; j < 4; j++) facc[i][j] = 0.0f;

    for (int kt = 0; kt < 8; kt++) {
        if (kt == 7) { asm volatile("cp.async.wait_group 0;\n" ::: "memory"); }
        else        { asm volatile("cp.async.wait_group 1;\n" ::: "memory"); }
        __syncthreads();
        __nv_bfloat16* Kh = KV + (kt & 1) * STAGE_E;
        __nv_bfloat16* Kl = Kh + MAT_E;
        __nv_bfloat16* Vh = Kl + MAT_E;
        __nv_bfloat16* Vl = Vh + MAT_E;

        float s[8][4];
#pragma unroll
        for (int i = 0; i < 8; i++)
#pragma unroll
            for (int j = 0; j < 4; j++) s[i][j] = 0.0f;

        {
            const int br = ((lane >> 4) << 3) + (lane & 7);
            const int bo = ((lane >> 3) & 1) << 3;
#pragma unroll
            for (int np = 0; np < 4; np++) {
                int rowb = np * 16 + br;
#pragma unroll
                for (int ks = 0; ks < 4; ks++) {
                    unsigned kh4[4], kl4[4];
                    int bk = ks * 16 + bo;
                    ldm_x4(kh4[0], kh4[1], kh4[2], kh4[3], Kh + rowb * QP + bk);
                    ldm_x4(kl4[0], kl4[1], kl4[2], kl4[3], Kl + rowb * QP + bk);
                    mma16816(s[2 * np],     qh[ks], &kh4[0]);
                    mma16816(s[2 * np + 1], qh[ks], &kh4[2]);
                    mma16816(s[2 * np],     qh[ks], &kl4[0]);
                    mma16816(s[2 * np + 1], qh[ks], &kl4[2]);
                    mma16816(s[2 * np],     ql[ks], &kh4[0]);
                    mma16816(s[2 * np + 1], ql[ks], &kh4[2]);
                }
            }
        }

        float tm0 = -1e30f, tm1 = -1e30f;
#pragma unroll
        for (int nt = 0; nt < 8; nt++) {
            int c = nt * 8 + (lane & 3) * 2;
            float g0 = gs[kt * 64 + c];
            float g1 = gs[kt * 64 + c + 1];
            s[nt][0] *= g0; s[nt][1] *= g1;
            s[nt][2] *= g0; s[nt][3] *= g1;
            tm0 = fmaxf(tm0, fmaxf(s[nt][0], s[nt][1]));
            tm1 = fmaxf(tm1, fmaxf(s[nt][2], s[nt][3]));
        }
        tm0 = fmaxf(tm0, __shfl_xor_sync(0xffffffffu, tm0, 1));
        tm0 = fmaxf(tm0, __shfl_xor_sync(0xffffffffu, tm0, 2));
        tm1 = fmaxf(tm1, __shfl_xor_sync(0xffffffffu, tm1, 1));
        tm1 = fmaxf(tm1, __shfl_xor_sync(0xffffffffu, tm1, 2));

        float mn0 = fmaxf(m0, tm0), mn1 = fmaxf(m1, tm1);
        float a0 = __expf(m0 - mn0), a1 = __expf(m1 - mn1);
        m0 = mn0; m1 = mn1;

        unsigned ph[4][4], pl[4][4];
        float ts0 = 0.0f, ts1 = 0.0f;
#pragma unroll
        for (int j = 0; j < 4; j++) {
#pragma unroll
            for (int half = 0; half < 2; half++) {
                int nt = 2 * j + half;
                float p00 = __expf(s[nt][0] - m0);
                float p01 = __expf(s[nt][1] - m0);
                float p10 = __expf(s[nt][2] - m1);
                float p11 = __expf(s[nt][3] - m1);
                ts0 += p00 + p01;
                ts1 += p10 + p11;
                unsigned hp0 = pack_bf16(p00, p01);
                unsigned hp1 = pack_bf16(p10, p11);
                ph[j][half * 2]     = hp0;
                ph[j][half * 2 + 1] = hp1;
                float r00 = p00 - __bfloat162float(__ushort_as_bfloat16((unsigned short)(hp0 & 0xffff)));
                float r01 = p01 - __bfloat162float(__ushort_as_bfloat16((unsigned short)(hp0 >> 16)));
                float r10 = p10 - __bfloat162float(__ushort_as_bfloat16((unsigned short)(hp1 & 0xffff)));
                float r11 = p11 - __bfloat162float(__ushort_as_bfloat16((unsigned short)(hp1 >> 16)));
                pl[j][half * 2]     = pack_bf16(r00, r01);
                pl[j][half * 2 + 1] = pack_bf16(r10, r11);
            }
        }
        l0 = l0 * a0 + ts0;
        l1 = l1 * a1 + ts1;
#pragma unroll
        for (int nt = 0; nt < 8; nt++) {
            facc[nt][0] *= a0; facc[nt][1] *= a0;
            facc[nt][2] *= a1; facc[nt][3] *= a1;
        }

        {
            const int vm = lane >> 3;
            const int vr = lane & 7;
#pragma unroll
            for (int dt = 0; dt < 4; dt++) {
#pragma unroll
                for (int ks = 0; ks < 4; ks++) {
                    unsigned vh4[4], vl4[4];
                    int row = ks * 16 + ((vm & 1) << 3) + vr;
                    int col = dt * 16 + ((vm >> 1) << 3);
                    ldm_x4t(vh4[0], vh4[1], vh4[2], vh4[3], Vh + row * QP + col);
                    ldm_x4t(vl4[0], vl4[1], vl4[2], vl4[3], Vl + row * QP + col);
                    mma16816(facc[2 * dt],     ph[ks], &vh4[0]);
                    mma16816(facc[2 * dt + 1], ph[ks], &vh4[2]);
                    mma16816(facc[2 * dt],     ph[ks], &vl4[0]);
                    mma16816(facc[2 * dt + 1], ph[ks], &vl4[2]);
                    mma16816(facc[2 * dt],     pl[ks], &vh4[0]);
                    mma16816(facc[2 * dt + 1], pl[ks], &vh4[2]);
                }
            }
        }

        __syncthreads();
        if (kt + 2 < 8) fillKV(kt & 1, kt + 2);
    }

    l0 += __shfl_xor_sync(0xffffffffu, l0, 1);
    l0 += __shfl_xor_sync(0xffffffffu, l0, 2);
    l1 += __shfl_xor_sync(0xffffffffu, l1, 1);
    l1 += __shfl_xor_sync(0xffffffffu, l1, 2);
    float inv0 = 1.0f / l0, inv1 = 1.0f / l1;

    int qrow0 = t0 + 16 * wid + (lane >> 2);
#pragma unroll
    for (int nt = 0; nt < 8; nt++) {
        int colC = h * 64 + nt * 8 + (lane & 3) * 2;
#pragma unroll
        for (int half = 0; half < 2; half++) {
            int rr = qrow0 + half * 8;
            float inv = half ? inv1 : inv0;
            float o0 = facc[nt][half * 2 + 0] * inv;
            float o1 = facc[nt][half * 2 + 1] * inv;
            __nv_bfloat16 h0 = __float2bfloat16_rn(o0);
            __nv_bfloat16 h1 = __float2bfloat16_rn(o1);
            __nv_bfloat16 L0 = __float2bfloat16_rn(o0 - __bfloat162float(h0));
            __nv_bfloat16 L1 = __float2bfloat16_rn(o1 - __bfloat162float(h1));
            __nv_bfloat16* base = g_atts + (size_t)(b * T_ + rr) * K2_;
            *(__nv_bfloat162*)(base + colC)      = __halves2bfloat162(h0, h1);
            *(__nv_bfloat162*)(base + C_ + colC) = __halves2bfloat162(L0, L1);
        }
    }
}

// ---------------------------------------------------------------------------
// Launch
// ---------------------------------------------------------------------------
extern "C" void kernel_launch(void* const* d_in, const int* in_sizes, int n_in,
                              void* d_out, int out_size) {
    const float* x    = (const float*)d_in[0];
    const float* Wqkv = (const float*)d_in[1];
    const float* Wout = (const float*)d_in[2];
    const float* bout = (const float*)d_in[3];
    const float* Wl1  = (const float*)d_in[4];
    const float* bl1  = (const float*)d_in[5];
    const float* Wl2  = (const float*)d_in[6];
    const float* bl2  = (const float*)d_in[7];
    float* out = (float*)d_out;

    float* qkv_ptr = nullptr;
    __nv_bfloat16 *xs = nullptr, *atts = nullptr, *wqkvs = nullptr, *wouts = nullptr;
    cudaGetSymbolAddress((void**)&qkv_ptr, g_qkv);
    cudaGetSymbolAddress((void**)&xs, g_xs);
    cudaGetSymbolAddress((void**)&atts, g_atts);
    cudaGetSymbolAddress((void**)&wqkvs, g_wqkvs);
    cudaGetSymbolAddress((void**)&wouts, g_wouts);

    cudaFuncSetAttribute(attn3_kernel,
                         cudaFuncAttributeMaxDynamicSharedMemorySize, ATT3_SMEM);
    cudaFuncSetAttribute(hgemm2_kernel,
                         cudaFuncAttributeMaxDynamicSharedMemorySize, GEMM2_SMEM);

    // 1) lambda gates
    lambda_kernel<<<(T_ + 127) / 128, 128>>>(Wl1, bl1, Wl2, bl2);

    // 2) [hi|lo] splits for QKV GEMM
    {
        int threads = 256;
        size_t tx4 = (size_t)M_ * C_ / 4;
        split2_kernel<<<(unsigned)((tx4 + threads - 1) / threads), threads>>>(x, xs, M_, C_);
        size_t tw4 = (size_t)QKV_N * C_ / 4;
        split2_kernel<<<(unsigned)((tw4 + threads - 1) / threads), threads>>>(Wqkv, wqkvs, QKV_N, C_);
    }

    // 3) QKV projection (fragment-split HMMA)
    {
        dim3 grid(QKV_N / 128, M_ / 128);
        hgemm2_kernel<<<grid, 256, GEMM2_SMEM>>>(xs, wqkvs, nullptr, qkv_ptr,
                                                 M_, QKV_N, C_);
    }

    // 4) q/k/v -> bf16 hi/lo per-(b,h)
    {
        size_t total = (size_t)M_ * QKV_N / 4;
        qkvsplit_kernel<<<(unsigned)((total + 255) / 256), 256>>>();
    }

    // 5) flash attention -> g_atts ([hi|lo])
    attn3_kernel<<<B_ * H_ * NC_ * (CS_ / 128), 256, ATT3_SMEM>>>();

    // 6) split Wout, output projection (fragment-split HMMA)
    {
        int threads = 256;
        size_t tw4 = (size_t)C_ * C_ / 4;
        split2_kernel<<<(unsigned)((tw4 + threads - 1) / threads), threads>>>(Wout, wouts, C_, C_);
    }
    {
        dim3 grid(C_ / 128, M_ / 128);
        hgemm2_kernel<<<grid, 256, GEMM2_SMEM>>>(atts, wouts, bout, out,
                                                 M_, C_, C_);
    }
}

// round 13
// speedup vs baseline: 4.4632x; 1.5146x over previous
#include <cuda_runtime.h>
#include <cuda_bf16.h>
#include <cuda_fp16.h>
#include <math.h>
#include <stdint.h>

// ---------------------------------------------------------------------------
// LogLinearAttention — R13 (third submit of the fp16-projection kernel;
// R11/R12 hit broker-burst failures, same signature as R0/R1 which resolved
// on resubmit). Projections = single-pass fp16 HMMA; QKV epilogue fuses the
// bf16 hi/lo split into g_s16. Attention = validated flash kernel (split-3
// bf16 internally), epilogue writes fp16 O.
//   B=4, T=4096, C=1024, H=16, dh=64, nc=8, cs=512
// ---------------------------------------------------------------------------

#define B_  4
#define T_  4096
#define C_  1024
#define H_  16
#define DH_ 64
#define NC_ 8
#define CS_ 512
#define QKV_N (3 * C_)
#define M_  (B_ * T_)

__device__ float g_lam[H_ * T_];
__device__ __half g_xh[(size_t)M_ * C_];          // x fp16
__device__ __half g_wqkvh[(size_t)QKV_N * C_];    // Wqkv fp16
__device__ __half g_wouth[(size_t)C_ * C_];       // Wout fp16
__device__ __half g_atth[(size_t)M_ * C_];        // O fp16 (attn output)
// q/k/v hi/lo bf16 per-(b,h): [comp3][part2][bh64][t4096][d64]
__device__ __nv_bfloat16 g_s16[(size_t)3 * 2 * 64 * T_ * DH_];

#define S16_OFF(comp, part, bh, t) \
    (((((size_t)((comp) * 2 + (part)) * 64 + (bh)) * T_) + (t)) * DH_)

// ---------------------------------------------------------------------------
__global__ void lambda_kernel(const float* __restrict__ Wl1,
                              const float* __restrict__ bl1,
                              const float* __restrict__ Wl2,
                              const float* __restrict__ bl2) {
    int t = blockIdx.x * blockDim.x + threadIdx.x;
    if (t >= T_) return;
    float lp = logf((float)t + 1.0f);
    float h1[64];
#pragma unroll
    for (int j = 0; j < 64; j++)
        h1[j] = fmaxf(lp * Wl1[j] + bl1[j], 0.0f);
#pragma unroll
    for (int h = 0; h < H_; h++) {
        float s = bl2[h];
        const float* w = Wl2 + h * 64;
#pragma unroll
        for (int j = 0; j < 64; j++) s += w[j] * h1[j];
        g_lam[h * T_ + t] = 1.0f / (1.0f + __expf(-s));
    }
}

// ---------------------------------------------------------------------------
// fp32 -> fp16 convert
// ---------------------------------------------------------------------------
__global__ void tohalf_kernel(const float* __restrict__ A,
                              __half* __restrict__ out, size_t n4) {
    size_t i = (size_t)blockIdx.x * blockDim.x + threadIdx.x;
    if (i >= n4) return;
    float4 v = *(const float4*)(A + i * 4);
    __half2 a = __floats2half2_rn(v.x, v.y);
    __half2 b = __floats2half2_rn(v.z, v.w);
    *(__half2*)(out + i * 4)     = a;
    *(__half2*)(out + i * 4 + 2) = b;
}

// ---------------------------------------------------------------------------
// PTX helpers
// ---------------------------------------------------------------------------
__device__ __forceinline__ unsigned smem_u32(const void* p) {
    return (unsigned)__cvta_generic_to_shared(p);
}
__device__ __forceinline__ void cp16(void* smem_dst, const void* gmem_src) {
    asm volatile("cp.async.cg.shared.global [%0], [%1], 16;\n"
                 :: "r"(smem_u32(smem_dst)), "l"(gmem_src));
}
__device__ __forceinline__ void ldm_x4(unsigned& r0, unsigned& r1,
                                       unsigned& r2, unsigned& r3,
                                       const void* p) {
    asm volatile("ldmatrix.sync.aligned.m8n8.x4.shared.b16 {%0,%1,%2,%3}, [%4];\n"
                 : "=r"(r0), "=r"(r1), "=r"(r2), "=r"(r3) : "r"(smem_u32(p)));
}
__device__ __forceinline__ void ldm_x4t(unsigned& r0, unsigned& r1,
                                        unsigned& r2, unsigned& r3,
                                        const void* p) {
    asm volatile("ldmatrix.sync.aligned.m8n8.x4.trans.shared.b16 {%0,%1,%2,%3}, [%4];\n"
                 : "=r"(r0), "=r"(r1), "=r"(r2), "=r"(r3) : "r"(smem_u32(p)));
}
__device__ __forceinline__ void mma16816(float* c, const unsigned* a, const unsigned* b) {
    asm volatile("mma.sync.aligned.m16n8k16.row.col.f32.bf16.bf16.f32 "
                 "{%0,%1,%2,%3}, {%4,%5,%6,%7}, {%8,%9}, {%0,%1,%2,%3};\n"
                 : "+f"(c[0]), "+f"(c[1]), "+f"(c[2]), "+f"(c[3])
                 : "r"(a[0]), "r"(a[1]), "r"(a[2]), "r"(a[3]),
                   "r"(b[0]), "r"(b[1]));
}
__device__ __forceinline__ void mma16816h(float* c, const unsigned* a, const unsigned* b) {
    asm volatile("mma.sync.aligned.m16n8k16.row.col.f32.f16.f16.f32 "
                 "{%0,%1,%2,%3}, {%4,%5,%6,%7}, {%8,%9}, {%0,%1,%2,%3};\n"
                 : "+f"(c[0]), "+f"(c[1]), "+f"(c[2]), "+f"(c[3])
                 : "r"(a[0]), "r"(a[1]), "r"(a[2]), "r"(a[3]),
                   "r"(b[0]), "r"(b[1]));
}
__device__ __forceinline__ unsigned pack_bf16(float a, float b) {
    unsigned ha = (unsigned)__bfloat16_as_ushort(__float2bfloat16_rn(a));
    unsigned hb = (unsigned)__bfloat16_as_ushort(__float2bfloat16_rn(b));
    return ha | (hb << 16);
}

// ---------------------------------------------------------------------------
// fp16 HMMA GEMM (validated skeleton): C[M,N] = A[M,Kp] @ B[N,Kp]^T
// mode 0: fp32 C + bias.  mode 1: write bf16 hi/lo into g_s16 (QKV path).
// Block 128x128, BK=32, 8 warps (2x4), warp tile 64x32, double-buffered.
// ---------------------------------------------------------------------------
#define GP 40

__global__ __launch_bounds__(256)
void hgemm_fp16_kernel(const __half* __restrict__ A,
                       const __half* __restrict__ B,
                       const float* __restrict__ bias,
                       float* __restrict__ C,
                       int M, int N, int Kp, int mode) {
    __shared__ __half As[2][128 * GP];
    __shared__ __half Bs[2][128 * GP];

    const int tid  = threadIdx.x;
    const int lane = tid & 31;
    const int wid  = tid >> 5;
    const int wm   = wid >> 2;
    const int wn   = wid & 3;
    const int m0   = blockIdx.y * 128;
    const int n0   = blockIdx.x * 128;

    float acc[4][4][4];
#pragma unroll
    for (int i = 0; i < 4; i++)
#pragma unroll
        for (int j = 0; j < 4; j++)
#pragma unroll
            for (int r = 0; r < 4; r++) acc[i][j][r] = 0.0f;

    const int KT = Kp / 32;
    {
        int c1 = tid, c2 = tid + 256;
        int r1 = c1 >> 2, kc1 = c1 & 3;
        int r2 = c2 >> 2, kc2 = c2 & 3;
        cp16(&As[0][r1 * GP + kc1 * 8], A + (size_t)(m0 + r1) * Kp + kc1 * 8);
        cp16(&As[0][r2 * GP + kc2 * 8], A + (size_t)(m0 + r2) * Kp + kc2 * 8);
        cp16(&Bs[0][r1 * GP + kc1 * 8], B + (size_t)(n0 + r1) * Kp + kc1 * 8);
        cp16(&Bs[0][r2 * GP + kc2 * 8], B + (size_t)(n0 + r2) * Kp + kc2 * 8);
        asm volatile("cp.async.commit_group;\n");
        asm volatile("cp.async.wait_group 0;\n");
    }
    __syncthreads();

    int buf = 0;
    for (int kt = 0; kt < KT; kt++) {
        if (kt + 1 < KT) {
            int k0 = (kt + 1) * 32;
            int c1 = tid, c2 = tid + 256;
            int r1 = c1 >> 2, kc1 = c1 & 3;
            int r2 = c2 >> 2, kc2 = c2 & 3;
            cp16(&As[buf ^ 1][r1 * GP + kc1 * 8], A + (size_t)(m0 + r1) * Kp + k0 + kc1 * 8);
            cp16(&As[buf ^ 1][r2 * GP + kc2 * 8], A + (size_t)(m0 + r2) * Kp + k0 + kc2 * 8);
            cp16(&Bs[buf ^ 1][r1 * GP + kc1 * 8], B + (size_t)(n0 + r1) * Kp + k0 + kc1 * 8);
            cp16(&Bs[buf ^ 1][r2 * GP + kc2 * 8], B + (size_t)(n0 + r2) * Kp + k0 + kc2 * 8);
            asm volatile("cp.async.commit_group;\n");
        }
        const __half* Ab = As[buf];
        const __half* Bb = Bs[buf];
#pragma unroll
        for (int ks = 0; ks < 2; ks++) {
            unsigned a[4][4], b[4][2];
            const int ar = lane & 15;
            const int ak = ks * 16 + ((lane >> 4) << 3);
#pragma unroll
            for (int mi = 0; mi < 4; mi++)
                ldm_x4(a[mi][0], a[mi][1], a[mi][2], a[mi][3],
                       Ab + (wm * 64 + mi * 16 + ar) * GP + ak);
            const int br = ((lane >> 4) << 3) + (lane & 7);
            const int bk = ks * 16 + (((lane >> 3) & 1) << 3);
#pragma unroll
            for (int njp = 0; njp < 2; njp++) {
                unsigned r0, r1, r2, r3;
                ldm_x4(r0, r1, r2, r3, Bb + (wn * 32 + njp * 16 + br) * GP + bk);
                b[njp * 2][0] = r0; b[njp * 2][1] = r1;
                b[njp * 2 + 1][0] = r2; b[njp * 2 + 1][1] = r3;
            }
#pragma unroll
            for (int mi = 0; mi < 4; mi++)
#pragma unroll
                for (int nj = 0; nj < 4; nj++)
                    mma16816h(acc[mi][nj], a[mi], b[nj]);
        }
        if (kt + 1 < KT) asm volatile("cp.async.wait_group 0;\n");
        __syncthreads();
        buf ^= 1;
    }

    const int rbase = m0 + wm * 64 + (lane >> 2);
    const int cbase = n0 + wn * 32 + (lane & 3) * 2;
    if (mode == 0) {
#pragma unroll
        for (int mi = 0; mi < 4; mi++) {
#pragma unroll
            for (int nj = 0; nj < 4; nj++) {
                int col = cbase + nj * 8;
                float b0 = bias ? bias[col] : 0.0f;
                float b1 = bias ? bias[col + 1] : 0.0f;
                int r0 = rbase + mi * 16;
                float2 v0 = make_float2(acc[mi][nj][0] + b0, acc[mi][nj][1] + b1);
                float2 v1 = make_float2(acc[mi][nj][2] + b0, acc[mi][nj][3] + b1);
                *(float2*)(C + (size_t)r0 * N + col)       = v0;
                *(float2*)(C + (size_t)(r0 + 8) * N + col) = v1;
            }
        }
    } else {
        // QKV: write bf16 hi/lo directly into g_s16 per-(b,h) layout
#pragma unroll
        for (int mi = 0; mi < 4; mi++) {
#pragma unroll
            for (int nj = 0; nj < 4; nj++) {
                int col = cbase + nj * 8;
                int comp = col >> 10;
                int hh   = (col >> 6) & 15;
                int d    = col & 63;
#pragma unroll
                for (int half_ = 0; half_ < 2; half_++) {
                    int rM = rbase + mi * 16 + half_ * 8;
                    int bb = rM >> 12;
                    int t  = rM & 4095;
                    int bh = bb * H_ + hh;
                    float v0 = acc[mi][nj][half_ * 2];
                    float v1 = acc[mi][nj][half_ * 2 + 1];
                    __nv_bfloat16 h0 = __float2bfloat16_rn(v0);
                    __nv_bfloat16 h1 = __float2bfloat16_rn(v1);
                    __nv_bfloat16 l0 = __float2bfloat16_rn(v0 - __bfloat162float(h0));
                    __nv_bfloat16 l1 = __float2bfloat16_rn(v1 - __bfloat162float(h1));
                    *(__nv_bfloat162*)(g_s16 + S16_OFF(comp, 0, bh, t) + d) =
                        __halves2bfloat162(h0, h1);
                    *(__nv_bfloat162*)(g_s16 + S16_OFF(comp, 1, bh, t) + d) =
                        __halves2bfloat162(l0, l1);
                }
            }
        }
    }
}

// ---------------------------------------------------------------------------
// Flash-style HMMA attention (validated R9/R10); epilogue writes fp16 O.
// ---------------------------------------------------------------------------
#define QP 72
#define MAT_E (64 * QP)
#define STAGE_E (4 * MAT_E)
#define ATT3_SMEM (2 * STAGE_E * 2 + 512 * 4)

__global__ __launch_bounds__(256)
void attn3_kernel() {
    extern __shared__ char sm3[];
    __nv_bfloat16* KV = (__nv_bfloat16*)sm3;
    float* gs = (float*)(KV + 2 * STAGE_E);

    const int tid  = threadIdx.x;
    const int lane = tid & 31;
    const int wid  = tid >> 5;

    const int cid = blockIdx.x;
    const int qt  = cid & 3;
    const int n   = (cid >> 2) & 7;
    const int h   = (cid >> 5) & 15;
    const int b   = cid >> 9;
    const int bh  = b * H_ + h;
    const int t0  = n * CS_ + qt * 128;
    const int tk0 = n * CS_;

    for (int q = tid; q < 2048; q += 256) {
        int part = q >> 10;
        int r = (q >> 3) & 127;
        int c8 = (q & 7) * 8;
        cp16(KV + part * (2 * MAT_E) + r * QP + c8,
             g_s16 + S16_OFF(0, part, bh, t0 + r) + c8);
    }
    asm volatile("cp.async.commit_group;\n");
    for (int i = tid; i < 512; i += 256)
        gs[i] = 0.125f * g_lam[h * T_ + tk0 + i];
    asm volatile("cp.async.wait_group 0;\n");
    __syncthreads();

    unsigned qh[4][4], ql[4][4];
    {
        const int ar = 16 * wid + (lane & 15);
        const int ao = (lane >> 4) << 3;
#pragma unroll
        for (int ks = 0; ks < 4; ks++) {
            ldm_x4(qh[ks][0], qh[ks][1], qh[ks][2], qh[ks][3],
                   KV + ar * QP + ks * 16 + ao);
            ldm_x4(ql[ks][0], ql[ks][1], ql[ks][2], ql[ks][3],
                   KV + 2 * MAT_E + ar * QP + ks * 16 + ao);
        }
    }
    __syncthreads();

    auto fillKV = [&](int st, int kt) {
        __nv_bfloat16* stage = KV + st * STAGE_E;
        int tb = tk0 + kt * 64;
        for (int q = tid; q < 2048; q += 256) {
            int part = q >> 9;
            int r = (q >> 3) & 63;
            int c8 = (q & 7) * 8;
            int comp = 1 + (part >> 1);
            int lo = part & 1;
            cp16(stage + part * MAT_E + r * QP + c8,
                 g_s16 + S16_OFF(comp, lo, bh, tb + r) + c8);
        }
        asm volatile("cp.async.commit_group;\n");
    };
    fillKV(0, 0);
    fillKV(1, 1);

    float m0 = -1e30f, m1 = -1e30f;
    float l0 = 0.0f, l1 = 0.0f;
    float facc[8][4];
#pragma unroll
    for (int i = 0; i < 8; i++)
#pragma unroll
        for (int j = 0; j < 4; j++) facc[i][j] = 0.0f;

    for (int kt = 0; kt < 8; kt++) {
        if (kt == 7) { asm volatile("cp.async.wait_group 0;\n" ::: "memory"); }
        else        { asm volatile("cp.async.wait_group 1;\n" ::: "memory"); }
        __syncthreads();
        __nv_bfloat16* Kh = KV + (kt & 1) * STAGE_E;
        __nv_bfloat16* Kl = Kh + MAT_E;
        __nv_bfloat16* Vh = Kl + MAT_E;
        __nv_bfloat16* Vl = Vh + MAT_E;

        float s[8][4];
#pragma unroll
        for (int i = 0; i < 8; i++)
#pragma unroll
            for (int j = 0; j < 4; j++) s[i][j] = 0.0f;

        {
            const int br = ((lane >> 4) << 3) + (lane & 7);
            const int bo = ((lane >> 3) & 1) << 3;
#pragma unroll
            for (int np = 0; np < 4; np++) {
                int rowb = np * 16 + br;
#pragma unroll
                for (int ks = 0; ks < 4; ks++) {
                    unsigned kh4[4], kl4[4];
                    int bk = ks * 16 + bo;
                    ldm_x4(kh4[0], kh4[1], kh4[2], kh4[3], Kh + rowb * QP + bk);
                    ldm_x4(kl4[0], kl4[1], kl4[2], kl4[3], Kl + rowb * QP + bk);
                    mma16816(s[2 * np],     qh[ks], &kh4[0]);
                    mma16816(s[2 * np + 1], qh[ks], &kh4[2]);
                    mma16816(s[2 * np],     qh[ks], &kl4[0]);
                    mma16816(s[2 * np + 1], qh[ks], &kl4[2]);
                    mma16816(s[2 * np],     ql[ks], &kh4[0]);
                    mma16816(s[2 * np + 1], ql[ks], &kh4[2]);
                }
            }
        }

        float tm0 = -1e30f, tm1 = -1e30f;
#pragma unroll
        for (int nt = 0; nt < 8; nt++) {
            int c = nt * 8 + (lane & 3) * 2;
            float g0 = gs[kt * 64 + c];
            float g1 = gs[kt * 64 + c + 1];
            s[nt][0] *= g0; s[nt][1] *= g1;
            s[nt][2] *= g0; s[nt][3] *= g1;
            tm0 = fmaxf(tm0, fmaxf(s[nt][0], s[nt][1]));
            tm1 = fmaxf(tm1, fmaxf(s[nt][2], s[nt][3]));
        }
        tm0 = fmaxf(tm0, __shfl_xor_sync(0xffffffffu, tm0, 1));
        tm0 = fmaxf(tm0, __shfl_xor_sync(0xffffffffu, tm0, 2));
        tm1 = fmaxf(tm1, __shfl_xor_sync(0xffffffffu, tm1, 1));
        tm1 = fmaxf(tm1, __shfl_xor_sync(0xffffffffu, tm1, 2));

        float mn0 = fmaxf(m0, tm0), mn1 = fmaxf(m1, tm1);
        float a0 = __expf(m0 - mn0), a1 = __expf(m1 - mn1);
        m0 = mn0; m1 = mn1;

        unsigned ph[4][4], pl[4][4];
        float ts0 = 0.0f, ts1 = 0.0f;
#pragma unroll
        for (int j = 0; j < 4; j++) {
#pragma unroll
            for (int half = 0; half < 2; half++) {
                int nt = 2 * j + half;
                float p00 = __expf(s[nt][0] - m0);
                float p01 = __expf(s[nt][1] - m0);
                float p10 = __expf(s[nt][2] - m1);
                float p11 = __expf(s[nt][3] - m1);
                ts0 += p00 + p01;
                ts1 += p10 + p11;
                unsigned hp0 = pack_bf16(p00, p01);
                unsigned hp1 = pack_bf16(p10, p11);
                ph[j][half * 2]     = hp0;
                ph[j][half * 2 + 1] = hp1;
                float r00 = p00 - __bfloat162float(__ushort_as_bfloat16((unsigned short)(hp0 & 0xffff)));
                float r01 = p01 - __bfloat162float(__ushort_as_bfloat16((unsigned short)(hp0 >> 16)));
                float r10 = p10 - __bfloat162float(__ushort_as_bfloat16((unsigned short)(hp1 & 0xffff)));
                float r11 = p11 - __bfloat162float(__ushort_as_bfloat16((unsigned short)(hp1 >> 16)));
                pl[j][half * 2]     = pack_bf16(r00, r01);
                pl[j][half * 2 + 1] = pack_bf16(r10, r11);
            }
        }
        l0 = l0 * a0 + ts0;
        l1 = l1 * a1 + ts1;
#pragma unroll
        for (int nt = 0; nt < 8; nt++) {
            facc[nt][0] *= a0; facc[nt][1] *= a0;
            facc[nt][2] *= a1; facc[nt][3] *= a1;
        }

        {
            const int vm = lane >> 3;
            const int vr = lane & 7;
#pragma unroll
            for (int dt = 0; dt < 4; dt++) {
#pragma unroll
                for (int ks = 0; ks < 4; ks++) {
                    unsigned vh4[4], vl4[4];
                    int row = ks * 16 + ((vm & 1) << 3) + vr;
                    int col = dt * 16 + ((vm >> 1) << 3);
                    ldm_x4t(vh4[0], vh4[1], vh4[2], vh4[3], Vh + row * QP + col);
                    ldm_x4t(vl4[0], vl4[1], vl4[2], vl4[3], Vl + row * QP + col);
                    mma16816(facc[2 * dt],     ph[ks], &vh4[0]);
                    mma16816(facc[2 * dt + 1], ph[ks], &vh4[2]);
                    mma16816(facc[2 * dt],     ph[ks], &vl4[0]);
                    mma16816(facc[2 * dt + 1], ph[ks], &vl4[2]);
                    mma16816(facc[2 * dt],     pl[ks], &vh4[0]);
                    mma16816(facc[2 * dt + 1], pl[ks], &vh4[2]);
                }
            }
        }

        __syncthreads();
        if (kt + 2 < 8) fillKV(kt & 1, kt + 2);
    }

    l0 += __shfl_xor_sync(0xffffffffu, l0, 1);
    l0 += __shfl_xor_sync(0xffffffffu, l0, 2);
    l1 += __shfl_xor_sync(0xffffffffu, l1, 1);
    l1 += __shfl_xor_sync(0xffffffffu, l1, 2);
    float inv0 = 1.0f / l0, inv1 = 1.0f / l1;

    int qrow0 = t0 + 16 * wid + (lane >> 2);
#pragma unroll
    for (int nt = 0; nt < 8; nt++) {
        int colC = h * 64 + nt * 8 + (lane & 3) * 2;
#pragma unroll
        for (int half = 0; half < 2; half++) {
            int rr = qrow0 + half * 8;
            float inv = half ? inv1 : inv0;
            float o0 = facc[nt][half * 2 + 0] * inv;
            float o1 = facc[nt][half * 2 + 1] * inv;
            *(__half2*)(g_atth + (size_t)(b * T_ + rr) * C_ + colC) =
                __floats2half2_rn(o0, o1);
        }
    }
}

// ---------------------------------------------------------------------------
// Launch
// ---------------------------------------------------------------------------
extern "C" void kernel_launch(void* const* d_in, const int* in_sizes, int n_in,
                              void* d_out, int out_size) {
    const float* x    = (const float*)d_in[0];
    const float* Wqkv = (const float*)d_in[1];
    const float* Wout = (const float*)d_in[2];
    const float* bout = (const float*)d_in[3];
    const float* Wl1  = (const float*)d_in[4];
    const float* bl1  = (const float*)d_in[5];
    const float* Wl2  = (const float*)d_in[6];
    const float* bl2  = (const float*)d_in[7];
    float* out = (float*)d_out;

    __half *xh = nullptr, *wqkvh = nullptr, *wouth = nullptr, *atth = nullptr;
    cudaGetSymbolAddress((void**)&xh, g_xh);
    cudaGetSymbolAddress((void**)&wqkvh, g_wqkvh);
    cudaGetSymbolAddress((void**)&wouth, g_wouth);
    cudaGetSymbolAddress((void**)&atth, g_atth);

    cudaFuncSetAttribute(attn3_kernel,
                         cudaFuncAttributeMaxDynamicSharedMemorySize, ATT3_SMEM);

    // 1) lambda gates
    lambda_kernel<<<(T_ + 127) / 128, 128>>>(Wl1, bl1, Wl2, bl2);

    // 2) fp16 converts
    {
        size_t n4 = (size_t)M_ * C_ / 4;
        tohalf_kernel<<<(unsigned)((n4 + 255) / 256), 256>>>(x, xh, n4);
        size_t w4 = (size_t)QKV_N * C_ / 4;
        tohalf_kernel<<<(unsigned)((w4 + 255) / 256), 256>>>(Wqkv, wqkvh, w4);
        size_t o4 = (size_t)C_ * C_ / 4;
        tohalf_kernel<<<(unsigned)((o4 + 255) / 256), 256>>>(Wout, wouth, o4);
    }

    // 3) QKV projection (fp16 single-pass), epilogue writes g_s16 hi/lo
    {
        dim3 grid(QKV_N / 128, M_ / 128);
        hgemm_fp16_kernel<<<grid, 256>>>(xh, wqkvh, nullptr, nullptr,
                                         M_, QKV_N, C_, 1);
    }

    // 4) flash attention -> g_atth (fp16)
    attn3_kernel<<<B_ * H_ * NC_ * (CS_ / 128), 256, ATT3_SMEM>>>();

    // 5) output projection (fp16 single-pass) + bias
    {
        dim3 grid(C_ / 128, M_ / 128);
        hgemm_fp16_kernel<<<grid, 256>>>(atth, wouth, bout, out,
                                         M_, C_, C_, 0);
    }
}

// round 14
// speedup vs baseline: 5.1918x; 1.1633x over previous
#include <cuda_runtime.h>
#include <cuda_bf16.h>
#include <cuda_fp16.h>
#include <math.h>
#include <stdint.h>

// ---------------------------------------------------------------------------
// LogLinearAttention — R14: fp16 GEMM warp tile 64x64 (4 warps / 128 threads,
// mma:LDSM ratio 4 vs 2) to relieve the LDSM bottleneck exposed in R13.
// Everything else identical to R13 (validated): fp16 single-pass projections,
// fused QKV->g_s16 hi/lo epilogue, bf16 split-3 flash attention.
//   B=4, T=4096, C=1024, H=16, dh=64, nc=8, cs=512
// ---------------------------------------------------------------------------

#define B_  4
#define T_  4096
#define C_  1024
#define H_  16
#define DH_ 64
#define NC_ 8
#define CS_ 512
#define QKV_N (3 * C_)
#define M_  (B_ * T_)

__device__ float g_lam[H_ * T_];
__device__ __half g_xh[(size_t)M_ * C_];          // x fp16
__device__ __half g_wqkvh[(size_t)QKV_N * C_];    // Wqkv fp16
__device__ __half g_wouth[(size_t)C_ * C_];       // Wout fp16
__device__ __half g_atth[(size_t)M_ * C_];        // O fp16 (attn output)
// q/k/v hi/lo bf16 per-(b,h): [comp3][part2][bh64][t4096][d64]
__device__ __nv_bfloat16 g_s16[(size_t)3 * 2 * 64 * T_ * DH_];

#define S16_OFF(comp, part, bh, t) \
    (((((size_t)((comp) * 2 + (part)) * 64 + (bh)) * T_) + (t)) * DH_)

// ---------------------------------------------------------------------------
__global__ void lambda_kernel(const float* __restrict__ Wl1,
                              const float* __restrict__ bl1,
                              const float* __restrict__ Wl2,
                              const float* __restrict__ bl2) {
    int t = blockIdx.x * blockDim.x + threadIdx.x;
    if (t >= T_) return;
    float lp = logf((float)t + 1.0f);
    float h1[64];
#pragma unroll
    for (int j = 0; j < 64; j++)
        h1[j] = fmaxf(lp * Wl1[j] + bl1[j], 0.0f);
#pragma unroll
    for (int h = 0; h < H_; h++) {
        float s = bl2[h];
        const float* w = Wl2 + h * 64;
#pragma unroll
        for (int j = 0; j < 64; j++) s += w[j] * h1[j];
        g_lam[h * T_ + t] = 1.0f / (1.0f + __expf(-s));
    }
}

// ---------------------------------------------------------------------------
__global__ void tohalf_kernel(const float* __restrict__ A,
                              __half* __restrict__ out, size_t n4) {
    size_t i = (size_t)blockIdx.x * blockDim.x + threadIdx.x;
    if (i >= n4) return;
    float4 v = *(const float4*)(A + i * 4);
    __half2 a = __floats2half2_rn(v.x, v.y);
    __half2 b = __floats2half2_rn(v.z, v.w);
    *(__half2*)(out + i * 4)     = a;
    *(__half2*)(out + i * 4 + 2) = b;
}

// ---------------------------------------------------------------------------
// PTX helpers
// ---------------------------------------------------------------------------
__device__ __forceinline__ unsigned smem_u32(const void* p) {
    return (unsigned)__cvta_generic_to_shared(p);
}
__device__ __forceinline__ void cp16(void* smem_dst, const void* gmem_src) {
    asm volatile("cp.async.cg.shared.global [%0], [%1], 16;\n"
                 :: "r"(smem_u32(smem_dst)), "l"(gmem_src));
}
__device__ __forceinline__ void ldm_x4(unsigned& r0, unsigned& r1,
                                       unsigned& r2, unsigned& r3,
                                       const void* p) {
    asm volatile("ldmatrix.sync.aligned.m8n8.x4.shared.b16 {%0,%1,%2,%3}, [%4];\n"
                 : "=r"(r0), "=r"(r1), "=r"(r2), "=r"(r3) : "r"(smem_u32(p)));
}
__device__ __forceinline__ void ldm_x4t(unsigned& r0, unsigned& r1,
                                        unsigned& r2, unsigned& r3,
                                        const void* p) {
    asm volatile("ldmatrix.sync.aligned.m8n8.x4.trans.shared.b16 {%0,%1,%2,%3}, [%4];\n"
                 : "=r"(r0), "=r"(r1), "=r"(r2), "=r"(r3) : "r"(smem_u32(p)));
}
__device__ __forceinline__ void mma16816(float* c, const unsigned* a, const unsigned* b) {
    asm volatile("mma.sync.aligned.m16n8k16.row.col.f32.bf16.bf16.f32 "
                 "{%0,%1,%2,%3}, {%4,%5,%6,%7}, {%8,%9}, {%0,%1,%2,%3};\n"
                 : "+f"(c[0]), "+f"(c[1]), "+f"(c[2]), "+f"(c[3])
                 : "r"(a[0]), "r"(a[1]), "r"(a[2]), "r"(a[3]),
                   "r"(b[0]), "r"(b[1]));
}
__device__ __forceinline__ void mma16816h(float* c, const unsigned* a, const unsigned* b) {
    asm volatile("mma.sync.aligned.m16n8k16.row.col.f32.f16.f16.f32 "
                 "{%0,%1,%2,%3}, {%4,%5,%6,%7}, {%8,%9}, {%0,%1,%2,%3};\n"
                 : "+f"(c[0]), "+f"(c[1]), "+f"(c[2]), "+f"(c[3])
                 : "r"(a[0]), "r"(a[1]), "r"(a[2]), "r"(a[3]),
                   "r"(b[0]), "r"(b[1]));
}
__device__ __forceinline__ unsigned pack_bf16(float a, float b) {
    unsigned ha = (unsigned)__bfloat16_as_ushort(__float2bfloat16_rn(a));
    unsigned hb = (unsigned)__bfloat16_as_ushort(__float2bfloat16_rn(b));
    return ha | (hb << 16);
}

// ---------------------------------------------------------------------------
// fp16 HMMA GEMM: C[M,N] = A[M,Kp] @ B[N,Kp]^T
// Block 128x128, BK=32, 4 warps (2x2), warp tile 64x64 (mma:LDSM ratio 4).
// mode 0: fp32 C + bias.  mode 1: write bf16 hi/lo into g_s16 (QKV path).
// ---------------------------------------------------------------------------
#define GP 40

__global__ __launch_bounds__(128)
void hgemm_fp16_kernel(const __half* __restrict__ A,
                       const __half* __restrict__ B,
                       const float* __restrict__ bias,
                       float* __restrict__ C,
                       int M, int N, int Kp, int mode) {
    __shared__ __half As[2][128 * GP];
    __shared__ __half Bs[2][128 * GP];

    const int tid  = threadIdx.x;
    const int lane = tid & 31;
    const int wid  = tid >> 5;       // 0..3
    const int wm   = wid >> 1;       // 0..1 (64 rows)
    const int wn   = wid & 1;        // 0..1 (64 cols)
    const int m0   = blockIdx.y * 128;
    const int n0   = blockIdx.x * 128;

    float acc[4][8][4];
#pragma unroll
    for (int i = 0; i < 4; i++)
#pragma unroll
        for (int j = 0; j < 8; j++)
#pragma unroll
            for (int r = 0; r < 4; r++) acc[i][j][r] = 0.0f;

    const int KT = Kp / 32;

    // stage fill: 1024 16B chunks (A 512 + B 512), 8 per thread
    auto fill = [&](int buf, int k0) {
#pragma unroll
        for (int q = tid; q < 1024; q += 128) {
            int tile = q >> 9;              // 0=A, 1=B
            int c    = q & 511;
            int row  = c >> 2;
            int kc   = (c & 3) * 8;
            const __half* src = (tile ? B + (size_t)(n0 + row) * Kp
                                      : A + (size_t)(m0 + row) * Kp) + k0 + kc;
            __half* dst = (tile ? Bs[buf] : As[buf]) + row * GP + kc;
            cp16(dst, src);
        }
        asm volatile("cp.async.commit_group;\n");
    };

    fill(0, 0);
    asm volatile("cp.async.wait_group 0;\n");
    __syncthreads();

    int buf = 0;
    for (int kt = 0; kt < KT; kt++) {
        if (kt + 1 < KT) fill(buf ^ 1, (kt + 1) * 32);

        const __half* Ab = As[buf];
        const __half* Bb = Bs[buf];
#pragma unroll
        for (int ks = 0; ks < 2; ks++) {
            unsigned a[4][4], b[8][2];
            const int ar = lane & 15;
            const int ak = ks * 16 + ((lane >> 4) << 3);
#pragma unroll
            for (int mi = 0; mi < 4; mi++)
                ldm_x4(a[mi][0], a[mi][1], a[mi][2], a[mi][3],
                       Ab + (wm * 64 + mi * 16 + ar) * GP + ak);
            const int br = ((lane >> 4) << 3) + (lane & 7);
            const int bk = ks * 16 + (((lane >> 3) & 1) << 3);
#pragma unroll
            for (int njp = 0; njp < 4; njp++) {
                unsigned r0, r1, r2, r3;
                ldm_x4(r0, r1, r2, r3, Bb + (wn * 64 + njp * 16 + br) * GP + bk);
                b[njp * 2][0] = r0; b[njp * 2][1] = r1;
                b[njp * 2 + 1][0] = r2; b[njp * 2 + 1][1] = r3;
            }
#pragma unroll
            for (int mi = 0; mi < 4; mi++)
#pragma unroll
                for (int nj = 0; nj < 8; nj++)
                    mma16816h(acc[mi][nj], a[mi], b[nj]);
        }
        if (kt + 1 < KT) asm volatile("cp.async.wait_group 0;\n");
        __syncthreads();
        buf ^= 1;
    }

    const int rbase = m0 + wm * 64 + (lane >> 2);
    const int cbase = n0 + wn * 64 + (lane & 3) * 2;
    if (mode == 0) {
#pragma unroll
        for (int mi = 0; mi < 4; mi++) {
#pragma unroll
            for (int nj = 0; nj < 8; nj++) {
                int col = cbase + nj * 8;
                float b0 = bias ? bias[col] : 0.0f;
                float b1 = bias ? bias[col + 1] : 0.0f;
                int r0 = rbase + mi * 16;
                float2 v0 = make_float2(acc[mi][nj][0] + b0, acc[mi][nj][1] + b1);
                float2 v1 = make_float2(acc[mi][nj][2] + b0, acc[mi][nj][3] + b1);
                *(float2*)(C + (size_t)r0 * N + col)       = v0;
                *(float2*)(C + (size_t)(r0 + 8) * N + col) = v1;
            }
        }
    } else {
        // QKV: write bf16 hi/lo directly into g_s16 per-(b,h) layout
#pragma unroll
        for (int mi = 0; mi < 4; mi++) {
#pragma unroll
            for (int nj = 0; nj < 8; nj++) {
                int col = cbase + nj * 8;
                int comp = col >> 10;
                int hh   = (col >> 6) & 15;
                int d    = col & 63;
#pragma unroll
                for (int half_ = 0; half_ < 2; half_++) {
                    int rM = rbase + mi * 16 + half_ * 8;
                    int bb = rM >> 12;
                    int t  = rM & 4095;
                    int bh = bb * H_ + hh;
                    float v0 = acc[mi][nj][half_ * 2];
                    float v1 = acc[mi][nj][half_ * 2 + 1];
                    __nv_bfloat16 h0 = __float2bfloat16_rn(v0);
                    __nv_bfloat16 h1 = __float2bfloat16_rn(v1);
                    __nv_bfloat16 l0 = __float2bfloat16_rn(v0 - __bfloat162float(h0));
                    __nv_bfloat16 l1 = __float2bfloat16_rn(v1 - __bfloat162float(h1));
                    *(__nv_bfloat162*)(g_s16 + S16_OFF(comp, 0, bh, t) + d) =
                        __halves2bfloat162(h0, h1);
                    *(__nv_bfloat162*)(g_s16 + S16_OFF(comp, 1, bh, t) + d) =
                        __halves2bfloat162(l0, l1);
                }
            }
        }
    }
}

// ---------------------------------------------------------------------------
// Flash-style HMMA attention (validated R9-R13); epilogue writes fp16 O.
// ---------------------------------------------------------------------------
#define QP 72
#define MAT_E (64 * QP)
#define STAGE_E (4 * MAT_E)
#define ATT3_SMEM (2 * STAGE_E * 2 + 512 * 4)

__global__ __launch_bounds__(256)
void attn3_kernel() {
    extern __shared__ char sm3[];
    __nv_bfloat16* KV = (__nv_bfloat16*)sm3;
    float* gs = (float*)(KV + 2 * STAGE_E);

    const int tid  = threadIdx.x;
    const int lane = tid & 31;
    const int wid  = tid >> 5;

    const int cid = blockIdx.x;
    const int qt  = cid & 3;
    const int n   = (cid >> 2) & 7;
    const int h   = (cid >> 5) & 15;
    const int b   = cid >> 9;
    const int bh  = b * H_ + h;
    const int t0  = n * CS_ + qt * 128;
    const int tk0 = n * CS_;

    for (int q = tid; q < 2048; q += 256) {
        int part = q >> 10;
        int r = (q >> 3) & 127;
        int c8 = (q & 7) * 8;
        cp16(KV + part * (2 * MAT_E) + r * QP + c8,
             g_s16 + S16_OFF(0, part, bh, t0 + r) + c8);
    }
    asm volatile("cp.async.commit_group;\n");
    for (int i = tid; i < 512; i += 256)
        gs[i] = 0.125f * g_lam[h * T_ + tk0 + i];
    asm volatile("cp.async.wait_group 0;\n");
    __syncthreads();

    unsigned qh[4][4], ql[4][4];
    {
        const int ar = 16 * wid + (lane & 15);
        const int ao = (lane >> 4) << 3;
#pragma unroll
        for (int ks = 0; ks < 4; ks++) {
            ldm_x4(qh[ks][0], qh[ks][1], qh[ks][2], qh[ks][3],
                   KV + ar * QP + ks * 16 + ao);
            ldm_x4(ql[ks][0], ql[ks][1], ql[ks][2], ql[ks][3],
                   KV + 2 * MAT_E + ar * QP + ks * 16 + ao);
        }
    }
    __syncthreads();

    auto fillKV = [&](int st, int kt) {
        __nv_bfloat16* stage = KV + st * STAGE_E;
        int tb = tk0 + kt * 64;
        for (int q = tid; q < 2048; q += 256) {
            int part = q >> 9;
            int r = (q >> 3) & 63;
            int c8 = (q & 7) * 8;
            int comp = 1 + (part >> 1);
            int lo = part & 1;
            cp16(stage + part * MAT_E + r * QP + c8,
                 g_s16 + S16_OFF(comp, lo, bh, tb + r) + c8);
        }
        asm volatile("cp.async.commit_group;\n");
    };
    fillKV(0, 0);
    fillKV(1, 1);

    float m0 = -1e30f, m1 = -1e30f;
    float l0 = 0.0f, l1 = 0.0f;
    float facc[8][4];
#pragma unroll
    for (int i = 0; i < 8; i++)
#pragma unroll
        for (int j = 0; j < 4; j++) facc[i][j] = 0.0f;

    for (int kt = 0; kt < 8; kt++) {
        if (kt == 7) { asm volatile("cp.async.wait_group 0;\n" ::: "memory"); }
        else        { asm volatile("cp.async.wait_group 1;\n" ::: "memory"); }
        __syncthreads();
        __nv_bfloat16* Kh = KV + (kt & 1) * STAGE_E;
        __nv_bfloat16* Kl = Kh + MAT_E;
        __nv_bfloat16* Vh = Kl + MAT_E;
        __nv_bfloat16* Vl = Vh + MAT_E;

        float s[8][4];
#pragma unroll
        for (int i = 0; i < 8; i++)
#pragma unroll
            for (int j = 0; j < 4; j++) s[i][j] = 0.0f;

        {
            const int br = ((lane >> 4) << 3) + (lane & 7);
            const int bo = ((lane >> 3) & 1) << 3;
#pragma unroll
            for (int np = 0; np < 4; np++) {
                int rowb = np * 16 + br;
#pragma unroll
                for (int ks = 0; ks < 4; ks++) {
                    unsigned kh4[4], kl4[4];
                    int bk = ks * 16 + bo;
                    ldm_x4(kh4[0], kh4[1], kh4[2], kh4[3], Kh + rowb * QP + bk);
                    ldm_x4(kl4[0], kl4[1], kl4[2], kl4[3], Kl + rowb * QP + bk);
                    mma16816(s[2 * np],     qh[ks], &kh4[0]);
                    mma16816(s[2 * np + 1], qh[ks], &kh4[2]);
                    mma16816(s[2 * np],     qh[ks], &kl4[0]);
                    mma16816(s[2 * np + 1], qh[ks], &kl4[2]);
                    mma16816(s[2 * np],     ql[ks], &kh4[0]);
                    mma16816(s[2 * np + 1], ql[ks], &kh4[2]);
                }
            }
        }

        float tm0 = -1e30f, tm1 = -1e30f;
#pragma unroll
        for (int nt = 0; nt < 8; nt++) {
            int c = nt * 8 + (lane & 3) * 2;
            float g0 = gs[kt * 64 + c];
            float g1 = gs[kt * 64 + c + 1];
            s[nt][0] *= g0; s[nt][1] *= g1;
            s[nt][2] *= g0; s[nt][3] *= g1;
            tm0 = fmaxf(tm0, fmaxf(s[nt][0], s[nt][1]));
            tm1 = fmaxf(tm1, fmaxf(s[nt][2], s[nt][3]));
        }
        tm0 = fmaxf(tm0, __shfl_xor_sync(0xffffffffu, tm0, 1));
        tm0 = fmaxf(tm0, __shfl_xor_sync(0xffffffffu, tm0, 2));
        tm1 = fmaxf(tm1, __shfl_xor_sync(0xffffffffu, tm1, 1));
        tm1 = fmaxf(tm1, __shfl_xor_sync(0xffffffffu, tm1, 2));

        float mn0 = fmaxf(m0, tm0), mn1 = fmaxf(m1, tm1);
        float a0 = __expf(m0 - mn0), a1 = __expf(m1 - mn1);
        m0 = mn0; m1 = mn1;

        unsigned ph[4][4], pl[4][4];
        float ts0 = 0.0f, ts1 = 0.0f;
#pragma unroll
        for (int j = 0; j < 4; j++) {
#pragma unroll
            for (int half = 0; half < 2; half++) {
                int nt = 2 * j + half;
                float p00 = __expf(s[nt][0] - m0);
                float p01 = __expf(s[nt][1] - m0);
                float p10 = __expf(s[nt][2] - m1);
                float p11 = __expf(s[nt][3] - m1);
                ts0 += p00 + p01;
                ts1 += p10 + p11;
                unsigned hp0 = pack_bf16(p00, p01);
                unsigned hp1 = pack_bf16(p10, p11);
                ph[j][half * 2]     = hp0;
                ph[j][half * 2 + 1] = hp1;
                float r00 = p00 - __bfloat162float(__ushort_as_bfloat16((unsigned short)(hp0 & 0xffff)));
                float r01 = p01 - __bfloat162float(__ushort_as_bfloat16((unsigned short)(hp0 >> 16)));
                float r10 = p10 - __bfloat162float(__ushort_as_bfloat16((unsigned short)(hp1 & 0xffff)));
                float r11 = p11 - __bfloat162float(__ushort_as_bfloat16((unsigned short)(hp1 >> 16)));
                pl[j][half * 2]     = pack_bf16(r00, r01);
                pl[j][half * 2 + 1] = pack_bf16(r10, r11);
            }
        }
        l0 = l0 * a0 + ts0;
        l1 = l1 * a1 + ts1;
#pragma unroll
        for (int nt = 0; nt < 8; nt++) {
            facc[nt][0] *= a0; facc[nt][1] *= a0;
            facc[nt][2] *= a1; facc[nt][3] *= a1;
        }

        {
            const int vm = lane >> 3;
            const int vr = lane & 7;
#pragma unroll
            for (int dt = 0; dt < 4; dt++) {
#pragma unroll
                for (int ks = 0; ks < 4; ks++) {
                    unsigned vh4[4], vl4[4];
                    int row = ks * 16 + ((vm & 1) << 3) + vr;
                    int col = dt * 16 + ((vm >> 1) << 3);
                    ldm_x4t(vh4[0], vh4[1], vh4[2], vh4[3], Vh + row * QP + col);
                    ldm_x4t(vl4[0], vl4[1], vl4[2], vl4[3], Vl + row * QP + col);
                    mma16816(facc[2 * dt],     ph[ks], &vh4[0]);
                    mma16816(facc[2 * dt + 1], ph[ks], &vh4[2]);
                    mma16816(facc[2 * dt],     ph[ks], &vl4[0]);
                    mma16816(facc[2 * dt + 1], ph[ks], &vl4[2]);
                    mma16816(facc[2 * dt],     pl[ks], &vh4[0]);
                    mma16816(facc[2 * dt + 1], pl[ks], &vh4[2]);
                }
            }
        }

        __syncthreads();
        if (kt + 2 < 8) fillKV(kt & 1, kt + 2);
    }

    l0 += __shfl_xor_sync(0xffffffffu, l0, 1);
    l0 += __shfl_xor_sync(0xffffffffu, l0, 2);
    l1 += __shfl_xor_sync(0xffffffffu, l1, 1);
    l1 += __shfl_xor_sync(0xffffffffu, l1, 2);
    float inv0 = 1.0f / l0, inv1 = 1.0f / l1;

    int qrow0 = t0 + 16 * wid + (lane >> 2);
#pragma unroll
    for (int nt = 0; nt < 8; nt++) {
        int colC = h * 64 + nt * 8 + (lane & 3) * 2;
#pragma unroll
        for (int half = 0; half < 2; half++) {
            int rr = qrow0 + half * 8;
            float inv = half ? inv1 : inv0;
            float o0 = facc[nt][half * 2 + 0] * inv;
            float o1 = facc[nt][half * 2 + 1] * inv;
            *(__half2*)(g_atth + (size_t)(b * T_ + rr) * C_ + colC) =
                __floats2half2_rn(o0, o1);
        }
    }
}

// ---------------------------------------------------------------------------
// Launch
// ---------------------------------------------------------------------------
extern "C" void kernel_launch(void* const* d_in, const int* in_sizes, int n_in,
                              void* d_out, int out_size) {
    const float* x    = (const float*)d_in[0];
    const float* Wqkv = (const float*)d_in[1];
    const float* Wout = (const float*)d_in[2];
    const float* bout = (const float*)d_in[3];
    const float* Wl1  = (const float*)d_in[4];
    const float* bl1  = (const float*)d_in[5];
    const float* Wl2  = (const float*)d_in[6];
    const float* bl2  = (const float*)d_in[7];
    float* out = (float*)d_out;

    __half *xh = nullptr, *wqkvh = nullptr, *wouth = nullptr, *atth = nullptr;
    cudaGetSymbolAddress((void**)&xh, g_xh);
    cudaGetSymbolAddress((void**)&wqkvh, g_wqkvh);
    cudaGetSymbolAddress((void**)&wouth, g_wouth);
    cudaGetSymbolAddress((void**)&atth, g_atth);

    cudaFuncSetAttribute(attn3_kernel,
                         cudaFuncAttributeMaxDynamicSharedMemorySize, ATT3_SMEM);

    // 1) lambda gates
    lambda_kernel<<<(T_ + 127) / 128, 128>>>(Wl1, bl1, Wl2, bl2);

    // 2) fp16 converts
    {
        size_t n4 = (size_t)M_ * C_ / 4;
        tohalf_kernel<<<(unsigned)((n4 + 255) / 256), 256>>>(x, xh, n4);
        size_t w4 = (size_t)QKV_N * C_ / 4;
        tohalf_kernel<<<(unsigned)((w4 + 255) / 256), 256>>>(Wqkv, wqkvh, w4);
        size_t o4 = (size_t)C_ * C_ / 4;
        tohalf_kernel<<<(unsigned)((o4 + 255) / 256), 256>>>(Wout, wouth, o4);
    }

    // 3) QKV projection (fp16 single-pass), epilogue writes g_s16 hi/lo
    {
        dim3 grid(QKV_N / 128, M_ / 128);
        hgemm_fp16_kernel<<<grid, 128>>>(xh, wqkvh, nullptr, nullptr,
                                         M_, QKV_N, C_, 1);
    }

    // 4) flash attention -> g_atth (fp16)
    attn3_kernel<<<B_ * H_ * NC_ * (CS_ / 128), 256, ATT3_SMEM>>>();

    // 5) output projection (fp16 single-pass) + bias
    {
        dim3 grid(C_ / 128, M_ / 128);
        hgemm_fp16_kernel<<<grid, 128>>>(atth, wouth, bout, out,
                                         M_, C_, C_, 0);
    }
}

// round 15
// speedup vs baseline: 6.5770x; 1.2668x over previous
#include <cuda_runtime.h>
#include <cuda_bf16.h>
#include <cuda_fp16.h>
#include <math.h>
#include <stdint.h>

// ---------------------------------------------------------------------------
// LogLinearAttention — R15: fully fp16 tensor-core pipeline.
//   - projections: single-pass fp16 HMMA 64x64-warp-tile (validated R14)
//   - attention: flash kernel now single-pass fp16 (q/k/v/P fp16, fp32 accum,
//     exact online softmax) — 3x fewer mma + half the K/V traffic vs split-3
//   B=4, T=4096, C=1024, H=16, dh=64, nc=8, cs=512
// ---------------------------------------------------------------------------

#define B_  4
#define T_  4096
#define C_  1024
#define H_  16
#define DH_ 64
#define NC_ 8
#define CS_ 512
#define QKV_N (3 * C_)
#define M_  (B_ * T_)

__device__ float g_lam[H_ * T_];
__device__ __half g_xh[(size_t)M_ * C_];          // x fp16
__device__ __half g_wqkvh[(size_t)QKV_N * C_];    // Wqkv fp16
__device__ __half g_wouth[(size_t)C_ * C_];       // Wout fp16
__device__ __half g_atth[(size_t)M_ * C_];        // O fp16 (attn output)
// q/k/v fp16 per-(b,h): [comp3][bh64][t4096][d64]
__device__ __half g_s16[(size_t)3 * 64 * T_ * DH_];

#define S16_OFF(comp, bh, t) \
    ((((size_t)(comp) * 64 + (bh)) * T_ + (t)) * DH_)

// ---------------------------------------------------------------------------
__global__ void lambda_kernel(const float* __restrict__ Wl1,
                              const float* __restrict__ bl1,
                              const float* __restrict__ Wl2,
                              const float* __restrict__ bl2) {
    int t = blockIdx.x * blockDim.x + threadIdx.x;
    if (t >= T_) return;
    float lp = logf((float)t + 1.0f);
    float h1[64];
#pragma unroll
    for (int j = 0; j < 64; j++)
        h1[j] = fmaxf(lp * Wl1[j] + bl1[j], 0.0f);
#pragma unroll
    for (int h = 0; h < H_; h++) {
        float s = bl2[h];
        const float* w = Wl2 + h * 64;
#pragma unroll
        for (int j = 0; j < 64; j++) s += w[j] * h1[j];
        g_lam[h * T_ + t] = 1.0f / (1.0f + __expf(-s));
    }
}

// ---------------------------------------------------------------------------
__global__ void tohalf_kernel(const float* __restrict__ A,
                              __half* __restrict__ out, size_t n4) {
    size_t i = (size_t)blockIdx.x * blockDim.x + threadIdx.x;
    if (i >= n4) return;
    float4 v = *(const float4*)(A + i * 4);
    __half2 a = __floats2half2_rn(v.x, v.y);
    __half2 b = __floats2half2_rn(v.z, v.w);
    *(__half2*)(out + i * 4)     = a;
    *(__half2*)(out + i * 4 + 2) = b;
}

// ---------------------------------------------------------------------------
// PTX helpers
// ---------------------------------------------------------------------------
__device__ __forceinline__ unsigned smem_u32(const void* p) {
    return (unsigned)__cvta_generic_to_shared(p);
}
__device__ __forceinline__ void cp16(void* smem_dst, const void* gmem_src) {
    asm volatile("cp.async.cg.shared.global [%0], [%1], 16;\n"
                 :: "r"(smem_u32(smem_dst)), "l"(gmem_src));
}
__device__ __forceinline__ void ldm_x4(unsigned& r0, unsigned& r1,
                                       unsigned& r2, unsigned& r3,
                                       const void* p) {
    asm volatile("ldmatrix.sync.aligned.m8n8.x4.shared.b16 {%0,%1,%2,%3}, [%4];\n"
                 : "=r"(r0), "=r"(r1), "=r"(r2), "=r"(r3) : "r"(smem_u32(p)));
}
__device__ __forceinline__ void ldm_x4t(unsigned& r0, unsigned& r1,
                                        unsigned& r2, unsigned& r3,
                                        const void* p) {
    asm volatile("ldmatrix.sync.aligned.m8n8.x4.trans.shared.b16 {%0,%1,%2,%3}, [%4];\n"
                 : "=r"(r0), "=r"(r1), "=r"(r2), "=r"(r3) : "r"(smem_u32(p)));
}
__device__ __forceinline__ void mma16816h(float* c, const unsigned* a, const unsigned* b) {
    asm volatile("mma.sync.aligned.m16n8k16.row.col.f32.f16.f16.f32 "
                 "{%0,%1,%2,%3}, {%4,%5,%6,%7}, {%8,%9}, {%0,%1,%2,%3};\n"
                 : "+f"(c[0]), "+f"(c[1]), "+f"(c[2]), "+f"(c[3])
                 : "r"(a[0]), "r"(a[1]), "r"(a[2]), "r"(a[3]),
                   "r"(b[0]), "r"(b[1]));
}
__device__ __forceinline__ unsigned pack_half(float a, float b) {
    __half2 h = __floats2half2_rn(a, b);
    return *(unsigned*)&h;
}

// ---------------------------------------------------------------------------
// fp16 HMMA GEMM (validated R14): C[M,N] = A[M,Kp] @ B[N,Kp]^T
// Block 128x128, BK=32, 4 warps (2x2), warp tile 64x64.
// mode 0: fp32 C + bias.  mode 1: write fp16 into g_s16 (QKV path).
// ---------------------------------------------------------------------------
#define GP 40

__global__ __launch_bounds__(128)
void hgemm_fp16_kernel(const __half* __restrict__ A,
                       const __half* __restrict__ B,
                       const float* __restrict__ bias,
                       float* __restrict__ C,
                       int M, int N, int Kp, int mode) {
    __shared__ __half As[2][128 * GP];
    __shared__ __half Bs[2][128 * GP];

    const int tid  = threadIdx.x;
    const int lane = tid & 31;
    const int wid  = tid >> 5;
    const int wm   = wid >> 1;
    const int wn   = wid & 1;
    const int m0   = blockIdx.y * 128;
    const int n0   = blockIdx.x * 128;

    float acc[4][8][4];
#pragma unroll
    for (int i = 0; i < 4; i++)
#pragma unroll
        for (int j = 0; j < 8; j++)
#pragma unroll
            for (int r = 0; r < 4; r++) acc[i][j][r] = 0.0f;

    const int KT = Kp / 32;

    auto fill = [&](int buf, int k0) {
#pragma unroll
        for (int q = tid; q < 1024; q += 128) {
            int tile = q >> 9;
            int c    = q & 511;
            int row  = c >> 2;
            int kc   = (c & 3) * 8;
            const __half* src = (tile ? B + (size_t)(n0 + row) * Kp
                                      : A + (size_t)(m0 + row) * Kp) + k0 + kc;
            __half* dst = (tile ? Bs[buf] : As[buf]) + row * GP + kc;
            cp16(dst, src);
        }
        asm volatile("cp.async.commit_group;\n");
    };

    fill(0, 0);
    asm volatile("cp.async.wait_group 0;\n");
    __syncthreads();

    int buf = 0;
    for (int kt = 0; kt < KT; kt++) {
        if (kt + 1 < KT) fill(buf ^ 1, (kt + 1) * 32);

        const __half* Ab = As[buf];
        const __half* Bb = Bs[buf];
#pragma unroll
        for (int ks = 0; ks < 2; ks++) {
            unsigned a[4][4], b[8][2];
            const int ar = lane & 15;
            const int ak = ks * 16 + ((lane >> 4) << 3);
#pragma unroll
            for (int mi = 0; mi < 4; mi++)
                ldm_x4(a[mi][0], a[mi][1], a[mi][2], a[mi][3],
                       Ab + (wm * 64 + mi * 16 + ar) * GP + ak);
            const int br = ((lane >> 4) << 3) + (lane & 7);
            const int bk = ks * 16 + (((lane >> 3) & 1) << 3);
#pragma unroll
            for (int njp = 0; njp < 4; njp++) {
                unsigned r0, r1, r2, r3;
                ldm_x4(r0, r1, r2, r3, Bb + (wn * 64 + njp * 16 + br) * GP + bk);
                b[njp * 2][0] = r0; b[njp * 2][1] = r1;
                b[njp * 2 + 1][0] = r2; b[njp * 2 + 1][1] = r3;
            }
#pragma unroll
            for (int mi = 0; mi < 4; mi++)
#pragma unroll
                for (int nj = 0; nj < 8; nj++)
                    mma16816h(acc[mi][nj], a[mi], b[nj]);
        }
        if (kt + 1 < KT) asm volatile("cp.async.wait_group 0;\n");
        __syncthreads();
        buf ^= 1;
    }

    const int rbase = m0 + wm * 64 + (lane >> 2);
    const int cbase = n0 + wn * 64 + (lane & 3) * 2;
    if (mode == 0) {
#pragma unroll
        for (int mi = 0; mi < 4; mi++) {
#pragma unroll
            for (int nj = 0; nj < 8; nj++) {
                int col = cbase + nj * 8;
                float b0 = bias ? bias[col] : 0.0f;
                float b1 = bias ? bias[col + 1] : 0.0f;
                int r0 = rbase + mi * 16;
                float2 v0 = make_float2(acc[mi][nj][0] + b0, acc[mi][nj][1] + b1);
                float2 v1 = make_float2(acc[mi][nj][2] + b0, acc[mi][nj][3] + b1);
                *(float2*)(C + (size_t)r0 * N + col)       = v0;
                *(float2*)(C + (size_t)(r0 + 8) * N + col) = v1;
            }
        }
    } else {
        // QKV: write fp16 directly into g_s16 per-(b,h) layout
#pragma unroll
        for (int mi = 0; mi < 4; mi++) {
#pragma unroll
            for (int nj = 0; nj < 8; nj++) {
                int col = cbase + nj * 8;
                int comp = col >> 10;
                int hh   = (col >> 6) & 15;
                int d    = col & 63;
#pragma unroll
                for (int half_ = 0; half_ < 2; half_++) {
                    int rM = rbase + mi * 16 + half_ * 8;
                    int bb = rM >> 12;
                    int t  = rM & 4095;
                    int bh = bb * H_ + hh;
                    *(__half2*)(g_s16 + S16_OFF(comp, bh, t) + d) =
                        __floats2half2_rn(acc[mi][nj][half_ * 2],
                                          acc[mi][nj][half_ * 2 + 1]);
                }
            }
        }
    }
}

// ---------------------------------------------------------------------------
// Flash-style fp16 attention. One block = 128 q rows of one (b,h,chunk).
// 256 threads / 8 warps; warp w owns q rows [16w,16w+16), all d=64.
// Single-pass fp16 mma (fp32 accum), exact online softmax, P fp16 in regs.
// smem: 2 stages x (K|V)[64][72] fp16 + gates = ~39 KB.
// ---------------------------------------------------------------------------
#define QP 72
#define MAT_E (64 * QP)
#define STAGE_E (2 * MAT_E)
#define ATT3_SMEM (2 * STAGE_E * 2 + 512 * 4)

__global__ __launch_bounds__(256)
void attn4_kernel() {
    extern __shared__ char sm3[];
    __half* KV = (__half*)sm3;                 // 2 stages x (K|V)
    float* gs = (float*)(KV + 2 * STAGE_E);    // [512]

    const int tid  = threadIdx.x;
    const int lane = tid & 31;
    const int wid  = tid >> 5;

    const int cid = blockIdx.x;
    const int qt  = cid & 3;
    const int n   = (cid >> 2) & 7;
    const int h   = (cid >> 5) & 15;
    const int b   = cid >> 9;
    const int bh  = b * H_ + h;
    const int t0  = n * CS_ + qt * 128;
    const int tk0 = n * CS_;

    // ---- Q load into stage0 area (128 rows; freed after frag extraction) ----
    for (int q = tid; q < 1024; q += 256) {
        int r = q >> 3;
        int c8 = (q & 7) * 8;
        cp16(KV + r * QP + c8, g_s16 + S16_OFF(0, bh, t0 + r) + c8);
    }
    asm volatile("cp.async.commit_group;\n");
    for (int i = tid; i < 512; i += 256)
        gs[i] = 0.125f * g_lam[h * T_ + tk0 + i];
    asm volatile("cp.async.wait_group 0;\n");
    __syncthreads();

    // Q fragments (persist)
    unsigned qf[4][4];
    {
        const int ar = 16 * wid + (lane & 15);
        const int ao = (lane >> 4) << 3;
#pragma unroll
        for (int ks = 0; ks < 4; ks++)
            ldm_x4(qf[ks][0], qf[ks][1], qf[ks][2], qf[ks][3],
                   KV + ar * QP + ks * 16 + ao);
    }
    __syncthreads();

    // ---- K/V stage fill ----
    auto fillKV = [&](int st, int kt) {
        __half* stage = KV + st * STAGE_E;
        int tb = tk0 + kt * 64;
        for (int q = tid; q < 1024; q += 256) {
            int part = q >> 9;                 // 0=K, 1=V
            int r = (q >> 3) & 63;
            int c8 = (q & 7) * 8;
            cp16(stage + part * MAT_E + r * QP + c8,
                 g_s16 + S16_OFF(1 + part, bh, tb + r) + c8);
        }
        asm volatile("cp.async.commit_group;\n");
    };
    fillKV(0, 0);
    fillKV(1, 1);

    float m0 = -1e30f, m1 = -1e30f;
    float l0 = 0.0f, l1 = 0.0f;
    float facc[8][4];
#pragma unroll
    for (int i = 0; i < 8; i++)
#pragma unroll
        for (int j = 0; j < 4; j++) facc[i][j] = 0.0f;

    for (int kt = 0; kt < 8; kt++) {
        if (kt == 7) { asm volatile("cp.async.wait_group 0;\n" ::: "memory"); }
        else        { asm volatile("cp.async.wait_group 1;\n" ::: "memory"); }
        __syncthreads();
        __half* Kh = KV + (kt & 1) * STAGE_E;
        __half* Vh = Kh + MAT_E;

        // ===== S = Q K^T =====
        float s[8][4];
#pragma unroll
        for (int i = 0; i < 8; i++)
#pragma unroll
            for (int j = 0; j < 4; j++) s[i][j] = 0.0f;

        {
            const int br = ((lane >> 4) << 3) + (lane & 7);
            const int bo = ((lane >> 3) & 1) << 3;
#pragma unroll
            for (int np = 0; np < 4; np++) {
                int rowb = np * 16 + br;
#pragma unroll
                for (int ks = 0; ks < 4; ks++) {
                    unsigned k4[4];
                    ldm_x4(k4[0], k4[1], k4[2], k4[3],
                           Kh + rowb * QP + ks * 16 + bo);
                    mma16816h(s[2 * np],     qf[ks], &k4[0]);
                    mma16816h(s[2 * np + 1], qf[ks], &k4[2]);
                }
            }
        }

        // ===== gate + online softmax =====
        float tm0 = -1e30f, tm1 = -1e30f;
#pragma unroll
        for (int nt = 0; nt < 8; nt++) {
            int c = nt * 8 + (lane & 3) * 2;
            float g0 = gs[kt * 64 + c];
            float g1 = gs[kt * 64 + c + 1];
            s[nt][0] *= g0; s[nt][1] *= g1;
            s[nt][2] *= g0; s[nt][3] *= g1;
            tm0 = fmaxf(tm0, fmaxf(s[nt][0], s[nt][1]));
            tm1 = fmaxf(tm1, fmaxf(s[nt][2], s[nt][3]));
        }
        tm0 = fmaxf(tm0, __shfl_xor_sync(0xffffffffu, tm0, 1));
        tm0 = fmaxf(tm0, __shfl_xor_sync(0xffffffffu, tm0, 2));
        tm1 = fmaxf(tm1, __shfl_xor_sync(0xffffffffu, tm1, 1));
        tm1 = fmaxf(tm1, __shfl_xor_sync(0xffffffffu, tm1, 2));

        float mn0 = fmaxf(m0, tm0), mn1 = fmaxf(m1, tm1);
        float a0 = __expf(m0 - mn0), a1 = __expf(m1 - mn1);
        m0 = mn0; m1 = mn1;

        unsigned pf[4][4];
        float ts0 = 0.0f, ts1 = 0.0f;
#pragma unroll
        for (int j = 0; j < 4; j++) {
#pragma unroll
            for (int half = 0; half < 2; half++) {
                int nt = 2 * j + half;
                float p00 = __expf(s[nt][0] - m0);
                float p01 = __expf(s[nt][1] - m0);
                float p10 = __expf(s[nt][2] - m1);
                float p11 = __expf(s[nt][3] - m1);
                ts0 += p00 + p01;
                ts1 += p10 + p11;
                pf[j][half * 2]     = pack_half(p00, p01);
                pf[j][half * 2 + 1] = pack_half(p10, p11);
            }
        }
        l0 = l0 * a0 + ts0;
        l1 = l1 * a1 + ts1;
#pragma unroll
        for (int nt = 0; nt < 8; nt++) {
            facc[nt][0] *= a0; facc[nt][1] *= a0;
            facc[nt][2] *= a1; facc[nt][3] *= a1;
        }

        // ===== O += P V =====
        {
            const int vm = lane >> 3;
            const int vr = lane & 7;
#pragma unroll
            for (int dt = 0; dt < 4; dt++) {
#pragma unroll
                for (int ks = 0; ks < 4; ks++) {
                    unsigned v4[4];
                    int row = ks * 16 + ((vm & 1) << 3) + vr;
                    int col = dt * 16 + ((vm >> 1) << 3);
                    ldm_x4t(v4[0], v4[1], v4[2], v4[3], Vh + row * QP + col);
                    mma16816h(facc[2 * dt],     pf[ks], &v4[0]);
                    mma16816h(facc[2 * dt + 1], pf[ks], &v4[2]);
                }
            }
        }

        __syncthreads();
        if (kt + 2 < 8) fillKV(kt & 1, kt + 2);
    }

    // ---- epilogue: normalize, write fp16 O ----
    l0 += __shfl_xor_sync(0xffffffffu, l0, 1);
    l0 += __shfl_xor_sync(0xffffffffu, l0, 2);
    l1 += __shfl_xor_sync(0xffffffffu, l1, 1);
    l1 += __shfl_xor_sync(0xffffffffu, l1, 2);
    float inv0 = 1.0f / l0, inv1 = 1.0f / l1;

    int qrow0 = t0 + 16 * wid + (lane >> 2);
#pragma unroll
    for (int nt = 0; nt < 8; nt++) {
        int colC = h * 64 + nt * 8 + (lane & 3) * 2;
#pragma unroll
        for (int half = 0; half < 2; half++) {
            int rr = qrow0 + half * 8;
            float inv = half ? inv1 : inv0;
            float o0 = facc[nt][half * 2 + 0] * inv;
            float o1 = facc[nt][half * 2 + 1] * inv;
            *(__half2*)(g_atth + (size_t)(b * T_ + rr) * C_ + colC) =
                __floats2half2_rn(o0, o1);
        }
    }
}

// ---------------------------------------------------------------------------
// Launch
// ---------------------------------------------------------------------------
extern "C" void kernel_launch(void* const* d_in, const int* in_sizes, int n_in,
                              void* d_out, int out_size) {
    const float* x    = (const float*)d_in[0];
    const float* Wqkv = (const float*)d_in[1];
    const float* Wout = (const float*)d_in[2];
    const float* bout = (const float*)d_in[3];
    const float* Wl1  = (const float*)d_in[4];
    const float* bl1  = (const float*)d_in[5];
    const float* Wl2  = (const float*)d_in[6];
    const float* bl2  = (const float*)d_in[7];
    float* out = (float*)d_out;

    __half *xh = nullptr, *wqkvh = nullptr, *wouth = nullptr, *atth = nullptr;
    cudaGetSymbolAddress((void**)&xh, g_xh);
    cudaGetSymbolAddress((void**)&wqkvh, g_wqkvh);
    cudaGetSymbolAddress((void**)&wouth, g_wouth);
    cudaGetSymbolAddress((void**)&atth, g_atth);

    cudaFuncSetAttribute(attn4_kernel,
                         cudaFuncAttributeMaxDynamicSharedMemorySize, ATT3_SMEM);

    // 1) lambda gates
    lambda_kernel<<<(T_ + 127) / 128, 128>>>(Wl1, bl1, Wl2, bl2);

    // 2) fp16 converts
    {
        size_t n4 = (size_t)M_ * C_ / 4;
        tohalf_kernel<<<(unsigned)((n4 + 255) / 256), 256>>>(x, xh, n4);
        size_t w4 = (size_t)QKV_N * C_ / 4;
        tohalf_kernel<<<(unsigned)((w4 + 255) / 256), 256>>>(Wqkv, wqkvh, w4);
        size_t o4 = (size_t)C_ * C_ / 4;
        tohalf_kernel<<<(unsigned)((o4 + 255) / 256), 256>>>(Wout, wouth, o4);
    }

    // 3) QKV projection (fp16), epilogue writes g_s16 fp16
    {
        dim3 grid(QKV_N / 128, M_ / 128);
        hgemm_fp16_kernel<<<grid, 128>>>(xh, wqkvh, nullptr, nullptr,
                                         M_, QKV_N, C_, 1);
    }

    // 4) fp16 flash attention -> g_atth
    attn4_kernel<<<B_ * H_ * NC_ * (CS_ / 128), 256, ATT3_SMEM>>>();

    // 5) output projection (fp16) + bias
    {
        dim3 grid(C_ / 128, M_ / 128);
        hgemm_fp16_kernel<<<grid, 128>>>(atth, wouth, bout, out,
                                         M_, C_, C_, 0);
    }
}

// round 16
// speedup vs baseline: 7.4183x; 1.1279x over previous
#include <cuda_runtime.h>
#include <cuda_bf16.h>
#include <cuda_fp16.h>
#include <math.h>
#include <stdint.h>

// ---------------------------------------------------------------------------
// LogLinearAttention — R16: fp16 GEMM occupancy + barrier-rate tuning:
//   __launch_bounds__(128,3) (3 blocks/SM, regs<=170) and BK 32->64 (half the
//   __syncthreads, pitch-72 smem, dynamic 73.7KB). Attention + everything else
//   identical to R15 (validated, 721us / 5.9e-4).
//   B=4, T=4096, C=1024, H=16, dh=64, nc=8, cs=512
// ---------------------------------------------------------------------------

#define B_  4
#define T_  4096
#define C_  1024
#define H_  16
#define DH_ 64
#define NC_ 8
#define CS_ 512
#define QKV_N (3 * C_)
#define M_  (B_ * T_)

__device__ float g_lam[H_ * T_];
__device__ __half g_xh[(size_t)M_ * C_];          // x fp16
__device__ __half g_wqkvh[(size_t)QKV_N * C_];    // Wqkv fp16
__device__ __half g_wouth[(size_t)C_ * C_];       // Wout fp16
__device__ __half g_atth[(size_t)M_ * C_];        // O fp16 (attn output)
// q/k/v fp16 per-(b,h): [comp3][bh64][t4096][d64]
__device__ __half g_s16[(size_t)3 * 64 * T_ * DH_];

#define S16_OFF(comp, bh, t) \
    ((((size_t)(comp) * 64 + (bh)) * T_ + (t)) * DH_)

// ---------------------------------------------------------------------------
__global__ void lambda_kernel(const float* __restrict__ Wl1,
                              const float* __restrict__ bl1,
                              const float* __restrict__ Wl2,
                              const float* __restrict__ bl2) {
    int t = blockIdx.x * blockDim.x + threadIdx.x;
    if (t >= T_) return;
    float lp = logf((float)t + 1.0f);
    float h1[64];
#pragma unroll
    for (int j = 0; j < 64; j++)
        h1[j] = fmaxf(lp * Wl1[j] + bl1[j], 0.0f);
#pragma unroll
    for (int h = 0; h < H_; h++) {
        float s = bl2[h];
        const float* w = Wl2 + h * 64;
#pragma unroll
        for (int j = 0; j < 64; j++) s += w[j] * h1[j];
        g_lam[h * T_ + t] = 1.0f / (1.0f + __expf(-s));
    }
}

// ---------------------------------------------------------------------------
__global__ void tohalf_kernel(const float* __restrict__ A,
                              __half* __restrict__ out, size_t n4) {
    size_t i = (size_t)blockIdx.x * blockDim.x + threadIdx.x;
    if (i >= n4) return;
    float4 v = *(const float4*)(A + i * 4);
    __half2 a = __floats2half2_rn(v.x, v.y);
    __half2 b = __floats2half2_rn(v.z, v.w);
    *(__half2*)(out + i * 4)     = a;
    *(__half2*)(out + i * 4 + 2) = b;
}

// ---------------------------------------------------------------------------
// PTX helpers
// ---------------------------------------------------------------------------
__device__ __forceinline__ unsigned smem_u32(const void* p) {
    return (unsigned)__cvta_generic_to_shared(p);
}
__device__ __forceinline__ void cp16(void* smem_dst, const void* gmem_src) {
    asm volatile("cp.async.cg.shared.global [%0], [%1], 16;\n"
                 :: "r"(smem_u32(smem_dst)), "l"(gmem_src));
}
__device__ __forceinline__ void ldm_x4(unsigned& r0, unsigned& r1,
                                       unsigned& r2, unsigned& r3,
                                       const void* p) {
    asm volatile("ldmatrix.sync.aligned.m8n8.x4.shared.b16 {%0,%1,%2,%3}, [%4];\n"
                 : "=r"(r0), "=r"(r1), "=r"(r2), "=r"(r3) : "r"(smem_u32(p)));
}
__device__ __forceinline__ void ldm_x4t(unsigned& r0, unsigned& r1,
                                        unsigned& r2, unsigned& r3,
                                        const void* p) {
    asm volatile("ldmatrix.sync.aligned.m8n8.x4.trans.shared.b16 {%0,%1,%2,%3}, [%4];\n"
                 : "=r"(r0), "=r"(r1), "=r"(r2), "=r"(r3) : "r"(smem_u32(p)));
}
__device__ __forceinline__ void mma16816h(float* c, const unsigned* a, const unsigned* b) {
    asm volatile("mma.sync.aligned.m16n8k16.row.col.f32.f16.f16.f32 "
                 "{%0,%1,%2,%3}, {%4,%5,%6,%7}, {%8,%9}, {%0,%1,%2,%3};\n"
                 : "+f"(c[0]), "+f"(c[1]), "+f"(c[2]), "+f"(c[3])
                 : "r"(a[0]), "r"(a[1]), "r"(a[2]), "r"(a[3]),
                   "r"(b[0]), "r"(b[1]));
}
__device__ __forceinline__ unsigned pack_half(float a, float b) {
    __half2 h = __floats2half2_rn(a, b);
    return *(unsigned*)&h;
}

// ---------------------------------------------------------------------------
// fp16 HMMA GEMM: C[M,N] = A[M,Kp] @ B[N,Kp]^T
// Block 128x128, BK=64 (pitch 72), 4 warps (2x2), warp tile 64x64.
// 3 blocks/SM target via __launch_bounds__(128,3). Dynamic smem 73.7KB.
// mode 0: fp32 C + bias.  mode 1: write fp16 into g_s16 (QKV path).
// ---------------------------------------------------------------------------
#define GPK 72
#define GTILE (128 * GPK)                 // halfs per matrix per buffer
#define GEMM_SMEM_BYTES (4 * GTILE * 2)   // As[2]+Bs[2]

__global__ __launch_bounds__(128, 3)
void hgemm_fp16_kernel(const __half* __restrict__ A,
                       const __half* __restrict__ B,
                       const float* __restrict__ bias,
                       float* __restrict__ C,
                       int M, int N, int Kp, int mode) {
    extern __shared__ __half S[];
    __half* As[2] = {S, S + GTILE};
    __half* Bs[2] = {S + 2 * GTILE, S + 3 * GTILE};

    const int tid  = threadIdx.x;
    const int lane = tid & 31;
    const int wid  = tid >> 5;
    const int wm   = wid >> 1;
    const int wn   = wid & 1;
    const int m0   = blockIdx.y * 128;
    const int n0   = blockIdx.x * 128;

    float acc[4][8][4];
#pragma unroll
    for (int i = 0; i < 4; i++)
#pragma unroll
        for (int j = 0; j < 8; j++)
#pragma unroll
            for (int r = 0; r < 4; r++) acc[i][j][r] = 0.0f;

    const int KT = Kp / 64;

    // fill one BK=64 stage: 2048 16B chunks (A 1024 + B 1024), 16/thread
    auto fill = [&](int buf, int k0) {
#pragma unroll
        for (int q = tid; q < 2048; q += 128) {
            int tile = q >> 10;
            int c    = q & 1023;
            int row  = c >> 3;
            int kc   = (c & 7) * 8;
            const __half* src = (tile ? B + (size_t)(n0 + row) * Kp
                                      : A + (size_t)(m0 + row) * Kp) + k0 + kc;
            __half* dst = (tile ? Bs[buf] : As[buf]) + row * GPK + kc;
            cp16(dst, src);
        }
        asm volatile("cp.async.commit_group;\n");
    };

    fill(0, 0);
    asm volatile("cp.async.wait_group 0;\n");
    __syncthreads();

    int buf = 0;
    for (int kt = 0; kt < KT; kt++) {
        if (kt + 1 < KT) fill(buf ^ 1, (kt + 1) * 64);

        const __half* Ab = As[buf];
        const __half* Bb = Bs[buf];
#pragma unroll
        for (int ks = 0; ks < 4; ks++) {
            unsigned a[4][4], b[8][2];
            const int ar = lane & 15;
            const int ak = ks * 16 + ((lane >> 4) << 3);
#pragma unroll
            for (int mi = 0; mi < 4; mi++)
                ldm_x4(a[mi][0], a[mi][1], a[mi][2], a[mi][3],
                       Ab + (wm * 64 + mi * 16 + ar) * GPK + ak);
            const int br = ((lane >> 4) << 3) + (lane & 7);
            const int bk = ks * 16 + (((lane >> 3) & 1) << 3);
#pragma unroll
            for (int njp = 0; njp < 4; njp++) {
                unsigned r0, r1, r2, r3;
                ldm_x4(r0, r1, r2, r3, Bb + (wn * 64 + njp * 16 + br) * GPK + bk);
                b[njp * 2][0] = r0; b[njp * 2][1] = r1;
                b[njp * 2 + 1][0] = r2; b[njp * 2 + 1][1] = r3;
            }
#pragma unroll
            for (int mi = 0; mi < 4; mi++)
#pragma unroll
                for (int nj = 0; nj < 8; nj++)
                    mma16816h(acc[mi][nj], a[mi], b[nj]);
        }
        if (kt + 1 < KT) asm volatile("cp.async.wait_group 0;\n");
        __syncthreads();
        buf ^= 1;
    }

    const int rbase = m0 + wm * 64 + (lane >> 2);
    const int cbase = n0 + wn * 64 + (lane & 3) * 2;
    if (mode == 0) {
#pragma unroll
        for (int mi = 0; mi < 4; mi++) {
#pragma unroll
            for (int nj = 0; nj < 8; nj++) {
                int col = cbase + nj * 8;
                float b0 = bias ? bias[col] : 0.0f;
                float b1 = bias ? bias[col + 1] : 0.0f;
                int r0 = rbase + mi * 16;
                float2 v0 = make_float2(acc[mi][nj][0] + b0, acc[mi][nj][1] + b1);
                float2 v1 = make_float2(acc[mi][nj][2] + b0, acc[mi][nj][3] + b1);
                *(float2*)(C + (size_t)r0 * N + col)       = v0;
                *(float2*)(C + (size_t)(r0 + 8) * N + col) = v1;
            }
        }
    } else {
        // QKV: write fp16 directly into g_s16 per-(b,h) layout
#pragma unroll
        for (int mi = 0; mi < 4; mi++) {
#pragma unroll
            for (int nj = 0; nj < 8; nj++) {
                int col = cbase + nj * 8;
                int comp = col >> 10;
                int hh   = (col >> 6) & 15;
                int d    = col & 63;
#pragma unroll
                for (int half_ = 0; half_ < 2; half_++) {
                    int rM = rbase + mi * 16 + half_ * 8;
                    int bb = rM >> 12;
                    int t  = rM & 4095;
                    int bh = bb * H_ + hh;
                    *(__half2*)(g_s16 + S16_OFF(comp, bh, t) + d) =
                        __floats2half2_rn(acc[mi][nj][half_ * 2],
                                          acc[mi][nj][half_ * 2 + 1]);
                }
            }
        }
    }
}

// ---------------------------------------------------------------------------
// Flash-style fp16 attention (validated R15). One block = 128 q rows.
// ---------------------------------------------------------------------------
#define QP 72
#define MAT_E (64 * QP)
#define STAGE_E (2 * MAT_E)
#define ATT3_SMEM (2 * STAGE_E * 2 + 512 * 4)

__global__ __launch_bounds__(256)
void attn4_kernel() {
    extern __shared__ char sm3[];
    __half* KV = (__half*)sm3;
    float* gs = (float*)(KV + 2 * STAGE_E);

    const int tid  = threadIdx.x;
    const int lane = tid & 31;
    const int wid  = tid >> 5;

    const int cid = blockIdx.x;
    const int qt  = cid & 3;
    const int n   = (cid >> 2) & 7;
    const int h   = (cid >> 5) & 15;
    const int b   = cid >> 9;
    const int bh  = b * H_ + h;
    const int t0  = n * CS_ + qt * 128;
    const int tk0 = n * CS_;

    for (int q = tid; q < 1024; q += 256) {
        int r = q >> 3;
        int c8 = (q & 7) * 8;
        cp16(KV + r * QP + c8, g_s16 + S16_OFF(0, bh, t0 + r) + c8);
    }
    asm volatile("cp.async.commit_group;\n");
    for (int i = tid; i < 512; i += 256)
        gs[i] = 0.125f * g_lam[h * T_ + tk0 + i];
    asm volatile("cp.async.wait_group 0;\n");
    __syncthreads();

    unsigned qf[4][4];
    {
        const int ar = 16 * wid + (lane & 15);
        const int ao = (lane >> 4) << 3;
#pragma unroll
        for (int ks = 0; ks < 4; ks++)
            ldm_x4(qf[ks][0], qf[ks][1], qf[ks][2], qf[ks][3],
                   KV + ar * QP + ks * 16 + ao);
    }
    __syncthreads();

    auto fillKV = [&](int st, int kt) {
        __half* stage = KV + st * STAGE_E;
        int tb = tk0 + kt * 64;
        for (int q = tid; q < 1024; q += 256) {
            int part = q >> 9;
            int r = (q >> 3) & 63;
            int c8 = (q & 7) * 8;
            cp16(stage + part * MAT_E + r * QP + c8,
                 g_s16 + S16_OFF(1 + part, bh, tb + r) + c8);
        }
        asm volatile("cp.async.commit_group;\n");
    };
    fillKV(0, 0);
    fillKV(1, 1);

    float m0 = -1e30f, m1 = -1e30f;
    float l0 = 0.0f, l1 = 0.0f;
    float facc[8][4];
#pragma unroll
    for (int i = 0; i < 8; i++)
#pragma unroll
        for (int j = 0; j < 4; j++) facc[i][j] = 0.0f;

    for (int kt = 0; kt < 8; kt++) {
        if (kt == 7) { asm volatile("cp.async.wait_group 0;\n" ::: "memory"); }
        else        { asm volatile("cp.async.wait_group 1;\n" ::: "memory"); }
        __syncthreads();
        __half* Kh = KV + (kt & 1) * STAGE_E;
        __half* Vh = Kh + MAT_E;

        float s[8][4];
#pragma unroll
        for (int i = 0; i < 8; i++)
#pragma unroll
            for (int j = 0; j < 4; j++) s[i][j] = 0.0f;

        {
            const int br = ((lane >> 4) << 3) + (lane & 7);
            const int bo = ((lane >> 3) & 1) << 3;
#pragma unroll
            for (int np = 0; np < 4; np++) {
                int rowb = np * 16 + br;
#pragma unroll
                for (int ks = 0; ks < 4; ks++) {
                    unsigned k4[4];
                    ldm_x4(k4[0], k4[1], k4[2], k4[3],
                           Kh + rowb * QP + ks * 16 + bo);
                    mma16816h(s[2 * np],     qf[ks], &k4[0]);
                    mma16816h(s[2 * np + 1], qf[ks], &k4[2]);
                }
            }
        }

        float tm0 = -1e30f, tm1 = -1e30f;
#pragma unroll
        for (int nt = 0; nt < 8; nt++) {
            int c = nt * 8 + (lane & 3) * 2;
            float g0 = gs[kt * 64 + c];
            float g1 = gs[kt * 64 + c + 1];
            s[nt][0] *= g0; s[nt][1] *= g1;
            s[nt][2] *= g0; s[nt][3] *= g1;
            tm0 = fmaxf(tm0, fmaxf(s[nt][0], s[nt][1]));
            tm1 = fmaxf(tm1, fmaxf(s[nt][2], s[nt][3]));
        }
        tm0 = fmaxf(tm0, __shfl_xor_sync(0xffffffffu, tm0, 1));
        tm0 = fmaxf(tm0, __shfl_xor_sync(0xffffffffu, tm0, 2));
        tm1 = fmaxf(tm1, __shfl_xor_sync(0xffffffffu, tm1, 1));
        tm1 = fmaxf(tm1, __shfl_xor_sync(0xffffffffu, tm1, 2));

        float mn0 = fmaxf(m0, tm0), mn1 = fmaxf(m1, tm1);
        float a0 = __expf(m0 - mn0), a1 = __expf(m1 - mn1);
        m0 = mn0; m1 = mn1;

        unsigned pf[4][4];
        float ts0 = 0.0f, ts1 = 0.0f;
#pragma unroll
        for (int j = 0; j < 4; j++) {
#pragma unroll
            for (int half = 0; half < 2; half++) {
                int nt = 2 * j + half;
                float p00 = __expf(s[nt][0] - m0);
                float p01 = __expf(s[nt][1] - m0);
                float p10 = __expf(s[nt][2] - m1);
                float p11 = __expf(s[nt][3] - m1);
                ts0 += p00 + p01;
                ts1 += p10 + p11;
                pf[j][half * 2]     = pack_half(p00, p01);
                pf[j][half * 2 + 1] = pack_half(p10, p11);
            }
        }
        l0 = l0 * a0 + ts0;
        l1 = l1 * a1 + ts1;
#pragma unroll
        for (int nt = 0; nt < 8; nt++) {
            facc[nt][0] *= a0; facc[nt][1] *= a0;
            facc[nt][2] *= a1; facc[nt][3] *= a1;
        }

        {
            const int vm = lane >> 3;
            const int vr = lane & 7;
#pragma unroll
            for (int dt = 0; dt < 4; dt++) {
#pragma unroll
                for (int ks = 0; ks < 4; ks++) {
                    unsigned v4[4];
                    int row = ks * 16 + ((vm & 1) << 3) + vr;
                    int col = dt * 16 + ((vm >> 1) << 3);
                    ldm_x4t(v4[0], v4[1], v4[2], v4[3], Vh + row * QP + col);
                    mma16816h(facc[2 * dt],     pf[ks], &v4[0]);
                    mma16816h(facc[2 * dt + 1], pf[ks], &v4[2]);
                }
            }
        }

        __syncthreads();
        if (kt + 2 < 8) fillKV(kt & 1, kt + 2);
    }

    l0 += __shfl_xor_sync(0xffffffffu, l0, 1);
    l0 += __shfl_xor_sync(0xffffffffu, l0, 2);
    l1 += __shfl_xor_sync(0xffffffffu, l1, 1);
    l1 += __shfl_xor_sync(0xffffffffu, l1, 2);
    float inv0 = 1.0f / l0, inv1 = 1.0f / l1;

    int qrow0 = t0 + 16 * wid + (lane >> 2);
#pragma unroll
    for (int nt = 0; nt < 8; nt++) {
        int colC = h * 64 + nt * 8 + (lane & 3) * 2;
#pragma unroll
        for (int half = 0; half < 2; half++) {
            int rr = qrow0 + half * 8;
            float inv = half ? inv1 : inv0;
            float o0 = facc[nt][half * 2 + 0] * inv;
            float o1 = facc[nt][half * 2 + 1] * inv;
            *(__half2*)(g_atth + (size_t)(b * T_ + rr) * C_ + colC) =
                __floats2half2_rn(o0, o1);
        }
    }
}

// ---------------------------------------------------------------------------
// Launch
// ---------------------------------------------------------------------------
extern "C" void kernel_launch(void* const* d_in, const int* in_sizes, int n_in,
                              void* d_out, int out_size) {
    const float* x    = (const float*)d_in[0];
    const float* Wqkv = (const float*)d_in[1];
    const float* Wout = (const float*)d_in[2];
    const float* bout = (const float*)d_in[3];
    const float* Wl1  = (const float*)d_in[4];
    const float* bl1  = (const float*)d_in[5];
    const float* Wl2  = (const float*)d_in[6];
    const float* bl2  = (const float*)d_in[7];
    float* out = (float*)d_out;

    __half *xh = nullptr, *wqkvh = nullptr, *wouth = nullptr, *atth = nullptr;
    cudaGetSymbolAddress((void**)&xh, g_xh);
    cudaGetSymbolAddress((void**)&wqkvh, g_wqkvh);
    cudaGetSymbolAddress((void**)&wouth, g_wouth);
    cudaGetSymbolAddress((void**)&atth, g_atth);

    cudaFuncSetAttribute(attn4_kernel,
                         cudaFuncAttributeMaxDynamicSharedMemorySize, ATT3_SMEM);
    cudaFuncSetAttribute(hgemm_fp16_kernel,
                         cudaFuncAttributeMaxDynamicSharedMemorySize,
                         GEMM_SMEM_BYTES);

    // 1) lambda gates
    lambda_kernel<<<(T_ + 127) / 128, 128>>>(Wl1, bl1, Wl2, bl2);

    // 2) fp16 converts
    {
        size_t n4 = (size_t)M_ * C_ / 4;
        tohalf_kernel<<<(unsigned)((n4 + 255) / 256), 256>>>(x, xh, n4);
        size_t w4 = (size_t)QKV_N * C_ / 4;
        tohalf_kernel<<<(unsigned)((w4 + 255) / 256), 256>>>(Wqkv, wqkvh, w4);
        size_t o4 = (size_t)C_ * C_ / 4;
        tohalf_kernel<<<(unsigned)((o4 + 255) / 256), 256>>>(Wout, wouth, o4);
    }

    // 3) QKV projection (fp16), epilogue writes g_s16 fp16
    {
        dim3 grid(QKV_N / 128, M_ / 128);
        hgemm_fp16_kernel<<<grid, 128, GEMM_SMEM_BYTES>>>(
            xh, wqkvh, nullptr, nullptr, M_, QKV_N, C_, 1);
    }

    // 4) fp16 flash attention -> g_atth
    attn4_kernel<<<B_ * H_ * NC_ * (CS_ / 128), 256, ATT3_SMEM>>>();

    // 5) output projection (fp16) + bias
    {
        dim3 grid(C_ / 128, M_ / 128);
        hgemm_fp16_kernel<<<grid, 128, GEMM_SMEM_BYTES>>>(
            atth, wouth, bout, out, M_, C_, C_, 0);
    }
}

// round 17
// speedup vs baseline: 8.1268x; 1.0955x over previous
#include <cuda_runtime.h>
#include <cuda_bf16.h>
#include <cuda_fp16.h>
#include <math.h>
#include <stdint.h>

// ---------------------------------------------------------------------------
// LogLinearAttention — R17: coalesced GEMM epilogues via smem staging
// (mode-1 g_s16 scatter was 4B/thread; now 16B/thread fully coalesced rows;
// mode-0 out stores now float4 rows). Mainloop + attention identical to R16
// (validated, 639us / 5.9e-4).
//   B=4, T=4096, C=1024, H=16, dh=64, nc=8, cs=512
// ---------------------------------------------------------------------------

#define B_  4
#define T_  4096
#define C_  1024
#define H_  16
#define DH_ 64
#define NC_ 8
#define CS_ 512
#define QKV_N (3 * C_)
#define M_  (B_ * T_)

__device__ float g_lam[H_ * T_];
__device__ __half g_xh[(size_t)M_ * C_];          // x fp16
__device__ __half g_wqkvh[(size_t)QKV_N * C_];    // Wqkv fp16
__device__ __half g_wouth[(size_t)C_ * C_];       // Wout fp16
__device__ __half g_atth[(size_t)M_ * C_];        // O fp16 (attn output)
// q/k/v fp16 per-(b,h): [comp3][bh64][t4096][d64]
__device__ __half g_s16[(size_t)3 * 64 * T_ * DH_];

#define S16_OFF(comp, bh, t) \
    ((((size_t)(comp) * 64 + (bh)) * T_ + (t)) * DH_)

// ---------------------------------------------------------------------------
__global__ void lambda_kernel(const float* __restrict__ Wl1,
                              const float* __restrict__ bl1,
                              const float* __restrict__ Wl2,
                              const float* __restrict__ bl2) {
    int t = blockIdx.x * blockDim.x + threadIdx.x;
    if (t >= T_) return;
    float lp = logf((float)t + 1.0f);
    float h1[64];
#pragma unroll
    for (int j = 0; j < 64; j++)
        h1[j] = fmaxf(lp * Wl1[j] + bl1[j], 0.0f);
#pragma unroll
    for (int h = 0; h < H_; h++) {
        float s = bl2[h];
        const float* w = Wl2 + h * 64;
#pragma unroll
        for (int j = 0; j < 64; j++) s += w[j] * h1[j];
        g_lam[h * T_ + t] = 1.0f / (1.0f + __expf(-s));
    }
}

// ---------------------------------------------------------------------------
__global__ void tohalf_kernel(const float* __restrict__ A,
                              __half* __restrict__ out, size_t n4) {
    size_t i = (size_t)blockIdx.x * blockDim.x + threadIdx.x;
    if (i >= n4) return;
    float4 v = *(const float4*)(A + i * 4);
    __half2 a = __floats2half2_rn(v.x, v.y);
    __half2 b = __floats2half2_rn(v.z, v.w);
    *(__half2*)(out + i * 4)     = a;
    *(__half2*)(out + i * 4 + 2) = b;
}

// ---------------------------------------------------------------------------
// PTX helpers
// ---------------------------------------------------------------------------
__device__ __forceinline__ unsigned smem_u32(const void* p) {
    return (unsigned)__cvta_generic_to_shared(p);
}
__device__ __forceinline__ void cp16(void* smem_dst, const void* gmem_src) {
    asm volatile("cp.async.cg.shared.global [%0], [%1], 16;\n"
                 :: "r"(smem_u32(smem_dst)), "l"(gmem_src));
}
__device__ __forceinline__ void ldm_x4(unsigned& r0, unsigned& r1,
                                       unsigned& r2, unsigned& r3,
                                       const void* p) {
    asm volatile("ldmatrix.sync.aligned.m8n8.x4.shared.b16 {%0,%1,%2,%3}, [%4];\n"
                 : "=r"(r0), "=r"(r1), "=r"(r2), "=r"(r3) : "r"(smem_u32(p)));
}
__device__ __forceinline__ void ldm_x4t(unsigned& r0, unsigned& r1,
                                        unsigned& r2, unsigned& r3,
                                        const void* p) {
    asm volatile("ldmatrix.sync.aligned.m8n8.x4.trans.shared.b16 {%0,%1,%2,%3}, [%4];\n"
                 : "=r"(r0), "=r"(r1), "=r"(r2), "=r"(r3) : "r"(smem_u32(p)));
}
__device__ __forceinline__ void mma16816h(float* c, const unsigned* a, const unsigned* b) {
    asm volatile("mma.sync.aligned.m16n8k16.row.col.f32.f16.f16.f32 "
                 "{%0,%1,%2,%3}, {%4,%5,%6,%7}, {%8,%9}, {%0,%1,%2,%3};\n"
                 : "+f"(c[0]), "+f"(c[1]), "+f"(c[2]), "+f"(c[3])
                 : "r"(a[0]), "r"(a[1]), "r"(a[2]), "r"(a[3]),
                   "r"(b[0]), "r"(b[1]));
}
__device__ __forceinline__ unsigned pack_half(float a, float b) {
    __half2 h = __floats2half2_rn(a, b);
    return *(unsigned*)&h;
}

// ---------------------------------------------------------------------------
// fp16 HMMA GEMM: C[M,N] = A[M,Kp] @ B[N,Kp]^T
// Block 128x128, BK=64 (pitch 72), 4 warps (2x2), warp tile 64x64,
// __launch_bounds__(128,3). Epilogues stage through the (now idle) smem
// double-buffer for fully coalesced global stores.
// mode 0: fp32 C + bias.  mode 1: write fp16 into g_s16 (QKV path).
// ---------------------------------------------------------------------------
#define GPK 72
#define GTILE (128 * GPK)                 // halfs per matrix per buffer
#define GEMM_SMEM_BYTES (4 * GTILE * 2)   // As[2]+Bs[2] = 73728 B
#define EPI_FP (132)                      // fp32 staging pitch (floats)
#define EPI_HP (136)                      // fp16 staging pitch (halfs)

__global__ __launch_bounds__(128, 3)
void hgemm_fp16_kernel(const __half* __restrict__ A,
                       const __half* __restrict__ B,
                       const float* __restrict__ bias,
                       float* __restrict__ C,
                       int M, int N, int Kp, int mode) {
    extern __shared__ __half S[];
    __half* As[2] = {S, S + GTILE};
    __half* Bs[2] = {S + 2 * GTILE, S + 3 * GTILE};

    const int tid  = threadIdx.x;
    const int lane = tid & 31;
    const int wid  = tid >> 5;
    const int wm   = wid >> 1;
    const int wn   = wid & 1;
    const int m0   = blockIdx.y * 128;
    const int n0   = blockIdx.x * 128;

    float acc[4][8][4];
#pragma unroll
    for (int i = 0; i < 4; i++)
#pragma unroll
        for (int j = 0; j < 8; j++)
#pragma unroll
            for (int r = 0; r < 4; r++) acc[i][j][r] = 0.0f;

    const int KT = Kp / 64;

    auto fill = [&](int buf, int k0) {
#pragma unroll
        for (int q = tid; q < 2048; q += 128) {
            int tile = q >> 10;
            int c    = q & 1023;
            int row  = c >> 3;
            int kc   = (c & 7) * 8;
            const __half* src = (tile ? B + (size_t)(n0 + row) * Kp
                                      : A + (size_t)(m0 + row) * Kp) + k0 + kc;
            __half* dst = (tile ? Bs[buf] : As[buf]) + row * GPK + kc;
            cp16(dst, src);
        }
        asm volatile("cp.async.commit_group;\n");
    };

    fill(0, 0);
    asm volatile("cp.async.wait_group 0;\n");
    __syncthreads();

    int buf = 0;
    for (int kt = 0; kt < KT; kt++) {
        if (kt + 1 < KT) fill(buf ^ 1, (kt + 1) * 64);

        const __half* Ab = As[buf];
        const __half* Bb = Bs[buf];
#pragma unroll
        for (int ks = 0; ks < 4; ks++) {
            unsigned a[4][4], b[8][2];
            const int ar = lane & 15;
            const int ak = ks * 16 + ((lane >> 4) << 3);
#pragma unroll
            for (int mi = 0; mi < 4; mi++)
                ldm_x4(a[mi][0], a[mi][1], a[mi][2], a[mi][3],
                       Ab + (wm * 64 + mi * 16 + ar) * GPK + ak);
            const int br = ((lane >> 4) << 3) + (lane & 7);
            const int bk = ks * 16 + (((lane >> 3) & 1) << 3);
#pragma unroll
            for (int njp = 0; njp < 4; njp++) {
                unsigned r0, r1, r2, r3;
                ldm_x4(r0, r1, r2, r3, Bb + (wn * 64 + njp * 16 + br) * GPK + bk);
                b[njp * 2][0] = r0; b[njp * 2][1] = r1;
                b[njp * 2 + 1][0] = r2; b[njp * 2 + 1][1] = r3;
            }
#pragma unroll
            for (int mi = 0; mi < 4; mi++)
#pragma unroll
                for (int nj = 0; nj < 8; nj++)
                    mma16816h(acc[mi][nj], a[mi], b[nj]);
        }
        if (kt + 1 < KT) asm volatile("cp.async.wait_group 0;\n");
        __syncthreads();
        buf ^= 1;
    }

    // ---- staged epilogues (smem double-buffer is now dead storage) ----
    const int rloc = wm * 64 + (lane >> 2);       // local row base
    const int cloc = wn * 64 + (lane & 3) * 2;    // local col base
    __syncthreads();

    if (mode == 0) {
        float* sb = (float*)S;                    // 128 x EPI_FP (67.6 KB)
#pragma unroll
        for (int mi = 0; mi < 4; mi++)
#pragma unroll
            for (int nj = 0; nj < 8; nj++) {
                int c = cloc + nj * 8;
                int r = rloc + mi * 16;
                *(float2*)&sb[(size_t)r * EPI_FP + c] =
                    make_float2(acc[mi][nj][0], acc[mi][nj][1]);
                *(float2*)&sb[(size_t)(r + 8) * EPI_FP + c] =
                    make_float2(acc[mi][nj][2], acc[mi][nj][3]);
            }
        __syncthreads();
        // coalesced: each iteration = one row chunk of 4 floats, warp = 128 floats
        for (int i = tid; i < 128 * 32; i += 128) {
            int r  = i >> 5;
            int c4 = (i & 31) * 4;
            float4 v = *(float4*)&sb[(size_t)r * EPI_FP + c4];
            int col = n0 + c4;
            v.x += bias[col];
            v.y += bias[col + 1];
            v.z += bias[col + 2];
            v.w += bias[col + 3];
            *(float4*)(C + (size_t)(m0 + r) * N + col) = v;
        }
    } else {
        __half* sh = (__half*)S;                  // 128 x EPI_HP (34.8 KB)
#pragma unroll
        for (int mi = 0; mi < 4; mi++)
#pragma unroll
            for (int nj = 0; nj < 8; nj++) {
                int c = cloc + nj * 8;
                int r = rloc + mi * 16;
                *(__half2*)&sh[(size_t)r * EPI_HP + c] =
                    __floats2half2_rn(acc[mi][nj][0], acc[mi][nj][1]);
                *(__half2*)&sh[(size_t)(r + 8) * EPI_HP + c] =
                    __floats2half2_rn(acc[mi][nj][2], acc[mi][nj][3]);
            }
        __syncthreads();
        // coalesced: 128 t-rows x 2 heads x 8 chunks of 8 halfs (16B/thread)
        for (int i = tid; i < 128 * 2 * 8; i += 128) {
            int chunk = i & 7;
            int head  = (i >> 3) & 1;
            int tl    = i >> 4;
            // read 8 halfs from staging
            float4 v = *(float4*)&sh[(size_t)tl * EPI_HP + head * 64 + chunk * 8];
            int colg = n0 + head * 64;            // global col of head start
            int comp = colg >> 10;
            int hh   = (colg >> 6) & 15;
            int rM   = m0 + tl;
            int bb   = rM >> 12;
            int t    = rM & 4095;
            int bh   = bb * H_ + hh;
            *(float4*)(g_s16 + S16_OFF(comp, bh, t) + chunk * 8) = v;
        }
    }
}

// ---------------------------------------------------------------------------
// Flash-style fp16 attention (validated R15/R16). One block = 128 q rows.
// ---------------------------------------------------------------------------
#define QP 72
#define MAT_E (64 * QP)
#define STAGE_E (2 * MAT_E)
#define ATT3_SMEM (2 * STAGE_E * 2 + 512 * 4)

__global__ __launch_bounds__(256)
void attn4_kernel() {
    extern __shared__ char sm3[];
    __half* KV = (__half*)sm3;
    float* gs = (float*)(KV + 2 * STAGE_E);

    const int tid  = threadIdx.x;
    const int lane = tid & 31;
    const int wid  = tid >> 5;

    const int cid = blockIdx.x;
    const int qt  = cid & 3;
    const int n   = (cid >> 2) & 7;
    const int h   = (cid >> 5) & 15;
    const int b   = cid >> 9;
    const int bh  = b * H_ + h;
    const int t0  = n * CS_ + qt * 128;
    const int tk0 = n * CS_;

    for (int q = tid; q < 1024; q += 256) {
        int r = q >> 3;
        int c8 = (q & 7) * 8;
        cp16(KV + r * QP + c8, g_s16 + S16_OFF(0, bh, t0 + r) + c8);
    }
    asm volatile("cp.async.commit_group;\n");
    for (int i = tid; i < 512; i += 256)
        gs[i] = 0.125f * g_lam[h * T_ + tk0 + i];
    asm volatile("cp.async.wait_group 0;\n");
    __syncthreads();

    unsigned qf[4][4];
    {
        const int ar = 16 * wid + (lane & 15);
        const int ao = (lane >> 4) << 3;
#pragma unroll
        for (int ks = 0; ks < 4; ks++)
            ldm_x4(qf[ks][0], qf[ks][1], qf[ks][2], qf[ks][3],
                   KV + ar * QP + ks * 16 + ao);
    }
    __syncthreads();

    auto fillKV = [&](int st, int kt) {
        __half* stage = KV + st * STAGE_E;
        int tb = tk0 + kt * 64;
        for (int q = tid; q < 1024; q += 256) {
            int part = q >> 9;
            int r = (q >> 3) & 63;
            int c8 = (q & 7) * 8;
            cp16(stage + part * MAT_E + r * QP + c8,
                 g_s16 + S16_OFF(1 + part, bh, tb + r) + c8);
        }
        asm volatile("cp.async.commit_group;\n");
    };
    fillKV(0, 0);
    fillKV(1, 1);

    float m0 = -1e30f, m1 = -1e30f;
    float l0 = 0.0f, l1 = 0.0f;
    float facc[8][4];
#pragma unroll
    for (int i = 0; i < 8; i++)
#pragma unroll
        for (int j = 0; j < 4; j++) facc[i][j] = 0.0f;

    for (int kt = 0; kt < 8; kt++) {
        if (kt == 7) { asm volatile("cp.async.wait_group 0;\n" ::: "memory"); }
        else        { asm volatile("cp.async.wait_group 1;\n" ::: "memory"); }
        __syncthreads();
        __half* Kh = KV + (kt & 1) * STAGE_E;
        __half* Vh = Kh + MAT_E;

        float s[8][4];
#pragma unroll
        for (int i = 0; i < 8; i++)
#pragma unroll
            for (int j = 0; j < 4; j++) s[i][j] = 0.0f;

        {
            const int br = ((lane >> 4) << 3) + (lane & 7);
            const int bo = ((lane >> 3) & 1) << 3;
#pragma unroll
            for (int np = 0; np < 4; np++) {
                int rowb = np * 16 + br;
#pragma unroll
                for (int ks = 0; ks < 4; ks++) {
                    unsigned k4[4];
                    ldm_x4(k4[0], k4[1], k4[2], k4[3],
                           Kh + rowb * QP + ks * 16 + bo);
                    mma16816h(s[2 * np],     qf[ks], &k4[0]);
                    mma16816h(s[2 * np + 1], qf[ks], &k4[2]);
                }
            }
        }

        float tm0 = -1e30f, tm1 = -1e30f;
#pragma unroll
        for (int nt = 0; nt < 8; nt++) {
            int c = nt * 8 + (lane & 3) * 2;
            float g0 = gs[kt * 64 + c];
            float g1 = gs[kt * 64 + c + 1];
            s[nt][0] *= g0; s[nt][1] *= g1;
            s[nt][2] *= g0; s[nt][3] *= g1;
            tm0 = fmaxf(tm0, fmaxf(s[nt][0], s[nt][1]));
            tm1 = fmaxf(tm1, fmaxf(s[nt][2], s[nt][3]));
        }
        tm0 = fmaxf(tm0, __shfl_xor_sync(0xffffffffu, tm0, 1));
        tm0 = fmaxf(tm0, __shfl_xor_sync(0xffffffffu, tm0, 2));
        tm1 = fmaxf(tm1, __shfl_xor_sync(0xffffffffu, tm1, 1));
        tm1 = fmaxf(tm1, __shfl_xor_sync(0xffffffffu, tm1, 2));

        float mn0 = fmaxf(m0, tm0), mn1 = fmaxf(m1, tm1);
        float a0 = __expf(m0 - mn0), a1 = __expf(m1 - mn1);
        m0 = mn0; m1 = mn1;

        unsigned pf[4][4];
        float ts0 = 0.0f, ts1 = 0.0f;
#pragma unroll
        for (int j = 0; j < 4; j++) {
#pragma unroll
            for (int half = 0; half < 2; half++) {
                int nt = 2 * j + half;
                float p00 = __expf(s[nt][0] - m0);
                float p01 = __expf(s[nt][1] - m0);
                float p10 = __expf(s[nt][2] - m1);
                float p11 = __expf(s[nt][3] - m1);
                ts0 += p00 + p01;
                ts1 += p10 + p11;
                pf[j][half * 2]     = pack_half(p00, p01);
                pf[j][half * 2 + 1] = pack_half(p10, p11);
            }
        }
        l0 = l0 * a0 + ts0;
        l1 = l1 * a1 + ts1;
#pragma unroll
        for (int nt = 0; nt < 8; nt++) {
            facc[nt][0] *= a0; facc[nt][1] *= a0;
            facc[nt][2] *= a1; facc[nt][3] *= a1;
        }

        {
            const int vm = lane >> 3;
            const int vr = lane & 7;
#pragma unroll
            for (int dt = 0; dt < 4; dt++) {
#pragma unroll
                for (int ks = 0; ks < 4; ks++) {
                    unsigned v4[4];
                    int row = ks * 16 + ((vm & 1) << 3) + vr;
                    int col = dt * 16 + ((vm >> 1) << 3);
                    ldm_x4t(v4[0], v4[1], v4[2], v4[3], Vh + row * QP + col);
                    mma16816h(facc[2 * dt],     pf[ks], &v4[0]);
                    mma16816h(facc[2 * dt + 1], pf[ks], &v4[2]);
                }
            }
        }

        __syncthreads();
        if (kt + 2 < 8) fillKV(kt & 1, kt + 2);
    }

    l0 += __shfl_xor_sync(0xffffffffu, l0, 1);
    l0 += __shfl_xor_sync(0xffffffffu, l0, 2);
    l1 += __shfl_xor_sync(0xffffffffu, l1, 1);
    l1 += __shfl_xor_sync(0xffffffffu, l1, 2);
    float inv0 = 1.0f / l0, inv1 = 1.0f / l1;

    int qrow0 = t0 + 16 * wid + (lane >> 2);
#pragma unroll
    for (int nt = 0; nt < 8; nt++) {
        int colC = h * 64 + nt * 8 + (lane & 3) * 2;
#pragma unroll
        for (int half = 0; half < 2; half++) {
            int rr = qrow0 + half * 8;
            float inv = half ? inv1 : inv0;
            float o0 = facc[nt][half * 2 + 0] * inv;
            float o1 = facc[nt][half * 2 + 1] * inv;
            *(__half2*)(g_atth + (size_t)(b * T_ + rr) * C_ + colC) =
                __floats2half2_rn(o0, o1);
        }
    }
}

// ---------------------------------------------------------------------------
// Launch
// ---------------------------------------------------------------------------
extern "C" void kernel_launch(void* const* d_in, const int* in_sizes, int n_in,
                              void* d_out, int out_size) {
    const float* x    = (const float*)d_in[0];
    const float* Wqkv = (const float*)d_in[1];
    const float* Wout = (const float*)d_in[2];
    const float* bout = (const float*)d_in[3];
    const float* Wl1  = (const float*)d_in[4];
    const float* bl1  = (const float*)d_in[5];
    const float* Wl2  = (const float*)d_in[6];
    const float* bl2  = (const float*)d_in[7];
    float* out = (float*)d_out;

    __half *xh = nullptr, *wqkvh = nullptr, *wouth = nullptr, *atth = nullptr;
    cudaGetSymbolAddress((void**)&xh, g_xh);
    cudaGetSymbolAddress((void**)&wqkvh, g_wqkvh);
    cudaGetSymbolAddress((void**)&wouth, g_wouth);
    cudaGetSymbolAddress((void**)&atth, g_atth);

    cudaFuncSetAttribute(attn4_kernel,
                         cudaFuncAttributeMaxDynamicSharedMemorySize, ATT3_SMEM);
    cudaFuncSetAttribute(hgemm_fp16_kernel,
                         cudaFuncAttributeMaxDynamicSharedMemorySize,
                         GEMM_SMEM_BYTES);

    // 1) lambda gates
    lambda_kernel<<<(T_ + 127) / 128, 128>>>(Wl1, bl1, Wl2, bl2);

    // 2) fp16 converts
    {
        size_t n4 = (size_t)M_ * C_ / 4;
        tohalf_kernel<<<(unsigned)((n4 + 255) / 256), 256>>>(x, xh, n4);
        size_t w4 = (size_t)QKV_N * C_ / 4;
        tohalf_kernel<<<(unsigned)((w4 + 255) / 256), 256>>>(Wqkv, wqkvh, w4);
        size_t o4 = (size_t)C_ * C_ / 4;
        tohalf_kernel<<<(unsigned)((o4 + 255) / 256), 256>>>(Wout, wouth, o4);
    }

    // 3) QKV projection (fp16), staged epilogue writes g_s16 fp16 coalesced
    {
        dim3 grid(QKV_N / 128, M_ / 128);
        hgemm_fp16_kernel<<<grid, 128, GEMM_SMEM_BYTES>>>(
            xh, wqkvh, nullptr, nullptr, M_, QKV_N, C_, 1);
    }

    // 4) fp16 flash attention -> g_atth
    attn4_kernel<<<B_ * H_ * NC_ * (CS_ / 128), 256, ATT3_SMEM>>>();

    // 5) output projection (fp16) + bias, staged epilogue
    {
        dim3 grid(C_ / 128, M_ / 128);
        hgemm_fp16_kernel<<<grid, 128, GEMM_SMEM_BYTES>>>(
            atth, wouth, bout, out, M_, C_, C_, 0);
    }
}